// round 9
// baseline (speedup 1.0000x reference)
#include <cuda_runtime.h>
#include <cuda_fp16.h>
#include <cuda_bf16.h>
#include <math.h>
#include <stdint.h>

// Problem dims
#define BATCH 2048
#define TT    128
#define VV    256
#define CC    32
#define HH    128
#define EE    256
#define GG    384   // 3*H
#define OO    256
#define NLN   3
#define BNK   32

// GRU tiling
#define BM    32      // batch rows per CTA (2 streams x 16)
#define NTH   512     // 16 warps, 24 gate-cols each
// SMEM byte offsets
#define SW0   0                   // w fp16: [384][128] half, swizzled (96KB)
#define SH16(s) (98304 + (s) * 4096)   // h fp16 per stream [16][128]
#define SMEM_TOTAL 106496

// Scratch (static device globals)
__device__ __align__(16) __half g_w0[2 * GG * HH];  // [dir][p][k] fp16
__device__ float g_xtab[2 * VV * GG];   // permuted x@w_ih^T + b_ih (+b_hh r,z)
__device__ float g_feat[BATCH * EE];
__device__ float g_upwT[NLN * BNK * EE]; // up_w transposed: [l][d][e]
__device__ int   g_tokT[TT * BATCH];     // tokens transposed [t][b]

// ---------------------------------------------------------------------------
// Activations (R6-exact): precise n-tanh; HW tanh for r/z sigmoids.
// ---------------------------------------------------------------------------
__device__ __forceinline__ float sigm_precise(float x) {
    float t = fminf(x * 1.4426950408889634f, 80.0f);
    float e; asm("ex2.approx.f32 %0, %1;" : "=f"(e) : "f"(t));
    float d = 1.0f + e;
    float y; asm("rcp.approx.f32 %0, %1;" : "=f"(y) : "f"(d));
    y = y * fmaf(-d, y, 2.0f);
    return e * y;
}
__device__ __forceinline__ float tanh_precise(float x) {
    return fmaf(2.0f, sigm_precise(2.0f * x), -1.0f);
}
__device__ __forceinline__ float tanh_hw(float x) {
    float y; asm("tanh.approx.f32 %0, %1;" : "=f"(y) : "f"(x));
    return y;
}
__device__ __forceinline__ float sigm_fast(float x) {
    return fmaf(tanh_hw(0.5f * x), 0.5f, 0.5f);
}

// ---------------------------------------------------------------------------
// MMA / ldmatrix wrappers
// ---------------------------------------------------------------------------
__device__ __forceinline__ void ldsm4(uint32_t& r0, uint32_t& r1, uint32_t& r2,
                                      uint32_t& r3, uint32_t addr) {
    asm volatile("ldmatrix.sync.aligned.m8n8.x4.shared.b16 {%0,%1,%2,%3}, [%4];"
                 : "=r"(r0), "=r"(r1), "=r"(r2), "=r"(r3) : "r"(addr));
}
__device__ __forceinline__ void mma16816(float* d, const uint32_t* a,
                                         uint32_t b0, uint32_t b1) {
    asm volatile(
        "mma.sync.aligned.m16n8k16.row.col.f32.f16.f16.f32 "
        "{%0,%1,%2,%3}, {%4,%5,%6,%7}, {%8,%9}, {%0,%1,%2,%3};"
        : "+f"(d[0]), "+f"(d[1]), "+f"(d[2]), "+f"(d[3])
        : "r"(a[0]), "r"(a[1]), "r"(a[2]), "r"(a[3]), "r"(b0), "r"(b1));
}

// gate-dim permutation: orig g = t*128 + j -> p = 24*(j>>3) + 8*t + (j&7)
__device__ __forceinline__ int permute_g(int g) {
    int t = g >> 7, j = g & 127;
    return 24 * (j >> 3) + 8 * t + (j & 7);
}

// ---------------------------------------------------------------------------
// Prep A: xtab (permuted). b_ih + b_hh(r,z) folded (no scaling - R6 semantics).
// ---------------------------------------------------------------------------
__global__ void xtab_kernel(const float* __restrict__ ce,
                            const float* __restrict__ wih_f, const float* __restrict__ bih_f,
                            const float* __restrict__ wih_b, const float* __restrict__ bih_b,
                            const float* __restrict__ bhh_f, const float* __restrict__ bhh_b) {
    extern __shared__ float xsm[];
    float* ws = xsm;               // [384*32]
    float* bs = ws + GG * CC;      // [384]
    float* cs = bs + GG;           // [32*32]
    const int d = blockIdx.y, g = threadIdx.x;
    const float* wih = d ? wih_b : wih_f;
    const float* bih = d ? bih_b : bih_f;
    const float* bhh = d ? bhh_b : bhh_f;
    for (int i = g; i < GG * CC; i += GG) ws[i] = wih[i];
    bs[g] = bih[g] + (g < 2 * HH ? bhh[g] : 0.0f);
    const int v0 = blockIdx.x * 32;
    for (int i = g; i < 32 * CC; i += GG) cs[i] = ce[v0 * CC + i];
    __syncthreads();
    const int p = permute_g(g);
    for (int vi = 0; vi < 32; vi++) {
        float s = bs[g];
        #pragma unroll
        for (int c = 0; c < CC; c++) s = fmaf(cs[vi * CC + c], ws[g * CC + c], s);
        g_xtab[(d * VV + v0 + vi) * GG + p] = s;
    }
}

// ---------------------------------------------------------------------------
// Prep B (fused): w_hh fp16 permuted + up_w transpose + tokens transpose.
// ---------------------------------------------------------------------------
__global__ void prep_misc(const float* __restrict__ whh_f,
                          const float* __restrict__ whh_b,
                          const float* __restrict__ up_w,
                          const int* __restrict__ tokens) {
    const int i = blockIdx.x * 256 + threadIdx.x;
    if (i < 2 * GG * HH) {
        int d = i / (GG * HH), rem = i % (GG * HH);
        int g = rem / HH, k = rem % HH;
        const float* w = d ? whh_b : whh_f;
        g_w0[d * GG * HH + permute_g(g) * HH + k] = __float2half_rn(w[g * HH + k]);
    } else if (i < 2 * GG * HH + NLN * EE * BNK) {
        int j = i - 2 * GG * HH;
        int l = j / (EE * BNK), rem = j % (EE * BNK);
        int e = rem / BNK, dd = rem % BNK;
        g_upwT[(l * BNK + dd) * EE + e] = up_w[j];
    } else {
        int j = i - (2 * GG * HH + NLN * EE * BNK);
        if (j < BATCH * TT) {
            int b = j / TT, t = j % TT;
            g_tokT[t * BATCH + b] = tokens[j];
        }
    }
}

// ---------------------------------------------------------------------------
// GRU via mma (R6 schedule; sole change: xp0 prefetched one step ahead).
// grid (64, 2) x 512 threads.
// ---------------------------------------------------------------------------
#define GATE_CELL(KC2, XP, SG) do {                                           \
    const int ri_ = (KC2) >> 1, c01_ = (KC2) & 1, rg_ = 2 * ri_ + c01_;       \
    float xr_ = (c01_ ? XP[ri_][0].y : XP[ri_][0].x) + acc[SG][0][rg_];       \
    float xz_ = (c01_ ? XP[ri_][1].y : XP[ri_][1].x) + acc[SG][1][rg_];       \
    float xn_ = (c01_ ? XP[ri_][2].y : XP[ri_][2].x);                         \
    float nh_ = acc[SG][2][rg_];                                              \
    float r_ = sigm_fast(xr_);                                                \
    float z_ = sigm_fast(xz_);                                                \
    float n_ = tanh_precise(fmaf(r_, nh_, xn_));                              \
    float h_ = fmaf(z_, hprev[SG][ri_][c01_] - n_, n_);                       \
    hprev[SG][ri_][c01_] = h_;                                                \
    *(__half*)(smem + SH16(SG) + stoff[ri_] + 2 * c01_) = __float2half_rn(h_);\
} while (0)

__global__ __launch_bounds__(NTH, 1) void gru_mma_kernel(
    const float* __restrict__ bhh_f, const float* __restrict__ bhh_b) {
    extern __shared__ __align__(16) char smem[];
    const uint32_t sb = (uint32_t)__cvta_generic_to_shared(smem);

    const int dir  = blockIdx.y;
    const int b0r  = blockIdx.x * BM;
    const int tid  = threadIdx.x;
    const int w    = tid >> 5;
    const int lane = tid & 31;
    const int lr   = lane >> 2;
    const int lq   = lane & 3;

    const float* bhh = dir ? bhh_b : bhh_f;
    const float* xt  = g_xtab + dir * VV * GG;

    // ---- load w (swizzled) + zero h buffers ----
    {
        const uint4* gw0 = (const uint4*)(g_w0 + dir * (GG * HH));
        for (int idx = tid; idx < GG * 16; idx += NTH) {
            int n = idx >> 4, c = idx & 15;
            int off = n * 256 + ((c ^ (n & 7)) << 4);
            *(uint4*)(smem + SW0 + off) = gw0[idx];
        }
        for (int idx = tid; idx < 512; idx += NTH)
            ((uint4*)(smem + SH16(0)))[idx] = make_uint4(0, 0, 0, 0);
    }

    float bias_n[2];
    #pragma unroll
    for (int c = 0; c < 2; c++)
        bias_n[c] = bhh[2 * 128 + 8 * w + 2 * lq + c];

    const int ar  = lane & 15;
    const int ahi = lane >> 4;
    const int asw = ar & 7;
    const int bj  = lane >> 3;
    const int bsw = lane & 7;
    const int brow = (24 * w + (lane & 7)) * 256;

    int stoff[2];
    #pragma unroll
    for (int ri = 0; ri < 2; ri++)
        stoff[ri] = (lr + 8 * ri) * 256 + ((w ^ lr) << 4) + 4 * lq;

    const uint32_t abase0 = sb + SH16(0) + ar * 256;
    const uint32_t abase1 = sb + SH16(1) + ar * 256;

    __syncthreads();

    // cache B fragments for gate groups nt=0,1 (loop-invariant)
    uint32_t Brg[2][4][4];
    #pragma unroll
    for (int nt = 0; nt < 2; nt++)
        #pragma unroll
        for (int kc2 = 0; kc2 < 4; kc2++) {
            uint32_t chunk = (uint32_t)(((4 * kc2 + bj) ^ bsw) << 4);
            ldsm4(Brg[nt][kc2][0], Brg[nt][kc2][1], Brg[nt][kc2][2],
                  Brg[nt][kc2][3], sb + SW0 + brow + nt * 2048 + chunk);
        }

    float hprev[2][2][2];
    float acc[2][3][4];
    #pragma unroll
    for (int s = 0; s < 2; s++) {
        #pragma unroll
        for (int ri = 0; ri < 2; ri++)
            #pragma unroll
            for (int c = 0; c < 2; c++) hprev[s][ri][c] = 0.0f;
        #pragma unroll
        for (int rg = 0; rg < 4; rg++) {
            acc[s][0][rg] = 0.0f;
            acc[s][1][rg] = 0.0f;
            acc[s][2][rg] = bias_n[rg & 1];
        }
    }

    // xp0: stream-0 gather, prefetched one step ahead; xp1 at t-top.
    float2 xp0[2][3], xp1[2][3];
    {
        const int tcol = dir ? (TT - 1) : 0;
        const int* tokrow = g_tokT + tcol * BATCH + b0r;
        #pragma unroll
        for (int ri = 0; ri < 2; ri++) {
            int tok = tokrow[8 * ri + lr];
            const float2* xr = (const float2*)(xt + tok * GG + 24 * w);
            #pragma unroll
            for (int u = 0; u < 3; u++) xp0[ri][u] = xr[4 * u + lq];
        }
    }

    #pragma unroll 1
    for (int t = 0; t < TT; t++) {
        const int tcol = dir ? (TT - 1 - t) : t;

        // xp1 for stream 1 (consumed in phase 1 -> full phase of lead time)
        {
            const int* tokrow = g_tokT + tcol * BATCH + b0r + 16;
            #pragma unroll
            for (int ri = 0; ri < 2; ri++) {
                int tok = tokrow[8 * ri + lr];
                const float2* xr = (const float2*)(xt + tok * GG + 24 * w);
                #pragma unroll
                for (int u = 0; u < 3; u++) xp1[ri][u] = xr[4 * u + lq];
            }
        }

        // ---------- phase 0: mma stream 1, gates stream 0 (xp0) ----------
        {
            #pragma unroll
            for (int rg = 0; rg < 4; rg++) {
                acc[1][0][rg] = 0.0f; acc[1][1][rg] = 0.0f;
                acc[1][2][rg] = bias_n[rg & 1];
            }
            const bool do_mma = (t > 0);
            #pragma unroll
            for (int kc2 = 0; kc2 < 4; kc2++) {
                uint32_t a0[8];
                if (do_mma) {
                    uint32_t clo = (uint32_t)(((4 * kc2 + ahi) ^ asw) << 4);
                    uint32_t chi = (uint32_t)(((4 * kc2 + 2 + ahi) ^ asw) << 4);
                    ldsm4(a0[0], a0[1], a0[2], a0[3], abase1 + clo);
                    ldsm4(a0[4], a0[5], a0[6], a0[7], abase1 + chi);
                }
                GATE_CELL(kc2, xp0, 0);
                if (do_mma) {
                    mma16816(acc[1][0], a0 + 0, Brg[0][kc2][0], Brg[0][kc2][1]);
                    mma16816(acc[1][0], a0 + 4, Brg[0][kc2][2], Brg[0][kc2][3]);
                    mma16816(acc[1][1], a0 + 0, Brg[1][kc2][0], Brg[1][kc2][1]);
                    mma16816(acc[1][1], a0 + 4, Brg[1][kc2][2], Brg[1][kc2][3]);
                    uint32_t bh[4];
                    const uint32_t chunk =
                        (uint32_t)(((4 * kc2 + bj) ^ bsw) << 4);
                    ldsm4(bh[0], bh[1], bh[2], bh[3],
                          sb + SW0 + brow + 2 * 2048 + chunk);
                    mma16816(acc[1][2], a0 + 0, bh[0], bh[1]);
                    mma16816(acc[1][2], a0 + 4, bh[2], bh[3]);
                }
            }
            __syncthreads();
        }

        // ---------- phase 1: mma stream 0, gates stream 1 (xp1) ----------
        {
            #pragma unroll
            for (int rg = 0; rg < 4; rg++) {
                acc[0][0][rg] = 0.0f; acc[0][1][rg] = 0.0f;
                acc[0][2][rg] = bias_n[rg & 1];
            }
            // prefetch xp0 for t+1 (consumed in next step's phase 0)
            {
                const int tn = (t + 1 < TT) ? t + 1 : t;
                const int tcoln = dir ? (TT - 1 - tn) : tn;
                const int* tokrow = g_tokT + tcoln * BATCH + b0r;
                #pragma unroll
                for (int ri = 0; ri < 2; ri++) {
                    int tok = tokrow[8 * ri + lr];
                    const float2* xr = (const float2*)(xt + tok * GG + 24 * w);
                    #pragma unroll
                    for (int u = 0; u < 3; u++) xp0[ri][u] = xr[4 * u + lq];
                }
            }
            const bool do_mma = (t < TT - 1);
            #pragma unroll
            for (int kc2 = 0; kc2 < 4; kc2++) {
                uint32_t a0[8];
                if (do_mma) {
                    uint32_t clo = (uint32_t)(((4 * kc2 + ahi) ^ asw) << 4);
                    uint32_t chi = (uint32_t)(((4 * kc2 + 2 + ahi) ^ asw) << 4);
                    ldsm4(a0[0], a0[1], a0[2], a0[3], abase0 + clo);
                    ldsm4(a0[4], a0[5], a0[6], a0[7], abase0 + chi);
                }
                GATE_CELL(kc2, xp1, 1);
                if (do_mma) {
                    mma16816(acc[0][0], a0 + 0, Brg[0][kc2][0], Brg[0][kc2][1]);
                    mma16816(acc[0][0], a0 + 4, Brg[0][kc2][2], Brg[0][kc2][3]);
                    mma16816(acc[0][1], a0 + 0, Brg[1][kc2][0], Brg[1][kc2][1]);
                    mma16816(acc[0][1], a0 + 4, Brg[1][kc2][2], Brg[1][kc2][3]);
                    uint32_t bh[4];
                    const uint32_t chunk =
                        (uint32_t)(((4 * kc2 + bj) ^ bsw) << 4);
                    ldsm4(bh[0], bh[1], bh[2], bh[3],
                          sb + SW0 + brow + 2 * 2048 + chunk);
                    mma16816(acc[0][2], a0 + 0, bh[0], bh[1]);
                    mma16816(acc[0][2], a0 + 4, bh[2], bh[3]);
                }
            }
            __syncthreads();
        }
    }

    // final hidden -> feat
    #pragma unroll
    for (int s = 0; s < 2; s++)
        #pragma unroll
        for (int ri = 0; ri < 2; ri++)
            #pragma unroll
            for (int c = 0; c < 2; c++) {
                int m = 16 * s + lr + 8 * ri;
                int j = 8 * w + 2 * lq + c;
                g_feat[(b0r + m) * EE + dir * HH + j] = hprev[s][ri][c];
            }
}

// ---------------------------------------------------------------------------
// Head v3: HB=4 rows per CTA (grid 512), 2 warps cooperate per row.
// warp pair (row, row+4): half 0 -> hid units 0-15 / e 0-127,
//                         half 1 -> hid units 16-31 / e 128-255.
// ---------------------------------------------------------------------------
#define HB 4
__global__ __launch_bounds__(256) void head_kernel(
    const int* __restrict__ lang_ids,
    const float* __restrict__ down_w, const float* __restrict__ down_b,
    const float* __restrict__ up_b,
    const float* __restrict__ ln_g,   const float* __restrict__ ln_b,
    const float* __restrict__ proj_w, const float* __restrict__ proj_b,
    float* __restrict__ out) {
    __shared__ float y_s[HB][EE];
    __shared__ float hid_s[HB][BNK];
    __shared__ float red_s[HB][2][2];
    const int tid = threadIdx.x, w = tid >> 5, lane = tid & 31;
    const int b0 = blockIdx.x * HB;
    const int row = w & 3;
    const int half = w >> 2;
    const int b = b0 + row;
    const int l = lang_ids[b];
    const float* fb = g_feat + b * EE;

    // feat in grouped pattern: lane covers elems (lane&7)*4 + 32c
    float4 f4[8];
    #pragma unroll
    for (int c = 0; c < 8; c++)
        f4[c] = *(const float4*)(fb + (lane & 7) * 4 + 32 * c);

    // down-proj: this warp computes hid units [half*16, half*16+16)
    const float* dwb = down_w + l * BNK * EE;
    #pragma unroll
    for (int g = 0; g < 4; g++) {
        const int d = half * 16 + 4 * g + (lane >> 3);
        const float* wr = dwb + d * EE + (lane & 7) * 4;
        float s = 0.0f;
        #pragma unroll
        for (int c = 0; c < 8; c++) {
            float4 wv = *(const float4*)(wr + 32 * c);
            s = fmaf(f4[c].x, wv.x, s); s = fmaf(f4[c].y, wv.y, s);
            s = fmaf(f4[c].z, wv.z, s); s = fmaf(f4[c].w, wv.w, s);
        }
        s += __shfl_xor_sync(0xffffffffu, s, 1);
        s += __shfl_xor_sync(0xffffffffu, s, 2);
        s += __shfl_xor_sync(0xffffffffu, s, 4);
        if ((lane & 7) == 0) {
            float v = s + down_b[l * BNK + d];
            hid_s[row][d] = 0.5f * v * (1.0f + erff(v * 0.7071067811865476f));
        }
    }
    __syncthreads();

    // up-proj + residual + LN: warp handles e in [half*128, half*128+128)
    const int e0 = half * 128 + lane * 4;
    float hval = hid_s[row][lane];
    float4 a = *(const float4*)(up_b + l * EE + e0);
    const float* uwb = g_upwT + l * BNK * EE + e0;
    #pragma unroll 4
    for (int d = 0; d < BNK; d++) {
        float hd = __shfl_sync(0xffffffffu, hval, d);
        float4 u = *(const float4*)(uwb + d * EE);
        a.x = fmaf(hd, u.x, a.x); a.y = fmaf(hd, u.y, a.y);
        a.z = fmaf(hd, u.z, a.z); a.w = fmaf(hd, u.w, a.w);
    }
    const float4 fx = *(const float4*)(fb + e0);
    float x[4] = {fx.x + a.x, fx.y + a.y, fx.z + a.z, fx.w + a.w};
    float s1 = 0.0f, s2 = 0.0f;
    #pragma unroll
    for (int j = 0; j < 4; j++) { s1 += x[j]; s2 = fmaf(x[j], x[j], s2); }
    #pragma unroll
    for (int o = 16; o; o >>= 1) {
        s1 += __shfl_xor_sync(0xffffffffu, s1, o);
        s2 += __shfl_xor_sync(0xffffffffu, s2, o);
    }
    if (lane == 0) { red_s[row][half][0] = s1; red_s[row][half][1] = s2; }
    __syncthreads();
    const float t1 = red_s[row][0][0] + red_s[row][1][0];
    const float t2 = red_s[row][0][1] + red_s[row][1][1];
    const float mu = t1 * (1.0f / EE);
    const float rstd = rsqrtf(t2 * (1.0f / EE) - mu * mu + 1e-5f);
    const float4 gg = *(const float4*)(ln_g + l * EE + e0);
    const float4 bb = *(const float4*)(ln_b + l * EE + e0);
    float4 y4;
    y4.x = (x[0] - mu) * rstd * gg.x + bb.x;
    y4.y = (x[1] - mu) * rstd * gg.y + bb.y;
    y4.z = (x[2] - mu) * rstd * gg.z + bb.z;
    y4.w = (x[3] - mu) * rstd * gg.w + bb.w;
    *(float4*)(&y_s[row][e0]) = y4;
    __syncthreads();

    // projection: thread owns output column `tid` for the CTA's 4 rows
    float accv[HB];
    #pragma unroll
    for (int r = 0; r < HB; r++) accv[r] = proj_b[tid];
    const float* pw = proj_w + tid * EE;
    for (int e = 0; e < EE; e += 4) {
        float4 wv = *(const float4*)(pw + e);
        #pragma unroll
        for (int r = 0; r < HB; r++) {
            float4 yv = *(const float4*)(&y_s[r][e]);
            accv[r] = fmaf(wv.x, yv.x, accv[r]);
            accv[r] = fmaf(wv.y, yv.y, accv[r]);
            accv[r] = fmaf(wv.z, yv.z, accv[r]);
            accv[r] = fmaf(wv.w, yv.w, accv[r]);
        }
    }
    #pragma unroll
    for (int r = 0; r < HB; r++) out[(b0 + r) * OO + tid] = accv[r];
}

// ---------------------------------------------------------------------------
extern "C" void kernel_launch(void* const* d_in, const int* in_sizes, int n_in,
                              void* d_out, int out_size) {
    const int*   tokens = (const int*)d_in[0];
    const int*   lang   = (const int*)d_in[1];
    const float* ce     = (const float*)d_in[2];
    const float* wih_f  = (const float*)d_in[3];
    const float* whh_f  = (const float*)d_in[4];
    const float* bih_f  = (const float*)d_in[5];
    const float* bhh_f  = (const float*)d_in[6];
    const float* wih_b  = (const float*)d_in[7];
    const float* whh_b  = (const float*)d_in[8];
    const float* bih_b  = (const float*)d_in[9];
    const float* bhh_b  = (const float*)d_in[10];
    const float* down_w = (const float*)d_in[11];
    const float* down_b = (const float*)d_in[12];
    const float* up_w   = (const float*)d_in[13];
    const float* up_b   = (const float*)d_in[14];
    const float* ln_g   = (const float*)d_in[15];
    const float* ln_b   = (const float*)d_in[16];
    const float* proj_w = (const float*)d_in[17];
    const float* proj_b = (const float*)d_in[18];
    float* out = (float*)d_out;

    cudaFuncSetAttribute(gru_mma_kernel,
                         cudaFuncAttributeMaxDynamicSharedMemorySize, SMEM_TOTAL);
    const size_t xsmem = (size_t)(GG * CC + GG + 32 * CC) * sizeof(float);
    cudaFuncSetAttribute(xtab_kernel,
                         cudaFuncAttributeMaxDynamicSharedMemorySize, (int)xsmem);

    const int prep_elems = 2 * GG * HH + NLN * EE * BNK + BATCH * TT;
    prep_misc<<<(prep_elems + 255) / 256, 256>>>(whh_f, whh_b, up_w, tokens);
    xtab_kernel<<<dim3(8, 2), GG, xsmem>>>(ce, wih_f, bih_f, wih_b, bih_b,
                                           bhh_f, bhh_b);
    gru_mma_kernel<<<dim3(BATCH / BM, 2), NTH, SMEM_TOTAL>>>(bhh_f, bhh_b);
    head_kernel<<<BATCH / HB, 256>>>(lang, down_w, down_b, up_b,
                                     ln_g, ln_b, proj_w, proj_b, out);
}

// round 10
// speedup vs baseline: 1.1349x; 1.1349x over previous
#include <cuda_runtime.h>
#include <cuda_fp16.h>
#include <cuda_bf16.h>
#include <math.h>
#include <stdint.h>

// Problem dims
#define BATCH 2048
#define TT    128
#define VV    256
#define CC    32
#define HH    128
#define EE    256
#define GG    384   // 3*H
#define OO    256
#define NLN   3
#define BNK   32

// GRU tiling
#define BM    32      // batch rows per CTA (2 streams x 16)
#define NTH   512     // 16 warps, 24 gate-cols each
// SMEM byte offsets
#define SW0   0                   // w fp16: [384][128] half, swizzled (96KB)
#define SH16(s) (98304 + (s) * 4096)   // h fp16 per stream [16][128]
#define SMEM_TOTAL 106496

// Scratch (static device globals)
__device__ __align__(16) __half g_w0[2 * GG * HH];  // [dir][p][k] fp16
__device__ float g_xtab[2 * VV * GG];   // permuted x@w_ih^T + b_ih (+b_hh r,z)
__device__ float g_feat[BATCH * EE];
__device__ float g_upwT[NLN * BNK * EE]; // up_w transposed: [l][d][e]
__device__ int   g_tokT[TT * BATCH];     // tokens transposed [t][b]

// ---------------------------------------------------------------------------
// Activations (R6-exact): precise n-tanh; HW tanh for r/z sigmoids.
// ---------------------------------------------------------------------------
__device__ __forceinline__ float sigm_precise(float x) {
    float t = fminf(x * 1.4426950408889634f, 80.0f);
    float e; asm("ex2.approx.f32 %0, %1;" : "=f"(e) : "f"(t));
    float d = 1.0f + e;
    float y; asm("rcp.approx.f32 %0, %1;" : "=f"(y) : "f"(d));
    y = y * fmaf(-d, y, 2.0f);
    return e * y;
}
__device__ __forceinline__ float tanh_precise(float x) {
    return fmaf(2.0f, sigm_precise(2.0f * x), -1.0f);
}
__device__ __forceinline__ float tanh_hw(float x) {
    float y; asm("tanh.approx.f32 %0, %1;" : "=f"(y) : "f"(x));
    return y;
}
__device__ __forceinline__ float sigm_fast(float x) {
    return fmaf(tanh_hw(0.5f * x), 0.5f, 0.5f);
}

// ---------------------------------------------------------------------------
// MMA / ldmatrix wrappers
// ---------------------------------------------------------------------------
__device__ __forceinline__ void ldsm4(uint32_t& r0, uint32_t& r1, uint32_t& r2,
                                      uint32_t& r3, uint32_t addr) {
    asm volatile("ldmatrix.sync.aligned.m8n8.x4.shared.b16 {%0,%1,%2,%3}, [%4];"
                 : "=r"(r0), "=r"(r1), "=r"(r2), "=r"(r3) : "r"(addr));
}
__device__ __forceinline__ void mma16816(float* d, const uint32_t* a,
                                         uint32_t b0, uint32_t b1) {
    asm volatile(
        "mma.sync.aligned.m16n8k16.row.col.f32.f16.f16.f32 "
        "{%0,%1,%2,%3}, {%4,%5,%6,%7}, {%8,%9}, {%0,%1,%2,%3};"
        : "+f"(d[0]), "+f"(d[1]), "+f"(d[2]), "+f"(d[3])
        : "r"(a[0]), "r"(a[1]), "r"(a[2]), "r"(a[3]), "r"(b0), "r"(b1));
}

// gate-dim permutation: orig g = t*128 + j -> p = 24*(j>>3) + 8*t + (j&7)
__device__ __forceinline__ int permute_g(int g) {
    int t = g >> 7, j = g & 127;
    return 24 * (j >> 3) + 8 * t + (j & 7);
}

// ---------------------------------------------------------------------------
// Prep A: xtab (permuted). b_ih + b_hh(r,z) folded (R6-exact).
// ---------------------------------------------------------------------------
__global__ void xtab_kernel(const float* __restrict__ ce,
                            const float* __restrict__ wih_f, const float* __restrict__ bih_f,
                            const float* __restrict__ wih_b, const float* __restrict__ bih_b,
                            const float* __restrict__ bhh_f, const float* __restrict__ bhh_b) {
    extern __shared__ float xsm[];
    float* ws = xsm;               // [384*32]
    float* bs = ws + GG * CC;      // [384]
    float* cs = bs + GG;           // [32*32]
    const int d = blockIdx.y, g = threadIdx.x;
    const float* wih = d ? wih_b : wih_f;
    const float* bih = d ? bih_b : bih_f;
    const float* bhh = d ? bhh_b : bhh_f;
    for (int i = g; i < GG * CC; i += GG) ws[i] = wih[i];
    bs[g] = bih[g] + (g < 2 * HH ? bhh[g] : 0.0f);
    const int v0 = blockIdx.x * 32;
    for (int i = g; i < 32 * CC; i += GG) cs[i] = ce[v0 * CC + i];
    __syncthreads();
    const int p = permute_g(g);
    for (int vi = 0; vi < 32; vi++) {
        float s = bs[g];
        #pragma unroll
        for (int c = 0; c < CC; c++) s = fmaf(cs[vi * CC + c], ws[g * CC + c], s);
        g_xtab[(d * VV + v0 + vi) * GG + p] = s;
    }
}

// ---------------------------------------------------------------------------
// Prep B (fused): w_hh fp16 permuted + up_w transpose + tokens transpose.
// ---------------------------------------------------------------------------
__global__ void prep_misc(const float* __restrict__ whh_f,
                          const float* __restrict__ whh_b,
                          const float* __restrict__ up_w,
                          const int* __restrict__ tokens) {
    const int i = blockIdx.x * 256 + threadIdx.x;
    if (i < 2 * GG * HH) {
        int d = i / (GG * HH), rem = i % (GG * HH);
        int g = rem / HH, k = rem % HH;
        const float* w = d ? whh_b : whh_f;
        g_w0[d * GG * HH + permute_g(g) * HH + k] = __float2half_rn(w[g * HH + k]);
    } else if (i < 2 * GG * HH + NLN * EE * BNK) {
        int j = i - 2 * GG * HH;
        int l = j / (EE * BNK), rem = j % (EE * BNK);
        int e = rem / BNK, dd = rem % BNK;
        g_upwT[(l * BNK + dd) * EE + e] = up_w[j];
    } else {
        int j = i - (2 * GG * HH + NLN * EE * BNK);
        if (j < BATCH * TT) {
            int b = j / TT, t = j % TT;
            g_tokT[t * BATCH + b] = tokens[j];
        }
    }
}

// ---------------------------------------------------------------------------
// GRU via mma (R6-exact). fp16 operands, fp32 accum + fp32 register hprev.
// B-frags for gate groups 0,1 cached in registers; gate cells interleaved
// into the mma k-loop. grid (64, 2) x 512 threads.
// ---------------------------------------------------------------------------
__global__ __launch_bounds__(NTH, 1) void gru_mma_kernel(
    const float* __restrict__ bhh_f, const float* __restrict__ bhh_b) {
    extern __shared__ __align__(16) char smem[];
    const uint32_t sb = (uint32_t)__cvta_generic_to_shared(smem);

    const int dir  = blockIdx.y;
    const int b0r  = blockIdx.x * BM;
    const int tid  = threadIdx.x;
    const int w    = tid >> 5;      // 0..15
    const int lane = tid & 31;
    const int lr   = lane >> 2;     // 0..7
    const int lq   = lane & 3;      // 0..3

    const float* bhh = dir ? bhh_b : bhh_f;
    const float* xt  = g_xtab + dir * VV * GG;

    // ---- load w (swizzled) + zero h buffers ----
    {
        const uint4* gw0 = (const uint4*)(g_w0 + dir * (GG * HH));
        for (int idx = tid; idx < GG * 16; idx += NTH) {
            int n = idx >> 4, c = idx & 15;
            int off = n * 256 + ((c ^ (n & 7)) << 4);
            *(uint4*)(smem + SW0 + off) = gw0[idx];
        }
        for (int idx = tid; idx < 512; idx += NTH)
            ((uint4*)(smem + SH16(0)))[idx] = make_uint4(0, 0, 0, 0);
    }

    // n-gate bias only (r,z folded into xtab)
    float bias_n[2];
    #pragma unroll
    for (int c = 0; c < 2; c++)
        bias_n[c] = bhh[2 * 128 + 8 * w + 2 * lq + c];

    // ldmatrix addressing constants
    const int ar  = lane & 15;
    const int ahi = lane >> 4;
    const int asw = ar & 7;
    const int bj  = lane >> 3;
    const int bsw = lane & 7;
    const int brow = (24 * w + (lane & 7)) * 256;

    // h' store offsets (chunk index = w since unit j = 8w + ..)
    int stoff[2];
    #pragma unroll
    for (int ri = 0; ri < 2; ri++)
        stoff[ri] = (lr + 8 * ri) * 256 + ((w ^ lr) << 4) + 4 * lq;

    __syncthreads();

    // ---- cache B fragments for gate groups nt=0,1 (loop-invariant) ----
    uint32_t Brg[2][4][4];
    #pragma unroll
    for (int nt = 0; nt < 2; nt++)
        #pragma unroll
        for (int kc2 = 0; kc2 < 4; kc2++) {
            uint32_t chunk = (uint32_t)(((4 * kc2 + bj) ^ bsw) << 4);
            ldsm4(Brg[nt][kc2][0], Brg[nt][kc2][1], Brg[nt][kc2][2],
                  Brg[nt][kc2][3], sb + SW0 + brow + nt * 2048 + chunk);
        }

    float hprev[2][2][2];
    float acc[2][3][4];
    #pragma unroll
    for (int s = 0; s < 2; s++) {
        #pragma unroll
        for (int ri = 0; ri < 2; ri++)
            #pragma unroll
            for (int c = 0; c < 2; c++) hprev[s][ri][c] = 0.0f;
        #pragma unroll
        for (int rg = 0; rg < 4; rg++) {
            acc[s][0][rg] = 0.0f;
            acc[s][1][rg] = 0.0f;
            acc[s][2][rg] = bias_n[rg & 1];
        }
    }

    #pragma unroll 1
    for (int t = 0; t < TT; t++) {
        const int tcol = dir ? (TT - 1 - t) : t;
        const int* tokrow = g_tokT + tcol * BATCH + b0r;

        // xp gather for both streams (coalesced tokens, L2-resident table)
        float2 xp[2][2][3];
        #pragma unroll
        for (int s = 0; s < 2; s++)
            #pragma unroll
            for (int ri = 0; ri < 2; ri++) {
                int tok = tokrow[16 * s + 8 * ri + lr];
                const float2* xr = (const float2*)(xt + tok * GG + 24 * w);
                #pragma unroll
                for (int u = 0; u < 3; u++)
                    xp[s][ri][u] = xr[4 * u + lq];
            }

        #pragma unroll
        for (int ph = 0; ph < 2; ph++) {
            const int sm_ = 1 - ph;   // mma stream
            const int sg  = ph;       // gate stream

            // reset mma-stream accumulators
            #pragma unroll
            for (int rg = 0; rg < 4; rg++) {
                acc[sm_][0][rg] = 0.0f;
                acc[sm_][1][rg] = 0.0f;
                acc[sm_][2][rg] = bias_n[rg & 1];
            }

            const bool do_mma = ph ? (t < TT - 1) : (t > 0);
            const uint32_t ab0 = sb + SH16(sm_) + ar * 256;

            #pragma unroll
            for (int kc2 = 0; kc2 < 4; kc2++) {
                uint32_t a0[8];
                if (do_mma) {
                    uint32_t clo = (uint32_t)(((4 * kc2 + ahi) ^ asw) << 4);
                    uint32_t chi = (uint32_t)(((4 * kc2 + 2 + ahi) ^ asw) << 4);
                    ldsm4(a0[0], a0[1], a0[2], a0[3], ab0 + clo);
                    ldsm4(a0[4], a0[5], a0[6], a0[7], ab0 + chi);
                }

                // one gate cell of the gate stream, interleaved with mma
                {
                    const int ri = kc2 >> 1, c01 = kc2 & 1, rg = 2 * ri + c01;
                    float xr_ = (c01 ? xp[sg][ri][0].y : xp[sg][ri][0].x)
                                + acc[sg][0][rg];
                    float xz_ = (c01 ? xp[sg][ri][1].y : xp[sg][ri][1].x)
                                + acc[sg][1][rg];
                    float xn_ = (c01 ? xp[sg][ri][2].y : xp[sg][ri][2].x);
                    float nh  = acc[sg][2][rg];
                    float r = sigm_fast(xr_);
                    float z = sigm_fast(xz_);
                    float n = tanh_precise(fmaf(r, nh, xn_));
                    float h = fmaf(z, hprev[sg][ri][c01] - n, n);
                    hprev[sg][ri][c01] = h;
                    *(__half*)(smem + SH16(sg) + stoff[ri] + 2 * c01) =
                        __float2half_rn(h);
                }

                if (do_mma) {
                    mma16816(acc[sm_][0], a0 + 0, Brg[0][kc2][0], Brg[0][kc2][1]);
                    mma16816(acc[sm_][0], a0 + 4, Brg[0][kc2][2], Brg[0][kc2][3]);
                    mma16816(acc[sm_][1], a0 + 0, Brg[1][kc2][0], Brg[1][kc2][1]);
                    mma16816(acc[sm_][1], a0 + 4, Brg[1][kc2][2], Brg[1][kc2][3]);
                    uint32_t bh[4];
                    const uint32_t chunk =
                        (uint32_t)(((4 * kc2 + bj) ^ bsw) << 4);
                    ldsm4(bh[0], bh[1], bh[2], bh[3],
                          sb + SW0 + brow + 2 * 2048 + chunk);
                    mma16816(acc[sm_][2], a0 + 0, bh[0], bh[1]);
                    mma16816(acc[sm_][2], a0 + 4, bh[2], bh[3]);
                }
            }
            __syncthreads();
        }
    }

    // final hidden -> feat
    #pragma unroll
    for (int s = 0; s < 2; s++)
        #pragma unroll
        for (int ri = 0; ri < 2; ri++)
            #pragma unroll
            for (int c = 0; c < 2; c++) {
                int m = 16 * s + lr + 8 * ri;
                int j = 8 * w + 2 * lq + c;
                g_feat[(b0r + m) * EE + dir * HH + j] = hprev[s][ri][c];
            }
}

// ---------------------------------------------------------------------------
// Head v4: HB=16 rows per CTA, 512 threads (one row per warp), grid 128
// (single wave). Projection uses all 512 threads: thread = (col, 8-row half);
// proj_w streamed once per CTA (32MB total, half of the HB=8 version).
// ---------------------------------------------------------------------------
#define HB 16
__global__ __launch_bounds__(512) void head_kernel(
    const int* __restrict__ lang_ids,
    const float* __restrict__ down_w, const float* __restrict__ down_b,
    const float* __restrict__ up_b,
    const float* __restrict__ ln_g,   const float* __restrict__ ln_b,
    const float* __restrict__ proj_w, const float* __restrict__ proj_b,
    float* __restrict__ out) {
    __shared__ float y_s[HB][EE];
    const int tid = threadIdx.x, w = tid >> 5, lane = tid & 31;
    const int b0 = blockIdx.x * HB;
    const int b = b0 + w;                   // one row per warp (16 warps)
    const int l = lang_ids[b];
    const float* fb = g_feat + b * EE;

    // feat in grouped pattern: lane covers elems (lane&7)*4 + 32c
    float4 f4[8];
    #pragma unroll
    for (int c = 0; c < 8; c++)
        f4[c] = *(const float4*)(fb + (lane & 7) * 4 + 32 * c);

    // down-proj: 8 groups of 4 units, 8 lanes per unit
    float hid = 0.0f;
    const float* dwb = down_w + l * BNK * EE;
    #pragma unroll
    for (int g = 0; g < 8; g++) {
        const int d = 4 * g + (lane >> 3);
        const float* wr = dwb + d * EE + (lane & 7) * 4;
        float s = 0.0f;
        #pragma unroll
        for (int c = 0; c < 8; c++) {
            float4 wv = *(const float4*)(wr + 32 * c);
            s = fmaf(f4[c].x, wv.x, s); s = fmaf(f4[c].y, wv.y, s);
            s = fmaf(f4[c].z, wv.z, s); s = fmaf(f4[c].w, wv.w, s);
        }
        s += __shfl_xor_sync(0xffffffffu, s, 1);
        s += __shfl_xor_sync(0xffffffffu, s, 2);
        s += __shfl_xor_sync(0xffffffffu, s, 4);
        float got = __shfl_sync(0xffffffffu, s, (lane & 3) * 8);
        if ((lane >> 2) == g) hid = got;
    }
    hid += down_b[l * BNK + lane];
    hid = 0.5f * hid * (1.0f + erff(hid * 0.7071067811865476f));

    // up-proj (transposed weights) + residual + LN
    const float4 fx0 = *(const float4*)(fb + lane * 8);
    const float4 fx1 = *(const float4*)(fb + lane * 8 + 4);
    float4 a0 = *(const float4*)(up_b + l * EE + lane * 8);
    float4 a1 = *(const float4*)(up_b + l * EE + lane * 8 + 4);
    const float* uwb = g_upwT + l * BNK * EE;
    #pragma unroll 4
    for (int d = 0; d < BNK; d++) {
        float hd = __shfl_sync(0xffffffffu, hid, d);
        float4 u0 = *(const float4*)(uwb + d * EE + lane * 8);
        float4 u1 = *(const float4*)(uwb + d * EE + lane * 8 + 4);
        a0.x = fmaf(hd, u0.x, a0.x); a0.y = fmaf(hd, u0.y, a0.y);
        a0.z = fmaf(hd, u0.z, a0.z); a0.w = fmaf(hd, u0.w, a0.w);
        a1.x = fmaf(hd, u1.x, a1.x); a1.y = fmaf(hd, u1.y, a1.y);
        a1.z = fmaf(hd, u1.z, a1.z); a1.w = fmaf(hd, u1.w, a1.w);
    }
    float x[8] = {fx0.x + a0.x, fx0.y + a0.y, fx0.z + a0.z, fx0.w + a0.w,
                  fx1.x + a1.x, fx1.y + a1.y, fx1.z + a1.z, fx1.w + a1.w};
    float s1 = 0.0f, s2 = 0.0f;
    #pragma unroll
    for (int j = 0; j < 8; j++) { s1 += x[j]; s2 = fmaf(x[j], x[j], s2); }
    #pragma unroll
    for (int o = 16; o; o >>= 1) {
        s1 += __shfl_xor_sync(0xffffffffu, s1, o);
        s2 += __shfl_xor_sync(0xffffffffu, s2, o);
    }
    const float mu = s1 * (1.0f / EE);
    const float rstd = rsqrtf(s2 * (1.0f / EE) - mu * mu + 1e-5f);
    const float4 g0 = *(const float4*)(ln_g + l * EE + lane * 8);
    const float4 g1 = *(const float4*)(ln_g + l * EE + lane * 8 + 4);
    const float4 bb0 = *(const float4*)(ln_b + l * EE + lane * 8);
    const float4 bb1 = *(const float4*)(ln_b + l * EE + lane * 8 + 4);
    float4 y0, y1;
    y0.x = (x[0]-mu)*rstd*g0.x + bb0.x;  y0.y = (x[1]-mu)*rstd*g0.y + bb0.y;
    y0.z = (x[2]-mu)*rstd*g0.z + bb0.z;  y0.w = (x[3]-mu)*rstd*g0.w + bb0.w;
    y1.x = (x[4]-mu)*rstd*g1.x + bb1.x;  y1.y = (x[5]-mu)*rstd*g1.y + bb1.y;
    y1.z = (x[6]-mu)*rstd*g1.z + bb1.z;  y1.w = (x[7]-mu)*rstd*g1.w + bb1.w;
    *(float4*)(&y_s[w][lane * 8])     = y0;
    *(float4*)(&y_s[w][lane * 8 + 4]) = y1;
    __syncthreads();

    // projection: thread (col = tid&255, half = tid>>8) does 8 rows
    const int col  = tid & 255;
    const int r0   = (tid >> 8) * 8;
    float accv[8];
    #pragma unroll
    for (int r = 0; r < 8; r++) accv[r] = proj_b[col];
    const float* pw = proj_w + col * EE;
    for (int e = 0; e < EE; e += 4) {
        float4 wv = *(const float4*)(pw + e);
        #pragma unroll
        for (int r = 0; r < 8; r++) {
            float4 yv = *(const float4*)(&y_s[r0 + r][e]);
            accv[r] = fmaf(wv.x, yv.x, accv[r]);
            accv[r] = fmaf(wv.y, yv.y, accv[r]);
            accv[r] = fmaf(wv.z, yv.z, accv[r]);
            accv[r] = fmaf(wv.w, yv.w, accv[r]);
        }
    }
    #pragma unroll
    for (int r = 0; r < 8; r++) out[(b0 + r0 + r) * OO + col] = accv[r];
}

// ---------------------------------------------------------------------------
extern "C" void kernel_launch(void* const* d_in, const int* in_sizes, int n_in,
                              void* d_out, int out_size) {
    const int*   tokens = (const int*)d_in[0];
    const int*   lang   = (const int*)d_in[1];
    const float* ce     = (const float*)d_in[2];
    const float* wih_f  = (const float*)d_in[3];
    const float* whh_f  = (const float*)d_in[4];
    const float* bih_f  = (const float*)d_in[5];
    const float* bhh_f  = (const float*)d_in[6];
    const float* wih_b  = (const float*)d_in[7];
    const float* whh_b  = (const float*)d_in[8];
    const float* bih_b  = (const float*)d_in[9];
    const float* bhh_b  = (const float*)d_in[10];
    const float* down_w = (const float*)d_in[11];
    const float* down_b = (const float*)d_in[12];
    const float* up_w   = (const float*)d_in[13];
    const float* up_b   = (const float*)d_in[14];
    const float* ln_g   = (const float*)d_in[15];
    const float* ln_b   = (const float*)d_in[16];
    const float* proj_w = (const float*)d_in[17];
    const float* proj_b = (const float*)d_in[18];
    float* out = (float*)d_out;

    cudaFuncSetAttribute(gru_mma_kernel,
                         cudaFuncAttributeMaxDynamicSharedMemorySize, SMEM_TOTAL);
    const size_t xsmem = (size_t)(GG * CC + GG + 32 * CC) * sizeof(float);
    cudaFuncSetAttribute(xtab_kernel,
                         cudaFuncAttributeMaxDynamicSharedMemorySize, (int)xsmem);

    const int prep_elems = 2 * GG * HH + NLN * EE * BNK + BATCH * TT;
    prep_misc<<<(prep_elems + 255) / 256, 256>>>(whh_f, whh_b, up_w, tokens);
    xtab_kernel<<<dim3(8, 2), GG, xsmem>>>(ce, wih_f, bih_f, wih_b, bih_b,
                                           bhh_f, bhh_b);
    gru_mma_kernel<<<dim3(BATCH / BM, 2), NTH, SMEM_TOTAL>>>(bhh_f, bhh_b);
    head_kernel<<<BATCH / HB, 512>>>(lang, down_w, down_b, up_b,
                                     ln_g, ln_b, proj_w, proj_b, out);
}

// round 11
// speedup vs baseline: 1.2064x; 1.0630x over previous
#include <cuda_runtime.h>
#include <cuda_fp16.h>
#include <cuda_bf16.h>
#include <math.h>
#include <stdint.h>

// Problem dims
#define BATCH 2048
#define TT    128
#define VV    256
#define CC    32
#define HH    128
#define EE    256
#define GG    384   // 3*H
#define OO    256
#define NLN   3
#define BNK   32

// GRU tiling
#define BM    32      // batch rows per CTA (2 streams x 16)
#define NTH   512     // 16 warps, 24 gate-cols each
// SMEM byte offsets
#define SW0   0                   // w fp16: [384][128] half, swizzled (96KB)
#define SH16(s) (98304 + (s) * 4096)   // h fp16 per stream [16][128]
#define SMEM_TOTAL 106496

// Head SMEM layout (dynamic): pw16 128KB | y hi 8KB | y lo 8KB
#define HPW   0
#define HYHI  131072
#define HYLO  139264
#define HEAD_SMEM 147456

// Scratch (static device globals)
__device__ __align__(16) __half g_w0[2 * GG * HH];  // [dir][p][k] fp16
__device__ float g_xtab[2 * VV * GG];   // permuted x@w_ih^T + b_ih (+b_hh r,z)
__device__ float g_feat[BATCH * EE];
__device__ float g_upwT[NLN * BNK * EE]; // up_w transposed: [l][d][e]
__device__ int   g_tokT[TT * BATCH];     // tokens transposed [t][b]
__device__ __align__(16) __half g_pw16[OO * EE];  // proj_w fp16, swizzled rows

// ---------------------------------------------------------------------------
// Activations (R6-exact): precise n-tanh; HW tanh for r/z sigmoids.
// ---------------------------------------------------------------------------
__device__ __forceinline__ float sigm_precise(float x) {
    float t = fminf(x * 1.4426950408889634f, 80.0f);
    float e; asm("ex2.approx.f32 %0, %1;" : "=f"(e) : "f"(t));
    float d = 1.0f + e;
    float y; asm("rcp.approx.f32 %0, %1;" : "=f"(y) : "f"(d));
    y = y * fmaf(-d, y, 2.0f);
    return e * y;
}
__device__ __forceinline__ float tanh_precise(float x) {
    return fmaf(2.0f, sigm_precise(2.0f * x), -1.0f);
}
__device__ __forceinline__ float tanh_hw(float x) {
    float y; asm("tanh.approx.f32 %0, %1;" : "=f"(y) : "f"(x));
    return y;
}
__device__ __forceinline__ float sigm_fast(float x) {
    return fmaf(tanh_hw(0.5f * x), 0.5f, 0.5f);
}

// ---------------------------------------------------------------------------
// MMA / ldmatrix wrappers
// ---------------------------------------------------------------------------
__device__ __forceinline__ void ldsm4(uint32_t& r0, uint32_t& r1, uint32_t& r2,
                                      uint32_t& r3, uint32_t addr) {
    asm volatile("ldmatrix.sync.aligned.m8n8.x4.shared.b16 {%0,%1,%2,%3}, [%4];"
                 : "=r"(r0), "=r"(r1), "=r"(r2), "=r"(r3) : "r"(addr));
}
__device__ __forceinline__ void mma16816(float* d, const uint32_t* a,
                                         uint32_t b0, uint32_t b1) {
    asm volatile(
        "mma.sync.aligned.m16n8k16.row.col.f32.f16.f16.f32 "
        "{%0,%1,%2,%3}, {%4,%5,%6,%7}, {%8,%9}, {%0,%1,%2,%3};"
        : "+f"(d[0]), "+f"(d[1]), "+f"(d[2]), "+f"(d[3])
        : "r"(a[0]), "r"(a[1]), "r"(a[2]), "r"(a[3]), "r"(b0), "r"(b1));
}

// gate-dim permutation: orig g = t*128 + j -> p = 24*(j>>3) + 8*t + (j&7)
__device__ __forceinline__ int permute_g(int g) {
    int t = g >> 7, j = g & 127;
    return 24 * (j >> 3) + 8 * t + (j & 7);
}

// ---------------------------------------------------------------------------
// Prep A: xtab (permuted). b_ih + b_hh(r,z) folded (R6-exact).
// ---------------------------------------------------------------------------
__global__ void xtab_kernel(const float* __restrict__ ce,
                            const float* __restrict__ wih_f, const float* __restrict__ bih_f,
                            const float* __restrict__ wih_b, const float* __restrict__ bih_b,
                            const float* __restrict__ bhh_f, const float* __restrict__ bhh_b) {
    extern __shared__ float xsm[];
    float* ws = xsm;               // [384*32]
    float* bs = ws + GG * CC;      // [384]
    float* cs = bs + GG;           // [32*32]
    const int d = blockIdx.y, g = threadIdx.x;
    const float* wih = d ? wih_b : wih_f;
    const float* bih = d ? bih_b : bih_f;
    const float* bhh = d ? bhh_b : bhh_f;
    for (int i = g; i < GG * CC; i += GG) ws[i] = wih[i];
    bs[g] = bih[g] + (g < 2 * HH ? bhh[g] : 0.0f);
    const int v0 = blockIdx.x * 32;
    for (int i = g; i < 32 * CC; i += GG) cs[i] = ce[v0 * CC + i];
    __syncthreads();
    const int p = permute_g(g);
    for (int vi = 0; vi < 32; vi++) {
        float s = bs[g];
        #pragma unroll
        for (int c = 0; c < CC; c++) s = fmaf(cs[vi * CC + c], ws[g * CC + c], s);
        g_xtab[(d * VV + v0 + vi) * GG + p] = s;
    }
}

// ---------------------------------------------------------------------------
// Prep B (fused): w_hh fp16 permuted + up_w transpose + tokens transpose
// + proj_w fp16 (swizzled rows for ldmatrix B).
// ---------------------------------------------------------------------------
#define PREP_N0 (2 * GG * HH)
#define PREP_N1 (PREP_N0 + NLN * EE * BNK)
#define PREP_N2 (PREP_N1 + BATCH * TT)
#define PREP_N3 (PREP_N2 + OO * EE)
__global__ void prep_misc(const float* __restrict__ whh_f,
                          const float* __restrict__ whh_b,
                          const float* __restrict__ up_w,
                          const int* __restrict__ tokens,
                          const float* __restrict__ proj_w) {
    const int i = blockIdx.x * 256 + threadIdx.x;
    if (i < PREP_N0) {
        int d = i / (GG * HH), rem = i % (GG * HH);
        int g = rem / HH, k = rem % HH;
        const float* w = d ? whh_b : whh_f;
        g_w0[d * GG * HH + permute_g(g) * HH + k] = __float2half_rn(w[g * HH + k]);
    } else if (i < PREP_N1) {
        int j = i - PREP_N0;
        int l = j / (EE * BNK), rem = j % (EE * BNK);
        int e = rem / BNK, dd = rem % BNK;
        g_upwT[(l * BNK + dd) * EE + e] = up_w[j];
    } else if (i < PREP_N2) {
        int j = i - PREP_N1;
        int b = j / TT, t = j % TT;
        g_tokT[t * BATCH + b] = tokens[j];
    } else if (i < PREP_N3) {
        int j = i - PREP_N2;
        int o = j >> 8, e = j & 255;
        // swizzled row layout: 16B chunk c=e>>3 -> position (c ^ (o&7)) low bits
        int pos = (((e >> 3) ^ (o & 7)) << 3) | (e & 7);
        g_pw16[o * EE + pos] = __float2half_rn(proj_w[j]);
    }
}

// ---------------------------------------------------------------------------
// GRU via mma (R6-exact, untouched). grid (64, 2) x 512 threads.
// ---------------------------------------------------------------------------
__global__ __launch_bounds__(NTH, 1) void gru_mma_kernel(
    const float* __restrict__ bhh_f, const float* __restrict__ bhh_b) {
    extern __shared__ __align__(16) char smem[];
    const uint32_t sb = (uint32_t)__cvta_generic_to_shared(smem);

    const int dir  = blockIdx.y;
    const int b0r  = blockIdx.x * BM;
    const int tid  = threadIdx.x;
    const int w    = tid >> 5;      // 0..15
    const int lane = tid & 31;
    const int lr   = lane >> 2;     // 0..7
    const int lq   = lane & 3;      // 0..3

    const float* bhh = dir ? bhh_b : bhh_f;
    const float* xt  = g_xtab + dir * VV * GG;

    // ---- load w (swizzled) + zero h buffers ----
    {
        const uint4* gw0 = (const uint4*)(g_w0 + dir * (GG * HH));
        for (int idx = tid; idx < GG * 16; idx += NTH) {
            int n = idx >> 4, c = idx & 15;
            int off = n * 256 + ((c ^ (n & 7)) << 4);
            *(uint4*)(smem + SW0 + off) = gw0[idx];
        }
        for (int idx = tid; idx < 512; idx += NTH)
            ((uint4*)(smem + SH16(0)))[idx] = make_uint4(0, 0, 0, 0);
    }

    // n-gate bias only (r,z folded into xtab)
    float bias_n[2];
    #pragma unroll
    for (int c = 0; c < 2; c++)
        bias_n[c] = bhh[2 * 128 + 8 * w + 2 * lq + c];

    // ldmatrix addressing constants
    const int ar  = lane & 15;
    const int ahi = lane >> 4;
    const int asw = ar & 7;
    const int bj  = lane >> 3;
    const int bsw = lane & 7;
    const int brow = (24 * w + (lane & 7)) * 256;

    // h' store offsets (chunk index = w since unit j = 8w + ..)
    int stoff[2];
    #pragma unroll
    for (int ri = 0; ri < 2; ri++)
        stoff[ri] = (lr + 8 * ri) * 256 + ((w ^ lr) << 4) + 4 * lq;

    __syncthreads();

    // ---- cache B fragments for gate groups nt=0,1 (loop-invariant) ----
    uint32_t Brg[2][4][4];
    #pragma unroll
    for (int nt = 0; nt < 2; nt++)
        #pragma unroll
        for (int kc2 = 0; kc2 < 4; kc2++) {
            uint32_t chunk = (uint32_t)(((4 * kc2 + bj) ^ bsw) << 4);
            ldsm4(Brg[nt][kc2][0], Brg[nt][kc2][1], Brg[nt][kc2][2],
                  Brg[nt][kc2][3], sb + SW0 + brow + nt * 2048 + chunk);
        }

    float hprev[2][2][2];
    float acc[2][3][4];
    #pragma unroll
    for (int s = 0; s < 2; s++) {
        #pragma unroll
        for (int ri = 0; ri < 2; ri++)
            #pragma unroll
            for (int c = 0; c < 2; c++) hprev[s][ri][c] = 0.0f;
        #pragma unroll
        for (int rg = 0; rg < 4; rg++) {
            acc[s][0][rg] = 0.0f;
            acc[s][1][rg] = 0.0f;
            acc[s][2][rg] = bias_n[rg & 1];
        }
    }

    #pragma unroll 1
    for (int t = 0; t < TT; t++) {
        const int tcol = dir ? (TT - 1 - t) : t;
        const int* tokrow = g_tokT + tcol * BATCH + b0r;

        // xp gather for both streams (coalesced tokens, L2-resident table)
        float2 xp[2][2][3];
        #pragma unroll
        for (int s = 0; s < 2; s++)
            #pragma unroll
            for (int ri = 0; ri < 2; ri++) {
                int tok = tokrow[16 * s + 8 * ri + lr];
                const float2* xr = (const float2*)(xt + tok * GG + 24 * w);
                #pragma unroll
                for (int u = 0; u < 3; u++)
                    xp[s][ri][u] = xr[4 * u + lq];
            }

        #pragma unroll
        for (int ph = 0; ph < 2; ph++) {
            const int sm_ = 1 - ph;   // mma stream
            const int sg  = ph;       // gate stream

            // reset mma-stream accumulators
            #pragma unroll
            for (int rg = 0; rg < 4; rg++) {
                acc[sm_][0][rg] = 0.0f;
                acc[sm_][1][rg] = 0.0f;
                acc[sm_][2][rg] = bias_n[rg & 1];
            }

            const bool do_mma = ph ? (t < TT - 1) : (t > 0);
            const uint32_t ab0 = sb + SH16(sm_) + ar * 256;

            #pragma unroll
            for (int kc2 = 0; kc2 < 4; kc2++) {
                uint32_t a0[8];
                if (do_mma) {
                    uint32_t clo = (uint32_t)(((4 * kc2 + ahi) ^ asw) << 4);
                    uint32_t chi = (uint32_t)(((4 * kc2 + 2 + ahi) ^ asw) << 4);
                    ldsm4(a0[0], a0[1], a0[2], a0[3], ab0 + clo);
                    ldsm4(a0[4], a0[5], a0[6], a0[7], ab0 + chi);
                }

                // one gate cell of the gate stream, interleaved with mma
                {
                    const int ri = kc2 >> 1, c01 = kc2 & 1, rg = 2 * ri + c01;
                    float xr_ = (c01 ? xp[sg][ri][0].y : xp[sg][ri][0].x)
                                + acc[sg][0][rg];
                    float xz_ = (c01 ? xp[sg][ri][1].y : xp[sg][ri][1].x)
                                + acc[sg][1][rg];
                    float xn_ = (c01 ? xp[sg][ri][2].y : xp[sg][ri][2].x);
                    float nh  = acc[sg][2][rg];
                    float r = sigm_fast(xr_);
                    float z = sigm_fast(xz_);
                    float n = tanh_precise(fmaf(r, nh, xn_));
                    float h = fmaf(z, hprev[sg][ri][c01] - n, n);
                    hprev[sg][ri][c01] = h;
                    *(__half*)(smem + SH16(sg) + stoff[ri] + 2 * c01) =
                        __float2half_rn(h);
                }

                if (do_mma) {
                    mma16816(acc[sm_][0], a0 + 0, Brg[0][kc2][0], Brg[0][kc2][1]);
                    mma16816(acc[sm_][0], a0 + 4, Brg[0][kc2][2], Brg[0][kc2][3]);
                    mma16816(acc[sm_][1], a0 + 0, Brg[1][kc2][0], Brg[1][kc2][1]);
                    mma16816(acc[sm_][1], a0 + 4, Brg[1][kc2][2], Brg[1][kc2][3]);
                    uint32_t bh[4];
                    const uint32_t chunk =
                        (uint32_t)(((4 * kc2 + bj) ^ bsw) << 4);
                    ldsm4(bh[0], bh[1], bh[2], bh[3],
                          sb + SW0 + brow + 2 * 2048 + chunk);
                    mma16816(acc[sm_][2], a0 + 0, bh[0], bh[1]);
                    mma16816(acc[sm_][2], a0 + 4, bh[2], bh[3]);
                }
            }
            __syncthreads();
        }
    }

    // final hidden -> feat
    #pragma unroll
    for (int s = 0; s < 2; s++)
        #pragma unroll
        for (int ri = 0; ri < 2; ri++)
            #pragma unroll
            for (int c = 0; c < 2; c++) {
                int m = 16 * s + lr + 8 * ri;
                int j = 8 * w + 2 * lq + c;
                g_feat[(b0r + m) * EE + dir * HH + j] = hprev[s][ri][c];
            }
}

// ---------------------------------------------------------------------------
// Head v5: HB=16 rows, 512 threads, grid 128 (single wave).
// Adapter+LN per warp (R10-proven), then PROJECTION VIA MMA:
//   A = y (16 x 256) fp16 hi/lo split in SMEM; B = proj_w fp16 (SMEM, 128KB).
//   warp w computes output cols [16w, 16w+16).
// ---------------------------------------------------------------------------
#define HB 16
__global__ __launch_bounds__(512) void head_kernel(
    const int* __restrict__ lang_ids,
    const float* __restrict__ down_w, const float* __restrict__ down_b,
    const float* __restrict__ up_b,
    const float* __restrict__ ln_g,   const float* __restrict__ ln_b,
    const float* __restrict__ proj_b,
    float* __restrict__ out) {
    extern __shared__ __align__(16) char hsm[];
    const uint32_t sb = (uint32_t)__cvta_generic_to_shared(hsm);
    const int tid = threadIdx.x, w = tid >> 5, lane = tid & 31;
    const int b0 = blockIdx.x * HB;
    const int b = b0 + w;                   // one row per warp (16 warps)
    const int l = lang_ids[b];
    const float* fb = g_feat + b * EE;

    // kick off proj_w copy to SMEM (completes before the post-LN sync)
    {
        const uint4* gp = (const uint4*)g_pw16;
        #pragma unroll
        for (int k = 0; k < 16; k++)
            ((uint4*)(hsm + HPW))[tid + 512 * k] = gp[tid + 512 * k];
    }

    // ---- adapter (R10-proven, one row per warp) ----
    float4 f4[8];
    #pragma unroll
    for (int c = 0; c < 8; c++)
        f4[c] = *(const float4*)(fb + (lane & 7) * 4 + 32 * c);

    float hid = 0.0f;
    const float* dwb = down_w + l * BNK * EE;
    #pragma unroll
    for (int g = 0; g < 8; g++) {
        const int d = 4 * g + (lane >> 3);
        const float* wr = dwb + d * EE + (lane & 7) * 4;
        float s = 0.0f;
        #pragma unroll
        for (int c = 0; c < 8; c++) {
            float4 wv = *(const float4*)(wr + 32 * c);
            s = fmaf(f4[c].x, wv.x, s); s = fmaf(f4[c].y, wv.y, s);
            s = fmaf(f4[c].z, wv.z, s); s = fmaf(f4[c].w, wv.w, s);
        }
        s += __shfl_xor_sync(0xffffffffu, s, 1);
        s += __shfl_xor_sync(0xffffffffu, s, 2);
        s += __shfl_xor_sync(0xffffffffu, s, 4);
        float got = __shfl_sync(0xffffffffu, s, (lane & 3) * 8);
        if ((lane >> 2) == g) hid = got;
    }
    hid += down_b[l * BNK + lane];
    hid = 0.5f * hid * (1.0f + erff(hid * 0.7071067811865476f));

    const float4 fx0 = *(const float4*)(fb + lane * 8);
    const float4 fx1 = *(const float4*)(fb + lane * 8 + 4);
    float4 a0 = *(const float4*)(up_b + l * EE + lane * 8);
    float4 a1 = *(const float4*)(up_b + l * EE + lane * 8 + 4);
    const float* uwb = g_upwT + l * BNK * EE;
    #pragma unroll 4
    for (int d = 0; d < BNK; d++) {
        float hd = __shfl_sync(0xffffffffu, hid, d);
        float4 u0 = *(const float4*)(uwb + d * EE + lane * 8);
        float4 u1 = *(const float4*)(uwb + d * EE + lane * 8 + 4);
        a0.x = fmaf(hd, u0.x, a0.x); a0.y = fmaf(hd, u0.y, a0.y);
        a0.z = fmaf(hd, u0.z, a0.z); a0.w = fmaf(hd, u0.w, a0.w);
        a1.x = fmaf(hd, u1.x, a1.x); a1.y = fmaf(hd, u1.y, a1.y);
        a1.z = fmaf(hd, u1.z, a1.z); a1.w = fmaf(hd, u1.w, a1.w);
    }
    float x[8] = {fx0.x + a0.x, fx0.y + a0.y, fx0.z + a0.z, fx0.w + a0.w,
                  fx1.x + a1.x, fx1.y + a1.y, fx1.z + a1.z, fx1.w + a1.w};
    float s1 = 0.0f, s2 = 0.0f;
    #pragma unroll
    for (int j = 0; j < 8; j++) { s1 += x[j]; s2 = fmaf(x[j], x[j], s2); }
    #pragma unroll
    for (int o = 16; o; o >>= 1) {
        s1 += __shfl_xor_sync(0xffffffffu, s1, o);
        s2 += __shfl_xor_sync(0xffffffffu, s2, o);
    }
    const float mu = s1 * (1.0f / EE);
    const float rstd = rsqrtf(s2 * (1.0f / EE) - mu * mu + 1e-5f);
    const float4 g0 = *(const float4*)(ln_g + l * EE + lane * 8);
    const float4 g1 = *(const float4*)(ln_g + l * EE + lane * 8 + 4);
    const float4 bb0 = *(const float4*)(ln_b + l * EE + lane * 8);
    const float4 bb1 = *(const float4*)(ln_b + l * EE + lane * 8 + 4);
    float y[8];
    y[0] = (x[0]-mu)*rstd*g0.x + bb0.x;  y[1] = (x[1]-mu)*rstd*g0.y + bb0.y;
    y[2] = (x[2]-mu)*rstd*g0.z + bb0.z;  y[3] = (x[3]-mu)*rstd*g0.w + bb0.w;
    y[4] = (x[4]-mu)*rstd*g1.x + bb1.x;  y[5] = (x[5]-mu)*rstd*g1.y + bb1.y;
    y[6] = (x[6]-mu)*rstd*g1.z + bb1.z;  y[7] = (x[7]-mu)*rstd*g1.w + bb1.w;

    // fp16 hi/lo split -> SMEM (lane = 16B chunk index, XOR-swizzled by row)
    {
        __half h_[8], c_[8];
        #pragma unroll
        for (int j = 0; j < 8; j++) {
            h_[j] = __float2half_rn(y[j]);
            c_[j] = __float2half_rn(y[j] - __half2float(h_[j]));
        }
        const int off = w * 512 + ((lane ^ (w & 7)) << 4);
        *(uint4*)(hsm + HYHI + off) = *(const uint4*)h_;
        *(uint4*)(hsm + HYLO + off) = *(const uint4*)c_;
    }
    __syncthreads();

    // ---- projection via mma: warp w -> output cols [16w, 16w+16) ----
    const int ar  = lane & 15;           // A row
    const int ahi = lane >> 4;
    const int asw = ar & 7;
    const int bj  = lane >> 3;           // B k-chunk within k32
    const int bsw = lane & 7;
    const uint32_t ahib = sb + HYHI + ar * 512;
    const uint32_t alob = sb + HYLO + ar * 512;
    const uint32_t brow0 = sb + HPW + (16 * w + (lane & 7)) * 512;
    const uint32_t brow1 = brow0 + 8 * 512;

    const int lr = lane >> 2, lq = lane & 3;
    float pb0 = proj_b[16 * w + 2 * lq];
    float pb1 = proj_b[16 * w + 2 * lq + 1];
    float pb8 = proj_b[16 * w + 8 + 2 * lq];
    float pb9 = proj_b[16 * w + 8 + 2 * lq + 1];
    float acc[2][4] = {{pb0, pb1, pb0, pb1}, {pb8, pb9, pb8, pb9}};

    #pragma unroll
    for (int kc32 = 0; kc32 < 8; kc32++) {
        uint32_t ah[8], al[8], bF0[4], bF1[4];
        uint32_t clo = (uint32_t)(((4 * kc32 + ahi) ^ asw) << 4);
        uint32_t chi = (uint32_t)(((4 * kc32 + 2 + ahi) ^ asw) << 4);
        ldsm4(ah[0], ah[1], ah[2], ah[3], ahib + clo);
        ldsm4(ah[4], ah[5], ah[6], ah[7], ahib + chi);
        ldsm4(al[0], al[1], al[2], al[3], alob + clo);
        ldsm4(al[4], al[5], al[6], al[7], alob + chi);
        uint32_t bc = (uint32_t)(((4 * kc32 + bj) ^ bsw) << 4);
        ldsm4(bF0[0], bF0[1], bF0[2], bF0[3], brow0 + bc);
        ldsm4(bF1[0], bF1[1], bF1[2], bF1[3], brow1 + bc);
        #pragma unroll
        for (int kk = 0; kk < 2; kk++) {
            mma16816(acc[0], ah + 4 * kk, bF0[2 * kk], bF0[2 * kk + 1]);
            mma16816(acc[0], al + 4 * kk, bF0[2 * kk], bF0[2 * kk + 1]);
            mma16816(acc[1], ah + 4 * kk, bF1[2 * kk], bF1[2 * kk + 1]);
            mma16816(acc[1], al + 4 * kk, bF1[2 * kk], bF1[2 * kk + 1]);
        }
    }

    // write out: c-frag: regs {0,1} row lr, {2,3} row lr+8; cols 2lq+{0,1}
    #pragma unroll
    for (int nt = 0; nt < 2; nt++) {
        const int col = 16 * w + 8 * nt + 2 * lq;
        *(float2*)(out + (b0 + lr) * OO + col)
            = make_float2(acc[nt][0], acc[nt][1]);
        *(float2*)(out + (b0 + lr + 8) * OO + col)
            = make_float2(acc[nt][2], acc[nt][3]);
    }
}

// ---------------------------------------------------------------------------
extern "C" void kernel_launch(void* const* d_in, const int* in_sizes, int n_in,
                              void* d_out, int out_size) {
    const int*   tokens = (const int*)d_in[0];
    const int*   lang   = (const int*)d_in[1];
    const float* ce     = (const float*)d_in[2];
    const float* wih_f  = (const float*)d_in[3];
    const float* whh_f  = (const float*)d_in[4];
    const float* bih_f  = (const float*)d_in[5];
    const float* bhh_f  = (const float*)d_in[6];
    const float* wih_b  = (const float*)d_in[7];
    const float* whh_b  = (const float*)d_in[8];
    const float* bih_b  = (const float*)d_in[9];
    const float* bhh_b  = (const float*)d_in[10];
    const float* down_w = (const float*)d_in[11];
    const float* down_b = (const float*)d_in[12];
    const float* up_w   = (const float*)d_in[13];
    const float* up_b   = (const float*)d_in[14];
    const float* ln_g   = (const float*)d_in[15];
    const float* ln_b   = (const float*)d_in[16];
    const float* proj_w = (const float*)d_in[17];
    const float* proj_b = (const float*)d_in[18];
    float* out = (float*)d_out;

    cudaFuncSetAttribute(gru_mma_kernel,
                         cudaFuncAttributeMaxDynamicSharedMemorySize, SMEM_TOTAL);
    cudaFuncSetAttribute(head_kernel,
                         cudaFuncAttributeMaxDynamicSharedMemorySize, HEAD_SMEM);
    const size_t xsmem = (size_t)(GG * CC + GG + 32 * CC) * sizeof(float);
    cudaFuncSetAttribute(xtab_kernel,
                         cudaFuncAttributeMaxDynamicSharedMemorySize, (int)xsmem);

    prep_misc<<<(PREP_N3 + 255) / 256, 256>>>(whh_f, whh_b, up_w, tokens, proj_w);
    xtab_kernel<<<dim3(8, 2), GG, xsmem>>>(ce, wih_f, bih_f, wih_b, bih_b,
                                           bhh_f, bhh_b);
    gru_mma_kernel<<<dim3(BATCH / BM, 2), NTH, SMEM_TOTAL>>>(bhh_f, bhh_b);
    head_kernel<<<BATCH / HB, 512, HEAD_SMEM>>>(lang, down_w, down_b, up_b,
                                                ln_g, ln_b, proj_b, out);
}

// round 12
// speedup vs baseline: 1.2091x; 1.0023x over previous
#include <cuda_runtime.h>
#include <cuda_fp16.h>
#include <cuda_bf16.h>
#include <math.h>
#include <stdint.h>

// Problem dims
#define BATCH 2048
#define TT    128
#define VV    256
#define CC    32
#define HH    128
#define EE    256
#define GG    384   // 3*H
#define OO    256
#define NLN   3
#define BNK   32

// GRU tiling
#define BM    32      // batch rows per CTA (2 streams x 16)
#define NTH   512     // 16 warps, 24 gate-cols each
// SMEM byte offsets
#define SW0   0                   // w fp16: [384][128] half, swizzled (96KB)
#define SH16(s) (98304 + (s) * 4096)   // h fp16 per stream [16][128]
#define SMEM_TOTAL 106496

// Head SMEM: phase A = down_w fp32 (96KB) | up_wT fp32 (96KB); y hi/lo 16KB.
// Phase B reuses [0,128KB) of the weight region for proj_w fp16.
#define HDOWN 0
#define HUP   98304
#define HYHI  196608
#define HYLO  204800
#define HEAD_SMEM 212992

// Scratch (static device globals)
__device__ __align__(16) __half g_w0[2 * GG * HH];  // [dir][p][k] fp16
__device__ float g_xtab[2 * VV * GG];   // permuted x@w_ih^T + b_ih (+b_hh r,z)
__device__ float g_feat[BATCH * EE];
__device__ float g_upwT[NLN * BNK * EE]; // up_w transposed: [l][d][e]
__device__ int   g_tokT[TT * BATCH];     // tokens transposed [t][b]
__device__ __align__(16) __half g_pw16[OO * EE];  // proj_w fp16, swizzled rows

// ---------------------------------------------------------------------------
// Activations (R6-exact): precise n-tanh; HW tanh for r/z sigmoids.
// ---------------------------------------------------------------------------
__device__ __forceinline__ float sigm_precise(float x) {
    float t = fminf(x * 1.4426950408889634f, 80.0f);
    float e; asm("ex2.approx.f32 %0, %1;" : "=f"(e) : "f"(t));
    float d = 1.0f + e;
    float y; asm("rcp.approx.f32 %0, %1;" : "=f"(y) : "f"(d));
    y = y * fmaf(-d, y, 2.0f);
    return e * y;
}
__device__ __forceinline__ float tanh_precise(float x) {
    return fmaf(2.0f, sigm_precise(2.0f * x), -1.0f);
}
__device__ __forceinline__ float tanh_hw(float x) {
    float y; asm("tanh.approx.f32 %0, %1;" : "=f"(y) : "f"(x));
    return y;
}
__device__ __forceinline__ float sigm_fast(float x) {
    return fmaf(tanh_hw(0.5f * x), 0.5f, 0.5f);
}

// ---------------------------------------------------------------------------
// MMA / ldmatrix wrappers
// ---------------------------------------------------------------------------
__device__ __forceinline__ void ldsm4(uint32_t& r0, uint32_t& r1, uint32_t& r2,
                                      uint32_t& r3, uint32_t addr) {
    asm volatile("ldmatrix.sync.aligned.m8n8.x4.shared.b16 {%0,%1,%2,%3}, [%4];"
                 : "=r"(r0), "=r"(r1), "=r"(r2), "=r"(r3) : "r"(addr));
}
__device__ __forceinline__ void mma16816(float* d, const uint32_t* a,
                                         uint32_t b0, uint32_t b1) {
    asm volatile(
        "mma.sync.aligned.m16n8k16.row.col.f32.f16.f16.f32 "
        "{%0,%1,%2,%3}, {%4,%5,%6,%7}, {%8,%9}, {%0,%1,%2,%3};"
        : "+f"(d[0]), "+f"(d[1]), "+f"(d[2]), "+f"(d[3])
        : "r"(a[0]), "r"(a[1]), "r"(a[2]), "r"(a[3]), "r"(b0), "r"(b1));
}

// gate-dim permutation: orig g = t*128 + j -> p = 24*(j>>3) + 8*t + (j&7)
__device__ __forceinline__ int permute_g(int g) {
    int t = g >> 7, j = g & 127;
    return 24 * (j >> 3) + 8 * t + (j & 7);
}

// ---------------------------------------------------------------------------
// Prep A: xtab (permuted). b_ih + b_hh(r,z) folded (R6-exact).
// ---------------------------------------------------------------------------
__global__ void xtab_kernel(const float* __restrict__ ce,
                            const float* __restrict__ wih_f, const float* __restrict__ bih_f,
                            const float* __restrict__ wih_b, const float* __restrict__ bih_b,
                            const float* __restrict__ bhh_f, const float* __restrict__ bhh_b) {
    extern __shared__ float xsm[];
    float* ws = xsm;               // [384*32]
    float* bs = ws + GG * CC;      // [384]
    float* cs = bs + GG;           // [32*32]
    const int d = blockIdx.y, g = threadIdx.x;
    const float* wih = d ? wih_b : wih_f;
    const float* bih = d ? bih_b : bih_f;
    const float* bhh = d ? bhh_b : bhh_f;
    for (int i = g; i < GG * CC; i += GG) ws[i] = wih[i];
    bs[g] = bih[g] + (g < 2 * HH ? bhh[g] : 0.0f);
    const int v0 = blockIdx.x * 32;
    for (int i = g; i < 32 * CC; i += GG) cs[i] = ce[v0 * CC + i];
    __syncthreads();
    const int p = permute_g(g);
    for (int vi = 0; vi < 32; vi++) {
        float s = bs[g];
        #pragma unroll
        for (int c = 0; c < CC; c++) s = fmaf(cs[vi * CC + c], ws[g * CC + c], s);
        g_xtab[(d * VV + v0 + vi) * GG + p] = s;
    }
}

// ---------------------------------------------------------------------------
// Prep B (fused): w_hh fp16 permuted + up_w transpose + tokens transpose
// + proj_w fp16 (swizzled rows for ldmatrix B).
// ---------------------------------------------------------------------------
#define PREP_N0 (2 * GG * HH)
#define PREP_N1 (PREP_N0 + NLN * EE * BNK)
#define PREP_N2 (PREP_N1 + BATCH * TT)
#define PREP_N3 (PREP_N2 + OO * EE)
__global__ void prep_misc(const float* __restrict__ whh_f,
                          const float* __restrict__ whh_b,
                          const float* __restrict__ up_w,
                          const int* __restrict__ tokens,
                          const float* __restrict__ proj_w) {
    const int i = blockIdx.x * 256 + threadIdx.x;
    if (i < PREP_N0) {
        int d = i / (GG * HH), rem = i % (GG * HH);
        int g = rem / HH, k = rem % HH;
        const float* w = d ? whh_b : whh_f;
        g_w0[d * GG * HH + permute_g(g) * HH + k] = __float2half_rn(w[g * HH + k]);
    } else if (i < PREP_N1) {
        int j = i - PREP_N0;
        int l = j / (EE * BNK), rem = j % (EE * BNK);
        int e = rem / BNK, dd = rem % BNK;
        g_upwT[(l * BNK + dd) * EE + e] = up_w[j];
    } else if (i < PREP_N2) {
        int j = i - PREP_N1;
        int b = j / TT, t = j % TT;
        g_tokT[t * BATCH + b] = tokens[j];
    } else if (i < PREP_N3) {
        int j = i - PREP_N2;
        int o = j >> 8, e = j & 255;
        // swizzled row layout: 16B chunk c=e>>3 -> position (c ^ (o&7)) low bits
        int pos = (((e >> 3) ^ (o & 7)) << 3) | (e & 7);
        g_pw16[o * EE + pos] = __float2half_rn(proj_w[j]);
    }
}

// ---------------------------------------------------------------------------
// GRU via mma (R6-exact, untouched). grid (64, 2) x 512 threads.
// ---------------------------------------------------------------------------
__global__ __launch_bounds__(NTH, 1) void gru_mma_kernel(
    const float* __restrict__ bhh_f, const float* __restrict__ bhh_b) {
    extern __shared__ __align__(16) char smem[];
    const uint32_t sb = (uint32_t)__cvta_generic_to_shared(smem);

    const int dir  = blockIdx.y;
    const int b0r  = blockIdx.x * BM;
    const int tid  = threadIdx.x;
    const int w    = tid >> 5;      // 0..15
    const int lane = tid & 31;
    const int lr   = lane >> 2;     // 0..7
    const int lq   = lane & 3;      // 0..3

    const float* bhh = dir ? bhh_b : bhh_f;
    const float* xt  = g_xtab + dir * VV * GG;

    // ---- load w (swizzled) + zero h buffers ----
    {
        const uint4* gw0 = (const uint4*)(g_w0 + dir * (GG * HH));
        for (int idx = tid; idx < GG * 16; idx += NTH) {
            int n = idx >> 4, c = idx & 15;
            int off = n * 256 + ((c ^ (n & 7)) << 4);
            *(uint4*)(smem + SW0 + off) = gw0[idx];
        }
        for (int idx = tid; idx < 512; idx += NTH)
            ((uint4*)(smem + SH16(0)))[idx] = make_uint4(0, 0, 0, 0);
    }

    // n-gate bias only (r,z folded into xtab)
    float bias_n[2];
    #pragma unroll
    for (int c = 0; c < 2; c++)
        bias_n[c] = bhh[2 * 128 + 8 * w + 2 * lq + c];

    // ldmatrix addressing constants
    const int ar  = lane & 15;
    const int ahi = lane >> 4;
    const int asw = ar & 7;
    const int bj  = lane >> 3;
    const int bsw = lane & 7;
    const int brow = (24 * w + (lane & 7)) * 256;

    // h' store offsets (chunk index = w since unit j = 8w + ..)
    int stoff[2];
    #pragma unroll
    for (int ri = 0; ri < 2; ri++)
        stoff[ri] = (lr + 8 * ri) * 256 + ((w ^ lr) << 4) + 4 * lq;

    __syncthreads();

    // ---- cache B fragments for gate groups nt=0,1 (loop-invariant) ----
    uint32_t Brg[2][4][4];
    #pragma unroll
    for (int nt = 0; nt < 2; nt++)
        #pragma unroll
        for (int kc2 = 0; kc2 < 4; kc2++) {
            uint32_t chunk = (uint32_t)(((4 * kc2 + bj) ^ bsw) << 4);
            ldsm4(Brg[nt][kc2][0], Brg[nt][kc2][1], Brg[nt][kc2][2],
                  Brg[nt][kc2][3], sb + SW0 + brow + nt * 2048 + chunk);
        }

    float hprev[2][2][2];
    float acc[2][3][4];
    #pragma unroll
    for (int s = 0; s < 2; s++) {
        #pragma unroll
        for (int ri = 0; ri < 2; ri++)
            #pragma unroll
            for (int c = 0; c < 2; c++) hprev[s][ri][c] = 0.0f;
        #pragma unroll
        for (int rg = 0; rg < 4; rg++) {
            acc[s][0][rg] = 0.0f;
            acc[s][1][rg] = 0.0f;
            acc[s][2][rg] = bias_n[rg & 1];
        }
    }

    #pragma unroll 1
    for (int t = 0; t < TT; t++) {
        const int tcol = dir ? (TT - 1 - t) : t;
        const int* tokrow = g_tokT + tcol * BATCH + b0r;

        // xp gather for both streams (coalesced tokens, L2-resident table)
        float2 xp[2][2][3];
        #pragma unroll
        for (int s = 0; s < 2; s++)
            #pragma unroll
            for (int ri = 0; ri < 2; ri++) {
                int tok = tokrow[16 * s + 8 * ri + lr];
                const float2* xr = (const float2*)(xt + tok * GG + 24 * w);
                #pragma unroll
                for (int u = 0; u < 3; u++)
                    xp[s][ri][u] = xr[4 * u + lq];
            }

        #pragma unroll
        for (int ph = 0; ph < 2; ph++) {
            const int sm_ = 1 - ph;   // mma stream
            const int sg  = ph;       // gate stream

            // reset mma-stream accumulators
            #pragma unroll
            for (int rg = 0; rg < 4; rg++) {
                acc[sm_][0][rg] = 0.0f;
                acc[sm_][1][rg] = 0.0f;
                acc[sm_][2][rg] = bias_n[rg & 1];
            }

            const bool do_mma = ph ? (t < TT - 1) : (t > 0);
            const uint32_t ab0 = sb + SH16(sm_) + ar * 256;

            #pragma unroll
            for (int kc2 = 0; kc2 < 4; kc2++) {
                uint32_t a0[8];
                if (do_mma) {
                    uint32_t clo = (uint32_t)(((4 * kc2 + ahi) ^ asw) << 4);
                    uint32_t chi = (uint32_t)(((4 * kc2 + 2 + ahi) ^ asw) << 4);
                    ldsm4(a0[0], a0[1], a0[2], a0[3], ab0 + clo);
                    ldsm4(a0[4], a0[5], a0[6], a0[7], ab0 + chi);
                }

                // one gate cell of the gate stream, interleaved with mma
                {
                    const int ri = kc2 >> 1, c01 = kc2 & 1, rg = 2 * ri + c01;
                    float xr_ = (c01 ? xp[sg][ri][0].y : xp[sg][ri][0].x)
                                + acc[sg][0][rg];
                    float xz_ = (c01 ? xp[sg][ri][1].y : xp[sg][ri][1].x)
                                + acc[sg][1][rg];
                    float xn_ = (c01 ? xp[sg][ri][2].y : xp[sg][ri][2].x);
                    float nh  = acc[sg][2][rg];
                    float r = sigm_fast(xr_);
                    float z = sigm_fast(xz_);
                    float n = tanh_precise(fmaf(r, nh, xn_));
                    float h = fmaf(z, hprev[sg][ri][c01] - n, n);
                    hprev[sg][ri][c01] = h;
                    *(__half*)(smem + SH16(sg) + stoff[ri] + 2 * c01) =
                        __float2half_rn(h);
                }

                if (do_mma) {
                    mma16816(acc[sm_][0], a0 + 0, Brg[0][kc2][0], Brg[0][kc2][1]);
                    mma16816(acc[sm_][0], a0 + 4, Brg[0][kc2][2], Brg[0][kc2][3]);
                    mma16816(acc[sm_][1], a0 + 0, Brg[1][kc2][0], Brg[1][kc2][1]);
                    mma16816(acc[sm_][1], a0 + 4, Brg[1][kc2][2], Brg[1][kc2][3]);
                    uint32_t bh[4];
                    const uint32_t chunk =
                        (uint32_t)(((4 * kc2 + bj) ^ bsw) << 4);
                    ldsm4(bh[0], bh[1], bh[2], bh[3],
                          sb + SW0 + brow + 2 * 2048 + chunk);
                    mma16816(acc[sm_][2], a0 + 0, bh[0], bh[1]);
                    mma16816(acc[sm_][2], a0 + 4, bh[2], bh[3]);
                }
            }
            __syncthreads();
        }
    }

    // final hidden -> feat
    #pragma unroll
    for (int s = 0; s < 2; s++)
        #pragma unroll
        for (int ri = 0; ri < 2; ri++)
            #pragma unroll
            for (int c = 0; c < 2; c++) {
                int m = 16 * s + lr + 8 * ri;
                int j = 8 * w + 2 * lq + c;
                g_feat[(b0r + m) * EE + dir * HH + j] = hprev[s][ri][c];
            }
}

// ---------------------------------------------------------------------------
// Head v6: HB=16 rows, 512 threads, grid 128 (single wave).
// Phase A: down_w + up_wT (all 3 langs, fp32) staged in SMEM -> adapter+LN
//          is LDS-fed (L2 traffic 128MB -> ~40MB).
// Phase B: weight region reused for proj_w fp16; projection via mma (R11).
// ---------------------------------------------------------------------------
#define HB 16
__global__ __launch_bounds__(512) void head_kernel(
    const int* __restrict__ lang_ids,
    const float* __restrict__ down_w, const float* __restrict__ down_b,
    const float* __restrict__ up_b,
    const float* __restrict__ ln_g,   const float* __restrict__ ln_b,
    const float* __restrict__ proj_b,
    float* __restrict__ out) {
    extern __shared__ __align__(16) char hsm[];
    const uint32_t sb = (uint32_t)__cvta_generic_to_shared(hsm);
    const int tid = threadIdx.x, w = tid >> 5, lane = tid & 31;
    const int b0 = blockIdx.x * HB;
    const int b = b0 + w;                   // one row per warp (16 warps)
    const int l = lang_ids[b];
    const float* fb = g_feat + b * EE;

    // ---- stage adapter weights (all langs) into SMEM ----
    {
        const uint4* gd = (const uint4*)down_w;
        const uint4* gu = (const uint4*)g_upwT;
        #pragma unroll
        for (int k = 0; k < 12; k++) {
            ((uint4*)(hsm + HDOWN))[tid + 512 * k] = gd[tid + 512 * k];
            ((uint4*)(hsm + HUP))[tid + 512 * k]   = gu[tid + 512 * k];
        }
    }
    __syncthreads();

    // ---- adapter (one row per warp), weights from SMEM ----
    float4 f4[8];
    #pragma unroll
    for (int c = 0; c < 8; c++)
        f4[c] = *(const float4*)(fb + (lane & 7) * 4 + 32 * c);

    float hid = 0.0f;
    const float* dwb = (const float*)(hsm + HDOWN) + l * BNK * EE;
    #pragma unroll
    for (int g = 0; g < 8; g++) {
        const int d = 4 * g + (lane >> 3);
        const float* wr = dwb + d * EE + (lane & 7) * 4;
        float s = 0.0f;
        #pragma unroll
        for (int c = 0; c < 8; c++) {
            float4 wv = *(const float4*)(wr + 32 * c);
            s = fmaf(f4[c].x, wv.x, s); s = fmaf(f4[c].y, wv.y, s);
            s = fmaf(f4[c].z, wv.z, s); s = fmaf(f4[c].w, wv.w, s);
        }
        s += __shfl_xor_sync(0xffffffffu, s, 1);
        s += __shfl_xor_sync(0xffffffffu, s, 2);
        s += __shfl_xor_sync(0xffffffffu, s, 4);
        float got = __shfl_sync(0xffffffffu, s, (lane & 3) * 8);
        if ((lane >> 2) == g) hid = got;
    }
    hid += down_b[l * BNK + lane];
    hid = 0.5f * hid * (1.0f + erff(hid * 0.7071067811865476f));

    const float4 fx0 = *(const float4*)(fb + lane * 8);
    const float4 fx1 = *(const float4*)(fb + lane * 8 + 4);
    float4 a0 = *(const float4*)(up_b + l * EE + lane * 8);
    float4 a1 = *(const float4*)(up_b + l * EE + lane * 8 + 4);
    const float* uwb = (const float*)(hsm + HUP) + l * BNK * EE;
    #pragma unroll 4
    for (int d = 0; d < BNK; d++) {
        float hd = __shfl_sync(0xffffffffu, hid, d);
        float4 u0 = *(const float4*)(uwb + d * EE + lane * 8);
        float4 u1 = *(const float4*)(uwb + d * EE + lane * 8 + 4);
        a0.x = fmaf(hd, u0.x, a0.x); a0.y = fmaf(hd, u0.y, a0.y);
        a0.z = fmaf(hd, u0.z, a0.z); a0.w = fmaf(hd, u0.w, a0.w);
        a1.x = fmaf(hd, u1.x, a1.x); a1.y = fmaf(hd, u1.y, a1.y);
        a1.z = fmaf(hd, u1.z, a1.z); a1.w = fmaf(hd, u1.w, a1.w);
    }
    float x[8] = {fx0.x + a0.x, fx0.y + a0.y, fx0.z + a0.z, fx0.w + a0.w,
                  fx1.x + a1.x, fx1.y + a1.y, fx1.z + a1.z, fx1.w + a1.w};
    float s1 = 0.0f, s2 = 0.0f;
    #pragma unroll
    for (int j = 0; j < 8; j++) { s1 += x[j]; s2 = fmaf(x[j], x[j], s2); }
    #pragma unroll
    for (int o = 16; o; o >>= 1) {
        s1 += __shfl_xor_sync(0xffffffffu, s1, o);
        s2 += __shfl_xor_sync(0xffffffffu, s2, o);
    }
    const float mu = s1 * (1.0f / EE);
    const float rstd = rsqrtf(s2 * (1.0f / EE) - mu * mu + 1e-5f);
    const float4 g0 = *(const float4*)(ln_g + l * EE + lane * 8);
    const float4 g1 = *(const float4*)(ln_g + l * EE + lane * 8 + 4);
    const float4 bb0 = *(const float4*)(ln_b + l * EE + lane * 8);
    const float4 bb1 = *(const float4*)(ln_b + l * EE + lane * 8 + 4);
    float y[8];
    y[0] = (x[0]-mu)*rstd*g0.x + bb0.x;  y[1] = (x[1]-mu)*rstd*g0.y + bb0.y;
    y[2] = (x[2]-mu)*rstd*g0.z + bb0.z;  y[3] = (x[3]-mu)*rstd*g0.w + bb0.w;
    y[4] = (x[4]-mu)*rstd*g1.x + bb1.x;  y[5] = (x[5]-mu)*rstd*g1.y + bb1.y;
    y[6] = (x[6]-mu)*rstd*g1.z + bb1.z;  y[7] = (x[7]-mu)*rstd*g1.w + bb1.w;

    // fp16 hi/lo split -> SMEM (lane = 16B chunk index, XOR-swizzled by row)
    {
        __half h_[8], c_[8];
        #pragma unroll
        for (int j = 0; j < 8; j++) {
            h_[j] = __float2half_rn(y[j]);
            c_[j] = __float2half_rn(y[j] - __half2float(h_[j]));
        }
        const int off = w * 512 + ((lane ^ (w & 7)) << 4);
        *(uint4*)(hsm + HYHI + off) = *(const uint4*)h_;
        *(uint4*)(hsm + HYLO + off) = *(const uint4*)c_;
    }
    __syncthreads();

    // ---- phase B: reuse weight region for proj_w fp16, then mma ----
    {
        const uint4* gp = (const uint4*)g_pw16;
        #pragma unroll
        for (int k = 0; k < 16; k++)
            ((uint4*)(hsm + HDOWN))[tid + 512 * k] = gp[tid + 512 * k];
    }
    __syncthreads();

    // projection via mma: warp w -> output cols [16w, 16w+16)
    const int ar  = lane & 15;           // A row
    const int ahi = lane >> 4;
    const int asw = ar & 7;
    const int bj  = lane >> 3;           // B k-chunk within k32
    const int bsw = lane & 7;
    const uint32_t ahib = sb + HYHI + ar * 512;
    const uint32_t alob = sb + HYLO + ar * 512;
    const uint32_t brow0 = sb + HDOWN + (16 * w + (lane & 7)) * 512;
    const uint32_t brow1 = brow0 + 8 * 512;

    const int lr = lane >> 2, lq = lane & 3;
    float pb0 = proj_b[16 * w + 2 * lq];
    float pb1 = proj_b[16 * w + 2 * lq + 1];
    float pb8 = proj_b[16 * w + 8 + 2 * lq];
    float pb9 = proj_b[16 * w + 8 + 2 * lq + 1];
    float acc[2][4] = {{pb0, pb1, pb0, pb1}, {pb8, pb9, pb8, pb9}};

    #pragma unroll
    for (int kc32 = 0; kc32 < 8; kc32++) {
        uint32_t ah[8], al[8], bF0[4], bF1[4];
        uint32_t clo = (uint32_t)(((4 * kc32 + ahi) ^ asw) << 4);
        uint32_t chi = (uint32_t)(((4 * kc32 + 2 + ahi) ^ asw) << 4);
        ldsm4(ah[0], ah[1], ah[2], ah[3], ahib + clo);
        ldsm4(ah[4], ah[5], ah[6], ah[7], ahib + chi);
        ldsm4(al[0], al[1], al[2], al[3], alob + clo);
        ldsm4(al[4], al[5], al[6], al[7], alob + chi);
        uint32_t bc = (uint32_t)(((4 * kc32 + bj) ^ bsw) << 4);
        ldsm4(bF0[0], bF0[1], bF0[2], bF0[3], brow0 + bc);
        ldsm4(bF1[0], bF1[1], bF1[2], bF1[3], brow1 + bc);
        #pragma unroll
        for (int kk = 0; kk < 2; kk++) {
            mma16816(acc[0], ah + 4 * kk, bF0[2 * kk], bF0[2 * kk + 1]);
            mma16816(acc[0], al + 4 * kk, bF0[2 * kk], bF0[2 * kk + 1]);
            mma16816(acc[1], ah + 4 * kk, bF1[2 * kk], bF1[2 * kk + 1]);
            mma16816(acc[1], al + 4 * kk, bF1[2 * kk], bF1[2 * kk + 1]);
        }
    }

    // write out: c-frag: regs {0,1} row lr, {2,3} row lr+8; cols 2lq+{0,1}
    #pragma unroll
    for (int nt = 0; nt < 2; nt++) {
        const int col = 16 * w + 8 * nt + 2 * lq;
        *(float2*)(out + (b0 + lr) * OO + col)
            = make_float2(acc[nt][0], acc[nt][1]);
        *(float2*)(out + (b0 + lr + 8) * OO + col)
            = make_float2(acc[nt][2], acc[nt][3]);
    }
}

// ---------------------------------------------------------------------------
extern "C" void kernel_launch(void* const* d_in, const int* in_sizes, int n_in,
                              void* d_out, int out_size) {
    const int*   tokens = (const int*)d_in[0];
    const int*   lang   = (const int*)d_in[1];
    const float* ce     = (const float*)d_in[2];
    const float* wih_f  = (const float*)d_in[3];
    const float* whh_f  = (const float*)d_in[4];
    const float* bih_f  = (const float*)d_in[5];
    const float* bhh_f  = (const float*)d_in[6];
    const float* wih_b  = (const float*)d_in[7];
    const float* whh_b  = (const float*)d_in[8];
    const float* bih_b  = (const float*)d_in[9];
    const float* bhh_b  = (const float*)d_in[10];
    const float* down_w = (const float*)d_in[11];
    const float* down_b = (const float*)d_in[12];
    const float* up_w   = (const float*)d_in[13];
    const float* up_b   = (const float*)d_in[14];
    const float* ln_g   = (const float*)d_in[15];
    const float* ln_b   = (const float*)d_in[16];
    const float* proj_w = (const float*)d_in[17];
    const float* proj_b = (const float*)d_in[18];
    float* out = (float*)d_out;

    cudaFuncSetAttribute(gru_mma_kernel,
                         cudaFuncAttributeMaxDynamicSharedMemorySize, SMEM_TOTAL);
    cudaFuncSetAttribute(head_kernel,
                         cudaFuncAttributeMaxDynamicSharedMemorySize, HEAD_SMEM);
    const size_t xsmem = (size_t)(GG * CC + GG + 32 * CC) * sizeof(float);
    cudaFuncSetAttribute(xtab_kernel,
                         cudaFuncAttributeMaxDynamicSharedMemorySize, (int)xsmem);

    prep_misc<<<(PREP_N3 + 255) / 256, 256>>>(whh_f, whh_b, up_w, tokens, proj_w);
    xtab_kernel<<<dim3(8, 2), GG, xsmem>>>(ce, wih_f, bih_f, wih_b, bih_b,
                                           bhh_f, bhh_b);
    gru_mma_kernel<<<dim3(BATCH / BM, 2), NTH, SMEM_TOTAL>>>(bhh_f, bhh_b);
    head_kernel<<<BATCH / HB, 512, HEAD_SMEM>>>(lang, down_w, down_b, up_b,
                                                ln_g, ln_b, proj_b, out);
}

// round 13
// speedup vs baseline: 1.2215x; 1.0103x over previous
#include <cuda_runtime.h>
#include <cuda_fp16.h>
#include <cuda_bf16.h>
#include <math.h>
#include <stdint.h>

// Problem dims
#define BATCH 2048
#define TT    128
#define VV    256
#define CC    32
#define HH    128
#define EE    256
#define GG    384   // 3*H
#define OO    256
#define NLN   3
#define BNK   32

// GRU tiling
#define BM    32      // batch rows per CTA (2 streams x 16)
#define NTH   512     // 16 warps, 24 gate-cols each
// SMEM byte offsets
#define SW0   0                   // w fp16: [384][128] half, swizzled (96KB)
#define SH16(s) (98304 + (s) * 4096)   // h fp16 per stream [16][128]
#define SMEM_TOTAL 106496

// Head SMEM: phase A = down_w fp32 (96KB) | up_wT fp32 (96KB); y hi/lo 16KB.
// Phase B reuses [0,128KB) of the weight region for proj_w fp16.
#define HDOWN 0
#define HUP   98304
#define HYHI  196608
#define HYLO  204800
#define HEAD_SMEM 212992

// Scratch (static device globals)
__device__ __align__(16) __half g_w0[2 * GG * HH];  // [dir][p][k] fp16
__device__ float g_xtab[2 * VV * GG];   // permuted x@w_ih^T + b_ih (+b_hh r,z)
__device__ float g_feat[BATCH * EE];
__device__ float g_upwT[NLN * BNK * EE]; // up_w transposed: [l][d][e]
__device__ int   g_tokT[TT * BATCH];     // tokens transposed [t][b]
__device__ __align__(16) __half g_pw16[OO * EE];  // proj_w fp16, swizzled rows

// ---------------------------------------------------------------------------
// Activations: HW tanh for r/z sigmoids; n-tanh via direct exp identity
// tanh(v) = (e-1)*rcp(e+1), e = 2^(2v*log2e) — 7 ops, 2 MUFU, ~1e-7 rel err.
// ---------------------------------------------------------------------------
__device__ __forceinline__ float tanh_e(float v) {
    float t = fminf(v * 2.8853900817779268f, 126.0f);
    float e; asm("ex2.approx.f32 %0, %1;" : "=f"(e) : "f"(t));
    float rp; asm("rcp.approx.f32 %0, %1;" : "=f"(rp) : "f"(e + 1.0f));
    return (e - 1.0f) * rp;
}
__device__ __forceinline__ float tanh_hw(float x) {
    float y; asm("tanh.approx.f32 %0, %1;" : "=f"(y) : "f"(x));
    return y;
}
__device__ __forceinline__ float sigm_fast(float x) {
    return fmaf(tanh_hw(0.5f * x), 0.5f, 0.5f);
}

// ---------------------------------------------------------------------------
// MMA / ldmatrix wrappers
// ---------------------------------------------------------------------------
__device__ __forceinline__ void ldsm4(uint32_t& r0, uint32_t& r1, uint32_t& r2,
                                      uint32_t& r3, uint32_t addr) {
    asm volatile("ldmatrix.sync.aligned.m8n8.x4.shared.b16 {%0,%1,%2,%3}, [%4];"
                 : "=r"(r0), "=r"(r1), "=r"(r2), "=r"(r3) : "r"(addr));
}
__device__ __forceinline__ void mma16816(float* d, const uint32_t* a,
                                         uint32_t b0, uint32_t b1) {
    asm volatile(
        "mma.sync.aligned.m16n8k16.row.col.f32.f16.f16.f32 "
        "{%0,%1,%2,%3}, {%4,%5,%6,%7}, {%8,%9}, {%0,%1,%2,%3};"
        : "+f"(d[0]), "+f"(d[1]), "+f"(d[2]), "+f"(d[3])
        : "r"(a[0]), "r"(a[1]), "r"(a[2]), "r"(a[3]), "r"(b0), "r"(b1));
}

// gate-dim permutation: orig g = t*128 + j -> p = 24*(j>>3) + 8*t + (j&7)
__device__ __forceinline__ int permute_g(int g) {
    int t = g >> 7, j = g & 127;
    return 24 * (j >> 3) + 8 * t + (j & 7);
}

// ---------------------------------------------------------------------------
// Prep A: xtab (permuted). b_ih + b_hh(r,z) folded (R6-exact).
// ---------------------------------------------------------------------------
__global__ void xtab_kernel(const float* __restrict__ ce,
                            const float* __restrict__ wih_f, const float* __restrict__ bih_f,
                            const float* __restrict__ wih_b, const float* __restrict__ bih_b,
                            const float* __restrict__ bhh_f, const float* __restrict__ bhh_b) {
    extern __shared__ float xsm[];
    float* ws = xsm;               // [384*32]
    float* bs = ws + GG * CC;      // [384]
    float* cs = bs + GG;           // [32*32]
    const int d = blockIdx.y, g = threadIdx.x;
    const float* wih = d ? wih_b : wih_f;
    const float* bih = d ? bih_b : bih_f;
    const float* bhh = d ? bhh_b : bhh_f;
    for (int i = g; i < GG * CC; i += GG) ws[i] = wih[i];
    bs[g] = bih[g] + (g < 2 * HH ? bhh[g] : 0.0f);
    const int v0 = blockIdx.x * 32;
    for (int i = g; i < 32 * CC; i += GG) cs[i] = ce[v0 * CC + i];
    __syncthreads();
    const int p = permute_g(g);
    for (int vi = 0; vi < 32; vi++) {
        float s = bs[g];
        #pragma unroll
        for (int c = 0; c < CC; c++) s = fmaf(cs[vi * CC + c], ws[g * CC + c], s);
        g_xtab[(d * VV + v0 + vi) * GG + p] = s;
    }
}

// ---------------------------------------------------------------------------
// Prep B (fused): w_hh fp16 permuted + up_w transpose + tokens transpose
// + proj_w fp16 (swizzled rows for ldmatrix B).
// ---------------------------------------------------------------------------
#define PREP_N0 (2 * GG * HH)
#define PREP_N1 (PREP_N0 + NLN * EE * BNK)
#define PREP_N2 (PREP_N1 + BATCH * TT)
#define PREP_N3 (PREP_N2 + OO * EE)
__global__ void prep_misc(const float* __restrict__ whh_f,
                          const float* __restrict__ whh_b,
                          const float* __restrict__ up_w,
                          const int* __restrict__ tokens,
                          const float* __restrict__ proj_w) {
    const int i = blockIdx.x * 256 + threadIdx.x;
    if (i < PREP_N0) {
        int d = i / (GG * HH), rem = i % (GG * HH);
        int g = rem / HH, k = rem % HH;
        const float* w = d ? whh_b : whh_f;
        g_w0[d * GG * HH + permute_g(g) * HH + k] = __float2half_rn(w[g * HH + k]);
    } else if (i < PREP_N1) {
        int j = i - PREP_N0;
        int l = j / (EE * BNK), rem = j % (EE * BNK);
        int e = rem / BNK, dd = rem % BNK;
        g_upwT[(l * BNK + dd) * EE + e] = up_w[j];
    } else if (i < PREP_N2) {
        int j = i - PREP_N1;
        int b = j / TT, t = j % TT;
        g_tokT[t * BATCH + b] = tokens[j];
    } else if (i < PREP_N3) {
        int j = i - PREP_N2;
        int o = j >> 8, e = j & 255;
        // swizzled row layout: 16B chunk c=e>>3 -> position (c ^ (o&7)) low bits
        int pos = (((e >> 3) ^ (o & 7)) << 3) | (e & 7);
        g_pw16[o * EE + pos] = __float2half_rn(proj_w[j]);
    }
}

// ---------------------------------------------------------------------------
// GRU via mma (R6 schedule; sole change this round: tanh_precise -> tanh_e).
// grid (64, 2) x 512 threads.
// ---------------------------------------------------------------------------
__global__ __launch_bounds__(NTH, 1) void gru_mma_kernel(
    const float* __restrict__ bhh_f, const float* __restrict__ bhh_b) {
    extern __shared__ __align__(16) char smem[];
    const uint32_t sb = (uint32_t)__cvta_generic_to_shared(smem);

    const int dir  = blockIdx.y;
    const int b0r  = blockIdx.x * BM;
    const int tid  = threadIdx.x;
    const int w    = tid >> 5;      // 0..15
    const int lane = tid & 31;
    const int lr   = lane >> 2;     // 0..7
    const int lq   = lane & 3;      // 0..3

    const float* bhh = dir ? bhh_b : bhh_f;
    const float* xt  = g_xtab + dir * VV * GG;

    // ---- load w (swizzled) + zero h buffers ----
    {
        const uint4* gw0 = (const uint4*)(g_w0 + dir * (GG * HH));
        for (int idx = tid; idx < GG * 16; idx += NTH) {
            int n = idx >> 4, c = idx & 15;
            int off = n * 256 + ((c ^ (n & 7)) << 4);
            *(uint4*)(smem + SW0 + off) = gw0[idx];
        }
        for (int idx = tid; idx < 512; idx += NTH)
            ((uint4*)(smem + SH16(0)))[idx] = make_uint4(0, 0, 0, 0);
    }

    // n-gate bias only (r,z folded into xtab)
    float bias_n[2];
    #pragma unroll
    for (int c = 0; c < 2; c++)
        bias_n[c] = bhh[2 * 128 + 8 * w + 2 * lq + c];

    // ldmatrix addressing constants
    const int ar  = lane & 15;
    const int ahi = lane >> 4;
    const int asw = ar & 7;
    const int bj  = lane >> 3;
    const int bsw = lane & 7;
    const int brow = (24 * w + (lane & 7)) * 256;

    // h' store offsets (chunk index = w since unit j = 8w + ..)
    int stoff[2];
    #pragma unroll
    for (int ri = 0; ri < 2; ri++)
        stoff[ri] = (lr + 8 * ri) * 256 + ((w ^ lr) << 4) + 4 * lq;

    __syncthreads();

    // ---- cache B fragments for gate groups nt=0,1 (loop-invariant) ----
    uint32_t Brg[2][4][4];
    #pragma unroll
    for (int nt = 0; nt < 2; nt++)
        #pragma unroll
        for (int kc2 = 0; kc2 < 4; kc2++) {
            uint32_t chunk = (uint32_t)(((4 * kc2 + bj) ^ bsw) << 4);
            ldsm4(Brg[nt][kc2][0], Brg[nt][kc2][1], Brg[nt][kc2][2],
                  Brg[nt][kc2][3], sb + SW0 + brow + nt * 2048 + chunk);
        }

    float hprev[2][2][2];
    float acc[2][3][4];
    #pragma unroll
    for (int s = 0; s < 2; s++) {
        #pragma unroll
        for (int ri = 0; ri < 2; ri++)
            #pragma unroll
            for (int c = 0; c < 2; c++) hprev[s][ri][c] = 0.0f;
        #pragma unroll
        for (int rg = 0; rg < 4; rg++) {
            acc[s][0][rg] = 0.0f;
            acc[s][1][rg] = 0.0f;
            acc[s][2][rg] = bias_n[rg & 1];
        }
    }

    #pragma unroll 1
    for (int t = 0; t < TT; t++) {
        const int tcol = dir ? (TT - 1 - t) : t;
        const int* tokrow = g_tokT + tcol * BATCH + b0r;

        // xp gather for both streams (coalesced tokens, L2-resident table)
        float2 xp[2][2][3];
        #pragma unroll
        for (int s = 0; s < 2; s++)
            #pragma unroll
            for (int ri = 0; ri < 2; ri++) {
                int tok = tokrow[16 * s + 8 * ri + lr];
                const float2* xr = (const float2*)(xt + tok * GG + 24 * w);
                #pragma unroll
                for (int u = 0; u < 3; u++)
                    xp[s][ri][u] = xr[4 * u + lq];
            }

        #pragma unroll
        for (int ph = 0; ph < 2; ph++) {
            const int sm_ = 1 - ph;   // mma stream
            const int sg  = ph;       // gate stream

            // reset mma-stream accumulators
            #pragma unroll
            for (int rg = 0; rg < 4; rg++) {
                acc[sm_][0][rg] = 0.0f;
                acc[sm_][1][rg] = 0.0f;
                acc[sm_][2][rg] = bias_n[rg & 1];
            }

            const bool do_mma = ph ? (t < TT - 1) : (t > 0);
            const uint32_t ab0 = sb + SH16(sm_) + ar * 256;

            #pragma unroll
            for (int kc2 = 0; kc2 < 4; kc2++) {
                uint32_t a0[8];
                if (do_mma) {
                    uint32_t clo = (uint32_t)(((4 * kc2 + ahi) ^ asw) << 4);
                    uint32_t chi = (uint32_t)(((4 * kc2 + 2 + ahi) ^ asw) << 4);
                    ldsm4(a0[0], a0[1], a0[2], a0[3], ab0 + clo);
                    ldsm4(a0[4], a0[5], a0[6], a0[7], ab0 + chi);
                }

                // one gate cell of the gate stream, interleaved with mma
                {
                    const int ri = kc2 >> 1, c01 = kc2 & 1, rg = 2 * ri + c01;
                    float xr_ = (c01 ? xp[sg][ri][0].y : xp[sg][ri][0].x)
                                + acc[sg][0][rg];
                    float xz_ = (c01 ? xp[sg][ri][1].y : xp[sg][ri][1].x)
                                + acc[sg][1][rg];
                    float xn_ = (c01 ? xp[sg][ri][2].y : xp[sg][ri][2].x);
                    float nh  = acc[sg][2][rg];
                    float r = sigm_fast(xr_);
                    float z = sigm_fast(xz_);
                    float n = tanh_e(fmaf(r, nh, xn_));
                    float h = fmaf(z, hprev[sg][ri][c01] - n, n);
                    hprev[sg][ri][c01] = h;
                    *(__half*)(smem + SH16(sg) + stoff[ri] + 2 * c01) =
                        __float2half_rn(h);
                }

                if (do_mma) {
                    mma16816(acc[sm_][0], a0 + 0, Brg[0][kc2][0], Brg[0][kc2][1]);
                    mma16816(acc[sm_][0], a0 + 4, Brg[0][kc2][2], Brg[0][kc2][3]);
                    mma16816(acc[sm_][1], a0 + 0, Brg[1][kc2][0], Brg[1][kc2][1]);
                    mma16816(acc[sm_][1], a0 + 4, Brg[1][kc2][2], Brg[1][kc2][3]);
                    uint32_t bh[4];
                    const uint32_t chunk =
                        (uint32_t)(((4 * kc2 + bj) ^ bsw) << 4);
                    ldsm4(bh[0], bh[1], bh[2], bh[3],
                          sb + SW0 + brow + 2 * 2048 + chunk);
                    mma16816(acc[sm_][2], a0 + 0, bh[0], bh[1]);
                    mma16816(acc[sm_][2], a0 + 4, bh[2], bh[3]);
                }
            }
            __syncthreads();
        }
    }

    // final hidden -> feat
    #pragma unroll
    for (int s = 0; s < 2; s++)
        #pragma unroll
        for (int ri = 0; ri < 2; ri++)
            #pragma unroll
            for (int c = 0; c < 2; c++) {
                int m = 16 * s + lr + 8 * ri;
                int j = 8 * w + 2 * lq + c;
                g_feat[(b0r + m) * EE + dir * HH + j] = hprev[s][ri][c];
            }
}

// ---------------------------------------------------------------------------
// Head v6 (R12-exact): HB=16 rows, 512 threads, grid 128 (single wave).
// Phase A: down_w + up_wT (all 3 langs, fp32) staged in SMEM.
// Phase B: weight region reused for proj_w fp16; projection via mma.
// ---------------------------------------------------------------------------
#define HB 16
__global__ __launch_bounds__(512) void head_kernel(
    const int* __restrict__ lang_ids,
    const float* __restrict__ down_w, const float* __restrict__ down_b,
    const float* __restrict__ up_b,
    const float* __restrict__ ln_g,   const float* __restrict__ ln_b,
    const float* __restrict__ proj_b,
    float* __restrict__ out) {
    extern __shared__ __align__(16) char hsm[];
    const uint32_t sb = (uint32_t)__cvta_generic_to_shared(hsm);
    const int tid = threadIdx.x, w = tid >> 5, lane = tid & 31;
    const int b0 = blockIdx.x * HB;
    const int b = b0 + w;                   // one row per warp (16 warps)
    const int l = lang_ids[b];
    const float* fb = g_feat + b * EE;

    // ---- stage adapter weights (all langs) into SMEM ----
    {
        const uint4* gd = (const uint4*)down_w;
        const uint4* gu = (const uint4*)g_upwT;
        #pragma unroll
        for (int k = 0; k < 12; k++) {
            ((uint4*)(hsm + HDOWN))[tid + 512 * k] = gd[tid + 512 * k];
            ((uint4*)(hsm + HUP))[tid + 512 * k]   = gu[tid + 512 * k];
        }
    }
    __syncthreads();

    // ---- adapter (one row per warp), weights from SMEM ----
    float4 f4[8];
    #pragma unroll
    for (int c = 0; c < 8; c++)
        f4[c] = *(const float4*)(fb + (lane & 7) * 4 + 32 * c);

    float hid = 0.0f;
    const float* dwb = (const float*)(hsm + HDOWN) + l * BNK * EE;
    #pragma unroll
    for (int g = 0; g < 8; g++) {
        const int d = 4 * g + (lane >> 3);
        const float* wr = dwb + d * EE + (lane & 7) * 4;
        float s = 0.0f;
        #pragma unroll
        for (int c = 0; c < 8; c++) {
            float4 wv = *(const float4*)(wr + 32 * c);
            s = fmaf(f4[c].x, wv.x, s); s = fmaf(f4[c].y, wv.y, s);
            s = fmaf(f4[c].z, wv.z, s); s = fmaf(f4[c].w, wv.w, s);
        }
        s += __shfl_xor_sync(0xffffffffu, s, 1);
        s += __shfl_xor_sync(0xffffffffu, s, 2);
        s += __shfl_xor_sync(0xffffffffu, s, 4);
        float got = __shfl_sync(0xffffffffu, s, (lane & 3) * 8);
        if ((lane >> 2) == g) hid = got;
    }
    hid += down_b[l * BNK + lane];
    hid = 0.5f * hid * (1.0f + erff(hid * 0.7071067811865476f));

    const float4 fx0 = *(const float4*)(fb + lane * 8);
    const float4 fx1 = *(const float4*)(fb + lane * 8 + 4);
    float4 a0 = *(const float4*)(up_b + l * EE + lane * 8);
    float4 a1 = *(const float4*)(up_b + l * EE + lane * 8 + 4);
    const float* uwb = (const float*)(hsm + HUP) + l * BNK * EE;
    #pragma unroll 4
    for (int d = 0; d < BNK; d++) {
        float hd = __shfl_sync(0xffffffffu, hid, d);
        float4 u0 = *(const float4*)(uwb + d * EE + lane * 8);
        float4 u1 = *(const float4*)(uwb + d * EE + lane * 8 + 4);
        a0.x = fmaf(hd, u0.x, a0.x); a0.y = fmaf(hd, u0.y, a0.y);
        a0.z = fmaf(hd, u0.z, a0.z); a0.w = fmaf(hd, u0.w, a0.w);
        a1.x = fmaf(hd, u1.x, a1.x); a1.y = fmaf(hd, u1.y, a1.y);
        a1.z = fmaf(hd, u1.z, a1.z); a1.w = fmaf(hd, u1.w, a1.w);
    }
    float x[8] = {fx0.x + a0.x, fx0.y + a0.y, fx0.z + a0.z, fx0.w + a0.w,
                  fx1.x + a1.x, fx1.y + a1.y, fx1.z + a1.z, fx1.w + a1.w};
    float s1 = 0.0f, s2 = 0.0f;
    #pragma unroll
    for (int j = 0; j < 8; j++) { s1 += x[j]; s2 = fmaf(x[j], x[j], s2); }
    #pragma unroll
    for (int o = 16; o; o >>= 1) {
        s1 += __shfl_xor_sync(0xffffffffu, s1, o);
        s2 += __shfl_xor_sync(0xffffffffu, s2, o);
    }
    const float mu = s1 * (1.0f / EE);
    const float rstd = rsqrtf(s2 * (1.0f / EE) - mu * mu + 1e-5f);
    const float4 g0 = *(const float4*)(ln_g + l * EE + lane * 8);
    const float4 g1 = *(const float4*)(ln_g + l * EE + lane * 8 + 4);
    const float4 bb0 = *(const float4*)(ln_b + l * EE + lane * 8);
    const float4 bb1 = *(const float4*)(ln_b + l * EE + lane * 8 + 4);
    float y[8];
    y[0] = (x[0]-mu)*rstd*g0.x + bb0.x;  y[1] = (x[1]-mu)*rstd*g0.y + bb0.y;
    y[2] = (x[2]-mu)*rstd*g0.z + bb0.z;  y[3] = (x[3]-mu)*rstd*g0.w + bb0.w;
    y[4] = (x[4]-mu)*rstd*g1.x + bb1.x;  y[5] = (x[5]-mu)*rstd*g1.y + bb1.y;
    y[6] = (x[6]-mu)*rstd*g1.z + bb1.z;  y[7] = (x[7]-mu)*rstd*g1.w + bb1.w;

    // fp16 hi/lo split -> SMEM (lane = 16B chunk index, XOR-swizzled by row)
    {
        __half h_[8], c_[8];
        #pragma unroll
        for (int j = 0; j < 8; j++) {
            h_[j] = __float2half_rn(y[j]);
            c_[j] = __float2half_rn(y[j] - __half2float(h_[j]));
        }
        const int off = w * 512 + ((lane ^ (w & 7)) << 4);
        *(uint4*)(hsm + HYHI + off) = *(const uint4*)h_;
        *(uint4*)(hsm + HYLO + off) = *(const uint4*)c_;
    }
    __syncthreads();

    // ---- phase B: reuse weight region for proj_w fp16, then mma ----
    {
        const uint4* gp = (const uint4*)g_pw16;
        #pragma unroll
        for (int k = 0; k < 16; k++)
            ((uint4*)(hsm + HDOWN))[tid + 512 * k] = gp[tid + 512 * k];
    }
    __syncthreads();

    // projection via mma: warp w -> output cols [16w, 16w+16)
    const int ar  = lane & 15;           // A row
    const int ahi = lane >> 4;
    const int asw = ar & 7;
    const int bj  = lane >> 3;           // B k-chunk within k32
    const int bsw = lane & 7;
    const uint32_t ahib = sb + HYHI + ar * 512;
    const uint32_t alob = sb + HYLO + ar * 512;
    const uint32_t brow0 = sb + HDOWN + (16 * w + (lane & 7)) * 512;
    const uint32_t brow1 = brow0 + 8 * 512;

    const int lr = lane >> 2, lq = lane & 3;
    float pb0 = proj_b[16 * w + 2 * lq];
    float pb1 = proj_b[16 * w + 2 * lq + 1];
    float pb8 = proj_b[16 * w + 8 + 2 * lq];
    float pb9 = proj_b[16 * w + 8 + 2 * lq + 1];
    float acc[2][4] = {{pb0, pb1, pb0, pb1}, {pb8, pb9, pb8, pb9}};

    #pragma unroll
    for (int kc32 = 0; kc32 < 8; kc32++) {
        uint32_t ah[8], al[8], bF0[4], bF1[4];
        uint32_t clo = (uint32_t)(((4 * kc32 + ahi) ^ asw) << 4);
        uint32_t chi = (uint32_t)(((4 * kc32 + 2 + ahi) ^ asw) << 4);
        ldsm4(ah[0], ah[1], ah[2], ah[3], ahib + clo);
        ldsm4(ah[4], ah[5], ah[6], ah[7], ahib + chi);
        ldsm4(al[0], al[1], al[2], al[3], alob + clo);
        ldsm4(al[4], al[5], al[6], al[7], alob + chi);
        uint32_t bc = (uint32_t)(((4 * kc32 + bj) ^ bsw) << 4);
        ldsm4(bF0[0], bF0[1], bF0[2], bF0[3], brow0 + bc);
        ldsm4(bF1[0], bF1[1], bF1[2], bF1[3], brow1 + bc);
        #pragma unroll
        for (int kk = 0; kk < 2; kk++) {
            mma16816(acc[0], ah + 4 * kk, bF0[2 * kk], bF0[2 * kk + 1]);
            mma16816(acc[0], al + 4 * kk, bF0[2 * kk], bF0[2 * kk + 1]);
            mma16816(acc[1], ah + 4 * kk, bF1[2 * kk], bF1[2 * kk + 1]);
            mma16816(acc[1], al + 4 * kk, bF1[2 * kk], bF1[2 * kk + 1]);
        }
    }

    // write out: c-frag: regs {0,1} row lr, {2,3} row lr+8; cols 2lq+{0,1}
    #pragma unroll
    for (int nt = 0; nt < 2; nt++) {
        const int col = 16 * w + 8 * nt + 2 * lq;
        *(float2*)(out + (b0 + lr) * OO + col)
            = make_float2(acc[nt][0], acc[nt][1]);
        *(float2*)(out + (b0 + lr + 8) * OO + col)
            = make_float2(acc[nt][2], acc[nt][3]);
    }
}

// ---------------------------------------------------------------------------
extern "C" void kernel_launch(void* const* d_in, const int* in_sizes, int n_in,
                              void* d_out, int out_size) {
    const int*   tokens = (const int*)d_in[0];
    const int*   lang   = (const int*)d_in[1];
    const float* ce     = (const float*)d_in[2];
    const float* wih_f  = (const float*)d_in[3];
    const float* whh_f  = (const float*)d_in[4];
    const float* bih_f  = (const float*)d_in[5];
    const float* bhh_f  = (const float*)d_in[6];
    const float* wih_b  = (const float*)d_in[7];
    const float* whh_b  = (const float*)d_in[8];
    const float* bih_b  = (const float*)d_in[9];
    const float* bhh_b  = (const float*)d_in[10];
    const float* down_w = (const float*)d_in[11];
    const float* down_b = (const float*)d_in[12];
    const float* up_w   = (const float*)d_in[13];
    const float* up_b   = (const float*)d_in[14];
    const float* ln_g   = (const float*)d_in[15];
    const float* ln_b   = (const float*)d_in[16];
    const float* proj_w = (const float*)d_in[17];
    const float* proj_b = (const float*)d_in[18];
    float* out = (float*)d_out;

    cudaFuncSetAttribute(gru_mma_kernel,
                         cudaFuncAttributeMaxDynamicSharedMemorySize, SMEM_TOTAL);
    cudaFuncSetAttribute(head_kernel,
                         cudaFuncAttributeMaxDynamicSharedMemorySize, HEAD_SMEM);
    const size_t xsmem = (size_t)(GG * CC + GG + 32 * CC) * sizeof(float);
    cudaFuncSetAttribute(xtab_kernel,
                         cudaFuncAttributeMaxDynamicSharedMemorySize, (int)xsmem);

    prep_misc<<<(PREP_N3 + 255) / 256, 256>>>(whh_f, whh_b, up_w, tokens, proj_w);
    xtab_kernel<<<dim3(8, 2), GG, xsmem>>>(ce, wih_f, bih_f, wih_b, bih_b,
                                           bhh_f, bhh_b);
    gru_mma_kernel<<<dim3(BATCH / BM, 2), NTH, SMEM_TOTAL>>>(bhh_f, bhh_b);
    head_kernel<<<BATCH / HB, 512, HEAD_SMEM>>>(lang, down_w, down_b, up_b,
                                                ln_g, ln_b, proj_b, out);
}

// round 14
// speedup vs baseline: 1.2299x; 1.0068x over previous
#include <cuda_runtime.h>
#include <cuda_fp16.h>
#include <cuda_bf16.h>
#include <math.h>
#include <stdint.h>

// Problem dims
#define BATCH 2048
#define TT    128
#define VV    256
#define CC    32
#define HH    128
#define EE    256
#define GG    384   // 3*H
#define OO    256
#define NLN   3
#define BNK   32

// GRU tiling
#define BM    32      // batch rows per CTA (2 streams x 16)
#define NTH   512     // 16 warps, 24 gate-cols each
// SMEM byte offsets
#define SW0   0                   // w fp16: [384][128] half, swizzled (96KB)
#define SH16(s) (98304 + (s) * 4096)   // h fp16 per stream [16][128]
#define SMEM_TOTAL 106496

// Head SMEM: phase A = down_w fp32 (96KB) | up_wT fp32 (96KB); y hi/lo 16KB.
// Phase B reuses [0,128KB) of the weight region for proj_w fp16.
#define HDOWN 0
#define HUP   98304
#define HYHI  196608
#define HYLO  204800
#define HEAD_SMEM 212992

// Scratch (static device globals)
__device__ __align__(16) __half g_w0[2 * GG * HH];  // [dir][p][k] fp16
__device__ float g_xtab[2 * VV * GG];   // permuted x@w_ih^T + b_ih (+b_hh r,z)
__device__ float g_feat[BATCH * EE];
__device__ float g_upwT[NLN * BNK * EE]; // up_w transposed: [l][d][e]
__device__ int   g_tokT[TT * BATCH];     // tokens transposed [t][b]
__device__ __align__(16) __half g_pw16[OO * EE];  // proj_w fp16, swizzled rows

// ---------------------------------------------------------------------------
// Activations: HW tanh for r/z sigmoids; n-tanh via direct exp identity.
// ---------------------------------------------------------------------------
__device__ __forceinline__ float tanh_e(float v) {
    float t = fminf(v * 2.8853900817779268f, 126.0f);
    float e; asm("ex2.approx.f32 %0, %1;" : "=f"(e) : "f"(t));
    float rp; asm("rcp.approx.f32 %0, %1;" : "=f"(rp) : "f"(e + 1.0f));
    return (e - 1.0f) * rp;
}
__device__ __forceinline__ float tanh_hw(float x) {
    float y; asm("tanh.approx.f32 %0, %1;" : "=f"(y) : "f"(x));
    return y;
}
__device__ __forceinline__ float sigm_fast(float x) {
    return fmaf(tanh_hw(0.5f * x), 0.5f, 0.5f);
}

// ---------------------------------------------------------------------------
// MMA / ldmatrix wrappers
// ---------------------------------------------------------------------------
__device__ __forceinline__ void ldsm4(uint32_t& r0, uint32_t& r1, uint32_t& r2,
                                      uint32_t& r3, uint32_t addr) {
    asm volatile("ldmatrix.sync.aligned.m8n8.x4.shared.b16 {%0,%1,%2,%3}, [%4];"
                 : "=r"(r0), "=r"(r1), "=r"(r2), "=r"(r3) : "r"(addr));
}
__device__ __forceinline__ void mma16816(float* d, const uint32_t* a,
                                         uint32_t b0, uint32_t b1) {
    asm volatile(
        "mma.sync.aligned.m16n8k16.row.col.f32.f16.f16.f32 "
        "{%0,%1,%2,%3}, {%4,%5,%6,%7}, {%8,%9}, {%0,%1,%2,%3};"
        : "+f"(d[0]), "+f"(d[1]), "+f"(d[2]), "+f"(d[3])
        : "r"(a[0]), "r"(a[1]), "r"(a[2]), "r"(a[3]), "r"(b0), "r"(b1));
}

// gate-dim permutation: orig g = t*128 + j -> p = 24*(j>>3) + 8*t + (j&7)
__device__ __forceinline__ int permute_g(int g) {
    int t = g >> 7, j = g & 127;
    return 24 * (j >> 3) + 8 * t + (j & 7);
}

// ---------------------------------------------------------------------------
// Prep A: xtab (permuted), 4 vocab rows per CTA -> grid (64, 2) = 128 CTAs.
// b_ih + b_hh(r,z) folded (R6-exact math).
// ---------------------------------------------------------------------------
__global__ void xtab_kernel(const float* __restrict__ ce,
                            const float* __restrict__ wih_f, const float* __restrict__ bih_f,
                            const float* __restrict__ wih_b, const float* __restrict__ bih_b,
                            const float* __restrict__ bhh_f, const float* __restrict__ bhh_b) {
    extern __shared__ float xsm[];
    float* ws = xsm;               // [384*32]
    float* bs = ws + GG * CC;      // [384]
    float* cs = bs + GG;           // [4*32]
    const int d = blockIdx.y, g = threadIdx.x;
    const float* wih = d ? wih_b : wih_f;
    const float* bih = d ? bih_b : bih_f;
    const float* bhh = d ? bhh_b : bhh_f;
    for (int i = g; i < GG * CC; i += GG) ws[i] = wih[i];
    bs[g] = bih[g] + (g < 2 * HH ? bhh[g] : 0.0f);
    const int v0 = blockIdx.x * 4;
    for (int i = g; i < 4 * CC; i += GG) cs[i] = ce[v0 * CC + i];
    __syncthreads();
    const int p = permute_g(g);
    #pragma unroll
    for (int vi = 0; vi < 4; vi++) {
        float s = bs[g];
        #pragma unroll
        for (int c = 0; c < CC; c++) s = fmaf(cs[vi * CC + c], ws[g * CC + c], s);
        g_xtab[(d * VV + v0 + vi) * GG + p] = s;
    }
}

// ---------------------------------------------------------------------------
// Prep B (fused): w_hh fp16 permuted + up_w transpose + proj_w fp16.
// ---------------------------------------------------------------------------
#define PREP_N0 (2 * GG * HH)
#define PREP_N1 (PREP_N0 + NLN * EE * BNK)
#define PREP_N2 (PREP_N1 + OO * EE)
__global__ void prep_misc(const float* __restrict__ whh_f,
                          const float* __restrict__ whh_b,
                          const float* __restrict__ up_w,
                          const float* __restrict__ proj_w) {
    const int i = blockIdx.x * 256 + threadIdx.x;
    if (i < PREP_N0) {
        int d = i / (GG * HH), rem = i % (GG * HH);
        int g = rem / HH, k = rem % HH;
        const float* w = d ? whh_b : whh_f;
        g_w0[d * GG * HH + permute_g(g) * HH + k] = __float2half_rn(w[g * HH + k]);
    } else if (i < PREP_N1) {
        int j = i - PREP_N0;
        int l = j / (EE * BNK), rem = j % (EE * BNK);
        int e = rem / BNK, dd = rem % BNK;
        g_upwT[(l * BNK + dd) * EE + e] = up_w[j];
    } else if (i < PREP_N2) {
        int j = i - PREP_N1;
        int o = j >> 8, e = j & 255;
        // swizzled row layout: 16B chunk c=e>>3 -> position (c ^ (o&7)) low bits
        int pos = (((e >> 3) ^ (o & 7)) << 3) | (e & 7);
        g_pw16[o * EE + pos] = __float2half_rn(proj_w[j]);
    }
}

// ---------------------------------------------------------------------------
// Prep C: tokens transpose via 32x32 SMEM tiles (coalesced both sides).
// grid (TT/32, BATCH/32) = (4, 64), 256 threads.
// ---------------------------------------------------------------------------
__global__ void tokT_kernel(const int* __restrict__ tokens) {
    __shared__ int tile[32][33];
    const int bt = blockIdx.x, bb = blockIdx.y;
    const int x = threadIdx.x & 31, y0 = threadIdx.x >> 5;  // y0: 0..7
    #pragma unroll
    for (int i = 0; i < 32; i += 8)
        tile[y0 + i][x] = tokens[(bb * 32 + y0 + i) * TT + bt * 32 + x];
    __syncthreads();
    #pragma unroll
    for (int i = 0; i < 32; i += 8)
        g_tokT[(bt * 32 + y0 + i) * BATCH + bb * 32 + x] = tile[x][y0 + i];
}

// ---------------------------------------------------------------------------
// GRU via mma (R13-exact, untouched). grid (64, 2) x 512 threads.
// ---------------------------------------------------------------------------
__global__ __launch_bounds__(NTH, 1) void gru_mma_kernel(
    const float* __restrict__ bhh_f, const float* __restrict__ bhh_b) {
    extern __shared__ __align__(16) char smem[];
    const uint32_t sb = (uint32_t)__cvta_generic_to_shared(smem);

    const int dir  = blockIdx.y;
    const int b0r  = blockIdx.x * BM;
    const int tid  = threadIdx.x;
    const int w    = tid >> 5;      // 0..15
    const int lane = tid & 31;
    const int lr   = lane >> 2;     // 0..7
    const int lq   = lane & 3;      // 0..3

    const float* bhh = dir ? bhh_b : bhh_f;
    const float* xt  = g_xtab + dir * VV * GG;

    // ---- load w (swizzled) + zero h buffers ----
    {
        const uint4* gw0 = (const uint4*)(g_w0 + dir * (GG * HH));
        for (int idx = tid; idx < GG * 16; idx += NTH) {
            int n = idx >> 4, c = idx & 15;
            int off = n * 256 + ((c ^ (n & 7)) << 4);
            *(uint4*)(smem + SW0 + off) = gw0[idx];
        }
        for (int idx = tid; idx < 512; idx += NTH)
            ((uint4*)(smem + SH16(0)))[idx] = make_uint4(0, 0, 0, 0);
    }

    // n-gate bias only (r,z folded into xtab)
    float bias_n[2];
    #pragma unroll
    for (int c = 0; c < 2; c++)
        bias_n[c] = bhh[2 * 128 + 8 * w + 2 * lq + c];

    // ldmatrix addressing constants
    const int ar  = lane & 15;
    const int ahi = lane >> 4;
    const int asw = ar & 7;
    const int bj  = lane >> 3;
    const int bsw = lane & 7;
    const int brow = (24 * w + (lane & 7)) * 256;

    // h' store offsets (chunk index = w since unit j = 8w + ..)
    int stoff[2];
    #pragma unroll
    for (int ri = 0; ri < 2; ri++)
        stoff[ri] = (lr + 8 * ri) * 256 + ((w ^ lr) << 4) + 4 * lq;

    __syncthreads();

    // ---- cache B fragments for gate groups nt=0,1 (loop-invariant) ----
    uint32_t Brg[2][4][4];
    #pragma unroll
    for (int nt = 0; nt < 2; nt++)
        #pragma unroll
        for (int kc2 = 0; kc2 < 4; kc2++) {
            uint32_t chunk = (uint32_t)(((4 * kc2 + bj) ^ bsw) << 4);
            ldsm4(Brg[nt][kc2][0], Brg[nt][kc2][1], Brg[nt][kc2][2],
                  Brg[nt][kc2][3], sb + SW0 + brow + nt * 2048 + chunk);
        }

    float hprev[2][2][2];
    float acc[2][3][4];
    #pragma unroll
    for (int s = 0; s < 2; s++) {
        #pragma unroll
        for (int ri = 0; ri < 2; ri++)
            #pragma unroll
            for (int c = 0; c < 2; c++) hprev[s][ri][c] = 0.0f;
        #pragma unroll
        for (int rg = 0; rg < 4; rg++) {
            acc[s][0][rg] = 0.0f;
            acc[s][1][rg] = 0.0f;
            acc[s][2][rg] = bias_n[rg & 1];
        }
    }

    #pragma unroll 1
    for (int t = 0; t < TT; t++) {
        const int tcol = dir ? (TT - 1 - t) : t;
        const int* tokrow = g_tokT + tcol * BATCH + b0r;

        // xp gather for both streams (coalesced tokens, L2-resident table)
        float2 xp[2][2][3];
        #pragma unroll
        for (int s = 0; s < 2; s++)
            #pragma unroll
            for (int ri = 0; ri < 2; ri++) {
                int tok = tokrow[16 * s + 8 * ri + lr];
                const float2* xr = (const float2*)(xt + tok * GG + 24 * w);
                #pragma unroll
                for (int u = 0; u < 3; u++)
                    xp[s][ri][u] = xr[4 * u + lq];
            }

        #pragma unroll
        for (int ph = 0; ph < 2; ph++) {
            const int sm_ = 1 - ph;   // mma stream
            const int sg  = ph;       // gate stream

            // reset mma-stream accumulators
            #pragma unroll
            for (int rg = 0; rg < 4; rg++) {
                acc[sm_][0][rg] = 0.0f;
                acc[sm_][1][rg] = 0.0f;
                acc[sm_][2][rg] = bias_n[rg & 1];
            }

            const bool do_mma = ph ? (t < TT - 1) : (t > 0);
            const uint32_t ab0 = sb + SH16(sm_) + ar * 256;

            #pragma unroll
            for (int kc2 = 0; kc2 < 4; kc2++) {
                uint32_t a0[8];
                if (do_mma) {
                    uint32_t clo = (uint32_t)(((4 * kc2 + ahi) ^ asw) << 4);
                    uint32_t chi = (uint32_t)(((4 * kc2 + 2 + ahi) ^ asw) << 4);
                    ldsm4(a0[0], a0[1], a0[2], a0[3], ab0 + clo);
                    ldsm4(a0[4], a0[5], a0[6], a0[7], ab0 + chi);
                }

                // one gate cell of the gate stream, interleaved with mma
                {
                    const int ri = kc2 >> 1, c01 = kc2 & 1, rg = 2 * ri + c01;
                    float xr_ = (c01 ? xp[sg][ri][0].y : xp[sg][ri][0].x)
                                + acc[sg][0][rg];
                    float xz_ = (c01 ? xp[sg][ri][1].y : xp[sg][ri][1].x)
                                + acc[sg][1][rg];
                    float xn_ = (c01 ? xp[sg][ri][2].y : xp[sg][ri][2].x);
                    float nh  = acc[sg][2][rg];
                    float r = sigm_fast(xr_);
                    float z = sigm_fast(xz_);
                    float n = tanh_e(fmaf(r, nh, xn_));
                    float h = fmaf(z, hprev[sg][ri][c01] - n, n);
                    hprev[sg][ri][c01] = h;
                    *(__half*)(smem + SH16(sg) + stoff[ri] + 2 * c01) =
                        __float2half_rn(h);
                }

                if (do_mma) {
                    mma16816(acc[sm_][0], a0 + 0, Brg[0][kc2][0], Brg[0][kc2][1]);
                    mma16816(acc[sm_][0], a0 + 4, Brg[0][kc2][2], Brg[0][kc2][3]);
                    mma16816(acc[sm_][1], a0 + 0, Brg[1][kc2][0], Brg[1][kc2][1]);
                    mma16816(acc[sm_][1], a0 + 4, Brg[1][kc2][2], Brg[1][kc2][3]);
                    uint32_t bh[4];
                    const uint32_t chunk =
                        (uint32_t)(((4 * kc2 + bj) ^ bsw) << 4);
                    ldsm4(bh[0], bh[1], bh[2], bh[3],
                          sb + SW0 + brow + 2 * 2048 + chunk);
                    mma16816(acc[sm_][2], a0 + 0, bh[0], bh[1]);
                    mma16816(acc[sm_][2], a0 + 4, bh[2], bh[3]);
                }
            }
            __syncthreads();
        }
    }

    // final hidden -> feat
    #pragma unroll
    for (int s = 0; s < 2; s++)
        #pragma unroll
        for (int ri = 0; ri < 2; ri++)
            #pragma unroll
            for (int c = 0; c < 2; c++) {
                int m = 16 * s + lr + 8 * ri;
                int j = 8 * w + 2 * lq + c;
                g_feat[(b0r + m) * EE + dir * HH + j] = hprev[s][ri][c];
            }
}

// ---------------------------------------------------------------------------
// Head v6 (R12-exact): HB=16 rows, 512 threads, grid 128 (single wave).
// ---------------------------------------------------------------------------
#define HB 16
__global__ __launch_bounds__(512) void head_kernel(
    const int* __restrict__ lang_ids,
    const float* __restrict__ down_w, const float* __restrict__ down_b,
    const float* __restrict__ up_b,
    const float* __restrict__ ln_g,   const float* __restrict__ ln_b,
    const float* __restrict__ proj_b,
    float* __restrict__ out) {
    extern __shared__ __align__(16) char hsm[];
    const uint32_t sb = (uint32_t)__cvta_generic_to_shared(hsm);
    const int tid = threadIdx.x, w = tid >> 5, lane = tid & 31;
    const int b0 = blockIdx.x * HB;
    const int b = b0 + w;                   // one row per warp (16 warps)
    const int l = lang_ids[b];
    const float* fb = g_feat + b * EE;

    // ---- stage adapter weights (all langs) into SMEM ----
    {
        const uint4* gd = (const uint4*)down_w;
        const uint4* gu = (const uint4*)g_upwT;
        #pragma unroll
        for (int k = 0; k < 12; k++) {
            ((uint4*)(hsm + HDOWN))[tid + 512 * k] = gd[tid + 512 * k];
            ((uint4*)(hsm + HUP))[tid + 512 * k]   = gu[tid + 512 * k];
        }
    }
    __syncthreads();

    // ---- adapter (one row per warp), weights from SMEM ----
    float4 f4[8];
    #pragma unroll
    for (int c = 0; c < 8; c++)
        f4[c] = *(const float4*)(fb + (lane & 7) * 4 + 32 * c);

    float hid = 0.0f;
    const float* dwb = (const float*)(hsm + HDOWN) + l * BNK * EE;
    #pragma unroll
    for (int g = 0; g < 8; g++) {
        const int d = 4 * g + (lane >> 3);
        const float* wr = dwb + d * EE + (lane & 7) * 4;
        float s = 0.0f;
        #pragma unroll
        for (int c = 0; c < 8; c++) {
            float4 wv = *(const float4*)(wr + 32 * c);
            s = fmaf(f4[c].x, wv.x, s); s = fmaf(f4[c].y, wv.y, s);
            s = fmaf(f4[c].z, wv.z, s); s = fmaf(f4[c].w, wv.w, s);
        }
        s += __shfl_xor_sync(0xffffffffu, s, 1);
        s += __shfl_xor_sync(0xffffffffu, s, 2);
        s += __shfl_xor_sync(0xffffffffu, s, 4);
        float got = __shfl_sync(0xffffffffu, s, (lane & 3) * 8);
        if ((lane >> 2) == g) hid = got;
    }
    hid += down_b[l * BNK + lane];
    hid = 0.5f * hid * (1.0f + erff(hid * 0.7071067811865476f));

    const float4 fx0 = *(const float4*)(fb + lane * 8);
    const float4 fx1 = *(const float4*)(fb + lane * 8 + 4);
    float4 a0 = *(const float4*)(up_b + l * EE + lane * 8);
    float4 a1 = *(const float4*)(up_b + l * EE + lane * 8 + 4);
    const float* uwb = (const float*)(hsm + HUP) + l * BNK * EE;
    #pragma unroll 4
    for (int d = 0; d < BNK; d++) {
        float hd = __shfl_sync(0xffffffffu, hid, d);
        float4 u0 = *(const float4*)(uwb + d * EE + lane * 8);
        float4 u1 = *(const float4*)(uwb + d * EE + lane * 8 + 4);
        a0.x = fmaf(hd, u0.x, a0.x); a0.y = fmaf(hd, u0.y, a0.y);
        a0.z = fmaf(hd, u0.z, a0.z); a0.w = fmaf(hd, u0.w, a0.w);
        a1.x = fmaf(hd, u1.x, a1.x); a1.y = fmaf(hd, u1.y, a1.y);
        a1.z = fmaf(hd, u1.z, a1.z); a1.w = fmaf(hd, u1.w, a1.w);
    }
    float x[8] = {fx0.x + a0.x, fx0.y + a0.y, fx0.z + a0.z, fx0.w + a0.w,
                  fx1.x + a1.x, fx1.y + a1.y, fx1.z + a1.z, fx1.w + a1.w};
    float s1 = 0.0f, s2 = 0.0f;
    #pragma unroll
    for (int j = 0; j < 8; j++) { s1 += x[j]; s2 = fmaf(x[j], x[j], s2); }
    #pragma unroll
    for (int o = 16; o; o >>= 1) {
        s1 += __shfl_xor_sync(0xffffffffu, s1, o);
        s2 += __shfl_xor_sync(0xffffffffu, s2, o);
    }
    const float mu = s1 * (1.0f / EE);
    const float rstd = rsqrtf(s2 * (1.0f / EE) - mu * mu + 1e-5f);
    const float4 g0 = *(const float4*)(ln_g + l * EE + lane * 8);
    const float4 g1 = *(const float4*)(ln_g + l * EE + lane * 8 + 4);
    const float4 bb0 = *(const float4*)(ln_b + l * EE + lane * 8);
    const float4 bb1 = *(const float4*)(ln_b + l * EE + lane * 8 + 4);
    float y[8];
    y[0] = (x[0]-mu)*rstd*g0.x + bb0.x;  y[1] = (x[1]-mu)*rstd*g0.y + bb0.y;
    y[2] = (x[2]-mu)*rstd*g0.z + bb0.z;  y[3] = (x[3]-mu)*rstd*g0.w + bb0.w;
    y[4] = (x[4]-mu)*rstd*g1.x + bb1.x;  y[5] = (x[5]-mu)*rstd*g1.y + bb1.y;
    y[6] = (x[6]-mu)*rstd*g1.z + bb1.z;  y[7] = (x[7]-mu)*rstd*g1.w + bb1.w;

    // fp16 hi/lo split -> SMEM (lane = 16B chunk index, XOR-swizzled by row)
    {
        __half h_[8], c_[8];
        #pragma unroll
        for (int j = 0; j < 8; j++) {
            h_[j] = __float2half_rn(y[j]);
            c_[j] = __float2half_rn(y[j] - __half2float(h_[j]));
        }
        const int off = w * 512 + ((lane ^ (w & 7)) << 4);
        *(uint4*)(hsm + HYHI + off) = *(const uint4*)h_;
        *(uint4*)(hsm + HYLO + off) = *(const uint4*)c_;
    }
    __syncthreads();

    // ---- phase B: reuse weight region for proj_w fp16, then mma ----
    {
        const uint4* gp = (const uint4*)g_pw16;
        #pragma unroll
        for (int k = 0; k < 16; k++)
            ((uint4*)(hsm + HDOWN))[tid + 512 * k] = gp[tid + 512 * k];
    }
    __syncthreads();

    // projection via mma: warp w -> output cols [16w, 16w+16)
    const int ar  = lane & 15;           // A row
    const int ahi = lane >> 4;
    const int asw = ar & 7;
    const int bj  = lane >> 3;           // B k-chunk within k32
    const int bsw = lane & 7;
    const uint32_t ahib = sb + HYHI + ar * 512;
    const uint32_t alob = sb + HYLO + ar * 512;
    const uint32_t brow0 = sb + HDOWN + (16 * w + (lane & 7)) * 512;
    const uint32_t brow1 = brow0 + 8 * 512;

    const int lr = lane >> 2, lq = lane & 3;
    float pb0 = proj_b[16 * w + 2 * lq];
    float pb1 = proj_b[16 * w + 2 * lq + 1];
    float pb8 = proj_b[16 * w + 8 + 2 * lq];
    float pb9 = proj_b[16 * w + 8 + 2 * lq + 1];
    float acc[2][4] = {{pb0, pb1, pb0, pb1}, {pb8, pb9, pb8, pb9}};

    #pragma unroll
    for (int kc32 = 0; kc32 < 8; kc32++) {
        uint32_t ah[8], al[8], bF0[4], bF1[4];
        uint32_t clo = (uint32_t)(((4 * kc32 + ahi) ^ asw) << 4);
        uint32_t chi = (uint32_t)(((4 * kc32 + 2 + ahi) ^ asw) << 4);
        ldsm4(ah[0], ah[1], ah[2], ah[3], ahib + clo);
        ldsm4(ah[4], ah[5], ah[6], ah[7], ahib + chi);
        ldsm4(al[0], al[1], al[2], al[3], alob + clo);
        ldsm4(al[4], al[5], al[6], al[7], alob + chi);
        uint32_t bc = (uint32_t)(((4 * kc32 + bj) ^ bsw) << 4);
        ldsm4(bF0[0], bF0[1], bF0[2], bF0[3], brow0 + bc);
        ldsm4(bF1[0], bF1[1], bF1[2], bF1[3], brow1 + bc);
        #pragma unroll
        for (int kk = 0; kk < 2; kk++) {
            mma16816(acc[0], ah + 4 * kk, bF0[2 * kk], bF0[2 * kk + 1]);
            mma16816(acc[0], al + 4 * kk, bF0[2 * kk], bF0[2 * kk + 1]);
            mma16816(acc[1], ah + 4 * kk, bF1[2 * kk], bF1[2 * kk + 1]);
            mma16816(acc[1], al + 4 * kk, bF1[2 * kk], bF1[2 * kk + 1]);
        }
    }

    // write out: c-frag: regs {0,1} row lr, {2,3} row lr+8; cols 2lq+{0,1}
    #pragma unroll
    for (int nt = 0; nt < 2; nt++) {
        const int col = 16 * w + 8 * nt + 2 * lq;
        *(float2*)(out + (b0 + lr) * OO + col)
            = make_float2(acc[nt][0], acc[nt][1]);
        *(float2*)(out + (b0 + lr + 8) * OO + col)
            = make_float2(acc[nt][2], acc[nt][3]);
    }
}

// ---------------------------------------------------------------------------
extern "C" void kernel_launch(void* const* d_in, const int* in_sizes, int n_in,
                              void* d_out, int out_size) {
    const int*   tokens = (const int*)d_in[0];
    const int*   lang   = (const int*)d_in[1];
    const float* ce     = (const float*)d_in[2];
    const float* wih_f  = (const float*)d_in[3];
    const float* whh_f  = (const float*)d_in[4];
    const float* bih_f  = (const float*)d_in[5];
    const float* bhh_f  = (const float*)d_in[6];
    const float* wih_b  = (const float*)d_in[7];
    const float* whh_b  = (const float*)d_in[8];
    const float* bih_b  = (const float*)d_in[9];
    const float* bhh_b  = (const float*)d_in[10];
    const float* down_w = (const float*)d_in[11];
    const float* down_b = (const float*)d_in[12];
    const float* up_w   = (const float*)d_in[13];
    const float* up_b   = (const float*)d_in[14];
    const float* ln_g   = (const float*)d_in[15];
    const float* ln_b   = (const float*)d_in[16];
    const float* proj_w = (const float*)d_in[17];
    const float* proj_b = (const float*)d_in[18];
    float* out = (float*)d_out;

    cudaFuncSetAttribute(gru_mma_kernel,
                         cudaFuncAttributeMaxDynamicSharedMemorySize, SMEM_TOTAL);
    cudaFuncSetAttribute(head_kernel,
                         cudaFuncAttributeMaxDynamicSharedMemorySize, HEAD_SMEM);
    const size_t xsmem = (size_t)(GG * CC + GG + 4 * CC) * sizeof(float);
    cudaFuncSetAttribute(xtab_kernel,
                         cudaFuncAttributeMaxDynamicSharedMemorySize, (int)xsmem);

    tokT_kernel<<<dim3(TT / 32, BATCH / 32), 256>>>(tokens);
    prep_misc<<<(PREP_N2 + 255) / 256, 256>>>(whh_f, whh_b, up_w, proj_w);
    xtab_kernel<<<dim3(VV / 4, 2), GG, xsmem>>>(ce, wih_f, bih_f, wih_b, bih_b,
                                                bhh_f, bhh_b);
    gru_mma_kernel<<<dim3(BATCH / BM, 2), NTH, SMEM_TOTAL>>>(bhh_f, bhh_b);
    head_kernel<<<BATCH / HB, 512, HEAD_SMEM>>>(lang, down_w, down_b, up_b,
                                                ln_g, ln_b, proj_b, out);
}

// round 15
// speedup vs baseline: 1.3193x; 1.0727x over previous
#include <cuda_runtime.h>
#include <cuda_fp16.h>
#include <cuda_bf16.h>
#include <math.h>
#include <stdint.h>

// Problem dims
#define BATCH 2048
#define TT    128
#define VV    256
#define CC    32
#define HH    128
#define EE    256
#define GG    384   // 3*H
#define OO    256
#define NLN   3
#define BNK   32

// GRU tiling: 256 threads (8 warps x 48 gate-cols), 16 rows, 2 CTAs/SM
#define BM    16
#define NTH   256
// SMEM byte offsets
#define SW0   0                   // w fp16: [384][128] half, swizzled (96KB)
#define SH16(b) (98304 + (b) * 4096)   // h fp16 double buffer [16][128]
#define SMEM_TOTAL 106496

// Head SMEM: phase A = down_w fp32 (96KB) | up_wT fp32 (96KB); y hi/lo 16KB.
#define HDOWN 0
#define HUP   98304
#define HYHI  196608
#define HYLO  204800
#define HEAD_SMEM 212992

// Scratch (static device globals)
__device__ __align__(16) __half g_w0[2 * GG * HH];  // [dir][p][k] fp16
__device__ float g_xtab[2 * VV * GG];   // permuted x@w_ih^T + b_ih (+b_hh r,z)
__device__ float g_feat[BATCH * EE];
__device__ float g_upwT[NLN * BNK * EE]; // up_w transposed: [l][d][e]
__device__ int   g_tokT[TT * BATCH];     // tokens transposed [t][b]
__device__ __align__(16) __half g_pw16[OO * EE];  // proj_w fp16, swizzled rows

// ---------------------------------------------------------------------------
// Activations: HW tanh for r/z sigmoids; n-tanh via direct exp identity.
// ---------------------------------------------------------------------------
__device__ __forceinline__ float tanh_e(float v) {
    float t = fminf(v * 2.8853900817779268f, 126.0f);
    float e; asm("ex2.approx.f32 %0, %1;" : "=f"(e) : "f"(t));
    float rp; asm("rcp.approx.f32 %0, %1;" : "=f"(rp) : "f"(e + 1.0f));
    return (e - 1.0f) * rp;
}
__device__ __forceinline__ float tanh_hw(float x) {
    float y; asm("tanh.approx.f32 %0, %1;" : "=f"(y) : "f"(x));
    return y;
}
__device__ __forceinline__ float sigm_fast(float x) {
    return fmaf(tanh_hw(0.5f * x), 0.5f, 0.5f);
}

// ---------------------------------------------------------------------------
// MMA / ldmatrix wrappers
// ---------------------------------------------------------------------------
__device__ __forceinline__ void ldsm4(uint32_t& r0, uint32_t& r1, uint32_t& r2,
                                      uint32_t& r3, uint32_t addr) {
    asm volatile("ldmatrix.sync.aligned.m8n8.x4.shared.b16 {%0,%1,%2,%3}, [%4];"
                 : "=r"(r0), "=r"(r1), "=r"(r2), "=r"(r3) : "r"(addr));
}
__device__ __forceinline__ void mma16816(float* d, const uint32_t* a,
                                         uint32_t b0, uint32_t b1) {
    asm volatile(
        "mma.sync.aligned.m16n8k16.row.col.f32.f16.f16.f32 "
        "{%0,%1,%2,%3}, {%4,%5,%6,%7}, {%8,%9}, {%0,%1,%2,%3};"
        : "+f"(d[0]), "+f"(d[1]), "+f"(d[2]), "+f"(d[3])
        : "r"(a[0]), "r"(a[1]), "r"(a[2]), "r"(a[3]), "r"(b0), "r"(b1));
}

// gate-dim permutation for 8 warps (48 cols each):
// orig g = t*128 + j -> p = 48*(j>>4) + 16*t + (j&15)
__device__ __forceinline__ int permute_g(int g) {
    int t = g >> 7, j = g & 127;
    return 48 * (j >> 4) + 16 * t + (j & 15);
}

// ---------------------------------------------------------------------------
// Prep A: xtab (permuted), 4 vocab rows per CTA -> grid (64, 2) = 128 CTAs.
// b_ih + b_hh(r,z) folded.
// ---------------------------------------------------------------------------
__global__ void xtab_kernel(const float* __restrict__ ce,
                            const float* __restrict__ wih_f, const float* __restrict__ bih_f,
                            const float* __restrict__ wih_b, const float* __restrict__ bih_b,
                            const float* __restrict__ bhh_f, const float* __restrict__ bhh_b) {
    extern __shared__ float xsm[];
    float* ws = xsm;               // [384*32]
    float* bs = ws + GG * CC;      // [384]
    float* cs = bs + GG;           // [4*32]
    const int d = blockIdx.y, g = threadIdx.x;
    const float* wih = d ? wih_b : wih_f;
    const float* bih = d ? bih_b : bih_f;
    const float* bhh = d ? bhh_b : bhh_f;
    for (int i = g; i < GG * CC; i += GG) ws[i] = wih[i];
    bs[g] = bih[g] + (g < 2 * HH ? bhh[g] : 0.0f);
    const int v0 = blockIdx.x * 4;
    for (int i = g; i < 4 * CC; i += GG) cs[i] = ce[v0 * CC + i];
    __syncthreads();
    const int p = permute_g(g);
    #pragma unroll
    for (int vi = 0; vi < 4; vi++) {
        float s = bs[g];
        #pragma unroll
        for (int c = 0; c < CC; c++) s = fmaf(cs[vi * CC + c], ws[g * CC + c], s);
        g_xtab[(d * VV + v0 + vi) * GG + p] = s;
    }
}

// ---------------------------------------------------------------------------
// Prep B (fused): w_hh fp16 permuted + up_w transpose + proj_w fp16.
// ---------------------------------------------------------------------------
#define PREP_N0 (2 * GG * HH)
#define PREP_N1 (PREP_N0 + NLN * EE * BNK)
#define PREP_N2 (PREP_N1 + OO * EE)
__global__ void prep_misc(const float* __restrict__ whh_f,
                          const float* __restrict__ whh_b,
                          const float* __restrict__ up_w,
                          const float* __restrict__ proj_w) {
    const int i = blockIdx.x * 256 + threadIdx.x;
    if (i < PREP_N0) {
        int d = i / (GG * HH), rem = i % (GG * HH);
        int g = rem / HH, k = rem % HH;
        const float* w = d ? whh_b : whh_f;
        g_w0[d * GG * HH + permute_g(g) * HH + k] = __float2half_rn(w[g * HH + k]);
    } else if (i < PREP_N1) {
        int j = i - PREP_N0;
        int l = j / (EE * BNK), rem = j % (EE * BNK);
        int e = rem / BNK, dd = rem % BNK;
        g_upwT[(l * BNK + dd) * EE + e] = up_w[j];
    } else if (i < PREP_N2) {
        int j = i - PREP_N1;
        int o = j >> 8, e = j & 255;
        int pos = (((e >> 3) ^ (o & 7)) << 3) | (e & 7);
        g_pw16[o * EE + pos] = __float2half_rn(proj_w[j]);
    }
}

// ---------------------------------------------------------------------------
// Prep C: tokens transpose via 32x32 SMEM tiles.
// ---------------------------------------------------------------------------
__global__ void tokT_kernel(const int* __restrict__ tokens) {
    __shared__ int tile[32][33];
    const int bt = blockIdx.x, bb = blockIdx.y;
    const int x = threadIdx.x & 31, y0 = threadIdx.x >> 5;
    #pragma unroll
    for (int i = 0; i < 32; i += 8)
        tile[y0 + i][x] = tokens[(bb * 32 + y0 + i) * TT + bt * 32 + x];
    __syncthreads();
    #pragma unroll
    for (int i = 0; i < 32; i += 8)
        g_tokT[(bt * 32 + y0 + i) * BATCH + bb * 32 + x] = tile[x][y0 + i];
}

// ---------------------------------------------------------------------------
// GRU via mma: 256 threads, 16 rows, 8 warps x 48 cols, h double-buffered,
// one barrier per step. 2 CTAs/SM (grid (128,2) = 256 CTAs) — the co-resident
// CTA fills the stalls of the serialized mma->gates chain.
// ---------------------------------------------------------------------------
__global__ __launch_bounds__(NTH, 2) void gru_mma_kernel(
    const float* __restrict__ bhh_f, const float* __restrict__ bhh_b) {
    extern __shared__ __align__(16) char smem[];
    const uint32_t sb = (uint32_t)__cvta_generic_to_shared(smem);

    const int dir  = blockIdx.y;
    const int b0r  = blockIdx.x * BM;
    const int tid  = threadIdx.x;
    const int w    = tid >> 5;      // 0..7
    const int lane = tid & 31;
    const int lr   = lane >> 2;     // 0..7
    const int lq   = lane & 3;      // 0..3

    const float* bhh = dir ? bhh_b : bhh_f;
    const float* xt  = g_xtab + dir * VV * GG;

    // ---- load w (swizzled) ----
    {
        const uint4* gw0 = (const uint4*)(g_w0 + dir * (GG * HH));
        for (int idx = tid; idx < GG * 16; idx += NTH) {
            int n = idx >> 4, c = idx & 15;
            int off = n * 256 + ((c ^ (n & 7)) << 4);
            *(uint4*)(smem + SW0 + off) = gw0[idx];
        }
    }

    // n-gate biases for this thread's 4 unit cols (j = 16w + 8hf + 2lq + c)
    float bias_n[2][2];
    #pragma unroll
    for (int hf = 0; hf < 2; hf++)
        #pragma unroll
        for (int c = 0; c < 2; c++)
            bias_n[hf][c] = bhh[2 * 128 + 16 * w + 8 * hf + 2 * lq + c];

    // ldmatrix addressing constants
    const int ar  = lane & 15;
    const int ahi = lane >> 4;
    const int asw = ar & 7;
    const int bj  = lane >> 3;
    const int bsw = lane & 7;
    const int brow = (48 * w + (lane & 7)) * 256;

    // h' store offsets: row = lr + 8rr, chunk = 2w + hf, halves at 4lq
    int stoff[2][2];
    #pragma unroll
    for (int rr = 0; rr < 2; rr++)
        #pragma unroll
        for (int hf = 0; hf < 2; hf++)
            stoff[rr][hf] = (lr + 8 * rr) * 256 + (((2 * w + hf) ^ lr) << 4)
                            + 4 * lq;

    float hprev[2][2][2];
    #pragma unroll
    for (int rr = 0; rr < 2; rr++)
        #pragma unroll
        for (int hf = 0; hf < 2; hf++)
            #pragma unroll
            for (int c = 0; c < 2; c++) hprev[rr][hf][c] = 0.0f;

    __syncthreads();

    #pragma unroll 1
    for (int t = 0; t < TT; t++) {
        const int tcol = dir ? (TT - 1 - t) : t;
        const int* tokrow = g_tokT + tcol * BATCH + b0r;

        // xp gather (consumed at end-of-step gates -> natural latency cover)
        float2 xp[2][2][3];   // [rr][hf][gate]
        #pragma unroll
        for (int rr = 0; rr < 2; rr++) {
            int tok = tokrow[8 * rr + lr];
            const float2* xr = (const float2*)(xt + tok * GG);
            #pragma unroll
            for (int hf = 0; hf < 2; hf++)
                #pragma unroll
                for (int u = 0; u < 3; u++)
                    xp[rr][hf][u] = xr[24 * w + 8 * u + 4 * hf + lq];
        }

        // accumulators
        float acc[6][4];
        #pragma unroll
        for (int nt = 0; nt < 4; nt++)
            #pragma unroll
            for (int rg = 0; rg < 4; rg++) acc[nt][rg] = 0.0f;
        #pragma unroll
        for (int hf = 0; hf < 2; hf++)
            #pragma unroll
            for (int rg = 0; rg < 4; rg++)
                acc[4 + hf][rg] = bias_n[hf][rg & 1];

        // ---- mma: acc += h(t) @ w^T ----
        if (t > 0) {
            const uint32_t ab = sb + SH16(t & 1) + ar * 256;
            #pragma unroll
            for (int kc2 = 0; kc2 < 4; kc2++) {
                uint32_t a0[8];
                uint32_t clo = (uint32_t)(((4 * kc2 + ahi) ^ asw) << 4);
                uint32_t chi = (uint32_t)(((4 * kc2 + 2 + ahi) ^ asw) << 4);
                ldsm4(a0[0], a0[1], a0[2], a0[3], ab + clo);
                ldsm4(a0[4], a0[5], a0[6], a0[7], ab + chi);
                const uint32_t chunk = (uint32_t)(((4 * kc2 + bj) ^ bsw) << 4);
                #pragma unroll
                for (int nt = 0; nt < 6; nt++) {
                    uint32_t bh[4];
                    ldsm4(bh[0], bh[1], bh[2], bh[3],
                          sb + SW0 + brow + nt * 2048 + chunk);
                    mma16816(acc[nt], a0 + 0, bh[0], bh[1]);
                    mma16816(acc[nt], a0 + 4, bh[2], bh[3]);
                }
            }
        }

        // ---- gates: 8 cells, store h(t+1) to the other buffer ----
        const uint32_t wrb = sb + SH16((t + 1) & 1);
        #pragma unroll
        for (int rr = 0; rr < 2; rr++)
            #pragma unroll
            for (int hf = 0; hf < 2; hf++) {
                float hv[2];
                #pragma unroll
                for (int c01 = 0; c01 < 2; c01++) {
                    const int rg = 2 * rr + c01;
                    float xr_ = (c01 ? xp[rr][hf][0].y : xp[rr][hf][0].x)
                                + acc[hf][rg];
                    float xz_ = (c01 ? xp[rr][hf][1].y : xp[rr][hf][1].x)
                                + acc[2 + hf][rg];
                    float xn_ = (c01 ? xp[rr][hf][2].y : xp[rr][hf][2].x);
                    float nh  = acc[4 + hf][rg];
                    float r = sigm_fast(xr_);
                    float z = sigm_fast(xz_);
                    float n = tanh_e(fmaf(r, nh, xn_));
                    float h = fmaf(z, hprev[rr][hf][c01] - n, n);
                    hprev[rr][hf][c01] = h;
                    hv[c01] = h;
                }
                *(__half2*)(smem + (wrb - sb) + stoff[rr][hf]) =
                    __halves2half2(__float2half_rn(hv[0]),
                                   __float2half_rn(hv[1]));
            }
        __syncthreads();
    }

    // final hidden -> feat
    #pragma unroll
    for (int rr = 0; rr < 2; rr++)
        #pragma unroll
        for (int hf = 0; hf < 2; hf++)
            #pragma unroll
            for (int c = 0; c < 2; c++) {
                int m = lr + 8 * rr;
                int j = 16 * w + 8 * hf + 2 * lq + c;
                g_feat[(b0r + m) * EE + dir * HH + j] = hprev[rr][hf][c];
            }
}

// ---------------------------------------------------------------------------
// Head v6 (R12-exact): HB=16 rows, 512 threads, grid 128 (single wave).
// ---------------------------------------------------------------------------
#define HB 16
__global__ __launch_bounds__(512) void head_kernel(
    const int* __restrict__ lang_ids,
    const float* __restrict__ down_w, const float* __restrict__ down_b,
    const float* __restrict__ up_b,
    const float* __restrict__ ln_g,   const float* __restrict__ ln_b,
    const float* __restrict__ proj_b,
    float* __restrict__ out) {
    extern __shared__ __align__(16) char hsm[];
    const uint32_t sb = (uint32_t)__cvta_generic_to_shared(hsm);
    const int tid = threadIdx.x, w = tid >> 5, lane = tid & 31;
    const int b0 = blockIdx.x * HB;
    const int b = b0 + w;
    const int l = lang_ids[b];
    const float* fb = g_feat + b * EE;

    // ---- stage adapter weights (all langs) into SMEM ----
    {
        const uint4* gd = (const uint4*)down_w;
        const uint4* gu = (const uint4*)g_upwT;
        #pragma unroll
        for (int k = 0; k < 12; k++) {
            ((uint4*)(hsm + HDOWN))[tid + 512 * k] = gd[tid + 512 * k];
            ((uint4*)(hsm + HUP))[tid + 512 * k]   = gu[tid + 512 * k];
        }
    }
    __syncthreads();

    // ---- adapter (one row per warp), weights from SMEM ----
    float4 f4[8];
    #pragma unroll
    for (int c = 0; c < 8; c++)
        f4[c] = *(const float4*)(fb + (lane & 7) * 4 + 32 * c);

    float hid = 0.0f;
    const float* dwb = (const float*)(hsm + HDOWN) + l * BNK * EE;
    #pragma unroll
    for (int g = 0; g < 8; g++) {
        const int d = 4 * g + (lane >> 3);
        const float* wr = dwb + d * EE + (lane & 7) * 4;
        float s = 0.0f;
        #pragma unroll
        for (int c = 0; c < 8; c++) {
            float4 wv = *(const float4*)(wr + 32 * c);
            s = fmaf(f4[c].x, wv.x, s); s = fmaf(f4[c].y, wv.y, s);
            s = fmaf(f4[c].z, wv.z, s); s = fmaf(f4[c].w, wv.w, s);
        }
        s += __shfl_xor_sync(0xffffffffu, s, 1);
        s += __shfl_xor_sync(0xffffffffu, s, 2);
        s += __shfl_xor_sync(0xffffffffu, s, 4);
        float got = __shfl_sync(0xffffffffu, s, (lane & 3) * 8);
        if ((lane >> 2) == g) hid = got;
    }
    hid += down_b[l * BNK + lane];
    hid = 0.5f * hid * (1.0f + erff(hid * 0.7071067811865476f));

    const float4 fx0 = *(const float4*)(fb + lane * 8);
    const float4 fx1 = *(const float4*)(fb + lane * 8 + 4);
    float4 a0 = *(const float4*)(up_b + l * EE + lane * 8);
    float4 a1 = *(const float4*)(up_b + l * EE + lane * 8 + 4);
    const float* uwb = (const float*)(hsm + HUP) + l * BNK * EE;
    #pragma unroll 4
    for (int d = 0; d < BNK; d++) {
        float hd = __shfl_sync(0xffffffffu, hid, d);
        float4 u0 = *(const float4*)(uwb + d * EE + lane * 8);
        float4 u1 = *(const float4*)(uwb + d * EE + lane * 8 + 4);
        a0.x = fmaf(hd, u0.x, a0.x); a0.y = fmaf(hd, u0.y, a0.y);
        a0.z = fmaf(hd, u0.z, a0.z); a0.w = fmaf(hd, u0.w, a0.w);
        a1.x = fmaf(hd, u1.x, a1.x); a1.y = fmaf(hd, u1.y, a1.y);
        a1.z = fmaf(hd, u1.z, a1.z); a1.w = fmaf(hd, u1.w, a1.w);
    }
    float x[8] = {fx0.x + a0.x, fx0.y + a0.y, fx0.z + a0.z, fx0.w + a0.w,
                  fx1.x + a1.x, fx1.y + a1.y, fx1.z + a1.z, fx1.w + a1.w};
    float s1 = 0.0f, s2 = 0.0f;
    #pragma unroll
    for (int j = 0; j < 8; j++) { s1 += x[j]; s2 = fmaf(x[j], x[j], s2); }
    #pragma unroll
    for (int o = 16; o; o >>= 1) {
        s1 += __shfl_xor_sync(0xffffffffu, s1, o);
        s2 += __shfl_xor_sync(0xffffffffu, s2, o);
    }
    const float mu = s1 * (1.0f / EE);
    const float rstd = rsqrtf(s2 * (1.0f / EE) - mu * mu + 1e-5f);
    const float4 g0 = *(const float4*)(ln_g + l * EE + lane * 8);
    const float4 g1 = *(const float4*)(ln_g + l * EE + lane * 8 + 4);
    const float4 bb0 = *(const float4*)(ln_b + l * EE + lane * 8);
    const float4 bb1 = *(const float4*)(ln_b + l * EE + lane * 8 + 4);
    float y[8];
    y[0] = (x[0]-mu)*rstd*g0.x + bb0.x;  y[1] = (x[1]-mu)*rstd*g0.y + bb0.y;
    y[2] = (x[2]-mu)*rstd*g0.z + bb0.z;  y[3] = (x[3]-mu)*rstd*g0.w + bb0.w;
    y[4] = (x[4]-mu)*rstd*g1.x + bb1.x;  y[5] = (x[5]-mu)*rstd*g1.y + bb1.y;
    y[6] = (x[6]-mu)*rstd*g1.z + bb1.z;  y[7] = (x[7]-mu)*rstd*g1.w + bb1.w;

    {
        __half h_[8], c_[8];
        #pragma unroll
        for (int j = 0; j < 8; j++) {
            h_[j] = __float2half_rn(y[j]);
            c_[j] = __float2half_rn(y[j] - __half2float(h_[j]));
        }
        const int off = w * 512 + ((lane ^ (w & 7)) << 4);
        *(uint4*)(hsm + HYHI + off) = *(const uint4*)h_;
        *(uint4*)(hsm + HYLO + off) = *(const uint4*)c_;
    }
    __syncthreads();

    // ---- phase B: reuse weight region for proj_w fp16, then mma ----
    {
        const uint4* gp = (const uint4*)g_pw16;
        #pragma unroll
        for (int k = 0; k < 16; k++)
            ((uint4*)(hsm + HDOWN))[tid + 512 * k] = gp[tid + 512 * k];
    }
    __syncthreads();

    const int ar  = lane & 15;
    const int ahi = lane >> 4;
    const int asw = ar & 7;
    const int bj  = lane >> 3;
    const int bsw = lane & 7;
    const uint32_t ahib = sb + HYHI + ar * 512;
    const uint32_t alob = sb + HYLO + ar * 512;
    const uint32_t brow0 = sb + HDOWN + (16 * w + (lane & 7)) * 512;
    const uint32_t brow1 = brow0 + 8 * 512;

    const int lr = lane >> 2, lq = lane & 3;
    float pb0 = proj_b[16 * w + 2 * lq];
    float pb1 = proj_b[16 * w + 2 * lq + 1];
    float pb8 = proj_b[16 * w + 8 + 2 * lq];
    float pb9 = proj_b[16 * w + 8 + 2 * lq + 1];
    float acc[2][4] = {{pb0, pb1, pb0, pb1}, {pb8, pb9, pb8, pb9}};

    #pragma unroll
    for (int kc32 = 0; kc32 < 8; kc32++) {
        uint32_t ah[8], al[8], bF0[4], bF1[4];
        uint32_t clo = (uint32_t)(((4 * kc32 + ahi) ^ asw) << 4);
        uint32_t chi = (uint32_t)(((4 * kc32 + 2 + ahi) ^ asw) << 4);
        ldsm4(ah[0], ah[1], ah[2], ah[3], ahib + clo);
        ldsm4(ah[4], ah[5], ah[6], ah[7], ahib + chi);
        ldsm4(al[0], al[1], al[2], al[3], alob + clo);
        ldsm4(al[4], al[5], al[6], al[7], alob + chi);
        uint32_t bc = (uint32_t)(((4 * kc32 + bj) ^ bsw) << 4);
        ldsm4(bF0[0], bF0[1], bF0[2], bF0[3], brow0 + bc);
        ldsm4(bF1[0], bF1[1], bF1[2], bF1[3], brow1 + bc);
        #pragma unroll
        for (int kk = 0; kk < 2; kk++) {
            mma16816(acc[0], ah + 4 * kk, bF0[2 * kk], bF0[2 * kk + 1]);
            mma16816(acc[0], al + 4 * kk, bF0[2 * kk], bF0[2 * kk + 1]);
            mma16816(acc[1], ah + 4 * kk, bF1[2 * kk], bF1[2 * kk + 1]);
            mma16816(acc[1], al + 4 * kk, bF1[2 * kk], bF1[2 * kk + 1]);
        }
    }

    #pragma unroll
    for (int nt = 0; nt < 2; nt++) {
        const int col = 16 * w + 8 * nt + 2 * lq;
        *(float2*)(out + (b0 + lr) * OO + col)
            = make_float2(acc[nt][0], acc[nt][1]);
        *(float2*)(out + (b0 + lr + 8) * OO + col)
            = make_float2(acc[nt][2], acc[nt][3]);
    }
}

// ---------------------------------------------------------------------------
extern "C" void kernel_launch(void* const* d_in, const int* in_sizes, int n_in,
                              void* d_out, int out_size) {
    const int*   tokens = (const int*)d_in[0];
    const int*   lang   = (const int*)d_in[1];
    const float* ce     = (const float*)d_in[2];
    const float* wih_f  = (const float*)d_in[3];
    const float* whh_f  = (const float*)d_in[4];
    const float* bih_f  = (const float*)d_in[5];
    const float* bhh_f  = (const float*)d_in[6];
    const float* wih_b  = (const float*)d_in[7];
    const float* whh_b  = (const float*)d_in[8];
    const float* bih_b  = (const float*)d_in[9];
    const float* bhh_b  = (const float*)d_in[10];
    const float* down_w = (const float*)d_in[11];
    const float* down_b = (const float*)d_in[12];
    const float* up_w   = (const float*)d_in[13];
    const float* up_b   = (const float*)d_in[14];
    const float* ln_g   = (const float*)d_in[15];
    const float* ln_b   = (const float*)d_in[16];
    const float* proj_w = (const float*)d_in[17];
    const float* proj_b = (const float*)d_in[18];
    float* out = (float*)d_out;

    cudaFuncSetAttribute(gru_mma_kernel,
                         cudaFuncAttributeMaxDynamicSharedMemorySize, SMEM_TOTAL);
    cudaFuncSetAttribute(head_kernel,
                         cudaFuncAttributeMaxDynamicSharedMemorySize, HEAD_SMEM);
    const size_t xsmem = (size_t)(GG * CC + GG + 4 * CC) * sizeof(float);
    cudaFuncSetAttribute(xtab_kernel,
                         cudaFuncAttributeMaxDynamicSharedMemorySize, (int)xsmem);

    tokT_kernel<<<dim3(TT / 32, BATCH / 32), 256>>>(tokens);
    prep_misc<<<(PREP_N2 + 255) / 256, 256>>>(whh_f, whh_b, up_w, proj_w);
    xtab_kernel<<<dim3(VV / 4, 2), GG, xsmem>>>(ce, wih_f, bih_f, wih_b, bih_b,
                                                bhh_f, bhh_b);
    gru_mma_kernel<<<dim3(BATCH / BM, 2), NTH, SMEM_TOTAL>>>(bhh_f, bhh_b);
    head_kernel<<<BATCH / HB, 512, HEAD_SMEM>>>(lang, down_w, down_b, up_b,
                                                ln_g, ln_b, proj_b, out);
}

// round 16
// speedup vs baseline: 1.3196x; 1.0002x over previous
#include <cuda_runtime.h>
#include <cuda_fp16.h>
#include <cuda_bf16.h>
#include <math.h>
#include <stdint.h>

// Problem dims
#define BATCH 2048
#define TT    128
#define VV    256
#define CC    32
#define HH    128
#define EE    256
#define GG    384   // 3*H
#define OO    256
#define NLN   3
#define BNK   32

// GRU tiling: 256 threads (8 warps x 48 gate-cols), 16 rows, 2 CTAs/SM
#define BM    16
#define NTH   256
// SMEM byte offsets
#define SW0   0                   // w fp16: [384][128] half, swizzled (96KB)
#define SH16(b) (98304 + (b) * 4096)   // h fp16 double buffer [16][128]
#define SMEM_TOTAL 106496

// Head SMEM: phase A = down_w fp32 (96KB) | up_wT fp32 (96KB); y hi/lo 16KB.
#define HDOWN 0
#define HUP   98304
#define HYHI  196608
#define HYLO  204800
#define HEAD_SMEM 212992

// Scratch (static device globals)
__device__ __align__(16) __half g_w0[2 * GG * HH];  // [dir][p][k] fp16 (r,z x0.5)
__device__ float g_xtab[2 * VV * GG];   // permuted x@w_ih^T + biases (r,z x0.5)
__device__ float g_feat[BATCH * EE];
__device__ float g_upwT[NLN * BNK * EE]; // up_w transposed: [l][d][e]
__device__ int   g_tokT[TT * BATCH];     // tokens transposed [t][b]
__device__ __align__(16) __half g_pw16[OO * EE];  // proj_w fp16, swizzled rows

// ---------------------------------------------------------------------------
// Activations: n-tanh via direct exp identity (2 MUFU).
// ---------------------------------------------------------------------------
__device__ __forceinline__ float tanh_e(float v) {
    float t = fminf(v * 2.8853900817779268f, 126.0f);
    float e; asm("ex2.approx.f32 %0, %1;" : "=f"(e) : "f"(t));
    float rp; asm("rcp.approx.f32 %0, %1;" : "=f"(rp) : "f"(e + 1.0f));
    return (e - 1.0f) * rp;
}

// ---------------------------------------------------------------------------
// MMA / ldmatrix wrappers
// ---------------------------------------------------------------------------
__device__ __forceinline__ void ldsm4(uint32_t& r0, uint32_t& r1, uint32_t& r2,
                                      uint32_t& r3, uint32_t addr) {
    asm volatile("ldmatrix.sync.aligned.m8n8.x4.shared.b16 {%0,%1,%2,%3}, [%4];"
                 : "=r"(r0), "=r"(r1), "=r"(r2), "=r"(r3) : "r"(addr));
}
__device__ __forceinline__ void mma16816(float* d, const uint32_t* a,
                                         uint32_t b0, uint32_t b1) {
    asm volatile(
        "mma.sync.aligned.m16n8k16.row.col.f32.f16.f16.f32 "
        "{%0,%1,%2,%3}, {%4,%5,%6,%7}, {%8,%9}, {%0,%1,%2,%3};"
        : "+f"(d[0]), "+f"(d[1]), "+f"(d[2]), "+f"(d[3])
        : "r"(a[0]), "r"(a[1]), "r"(a[2]), "r"(a[3]), "r"(b0), "r"(b1));
}

// gate-dim permutation for 8 warps (48 cols each):
// orig g = t*128 + j -> p = 48*(j>>4) + 16*t + (j&15)
__device__ __forceinline__ int permute_g(int g) {
    int t = g >> 7, j = g & 127;
    return 48 * (j >> 4) + 16 * t + (j & 15);
}

// ---------------------------------------------------------------------------
// Prep A: xtab (permuted), 4 vocab rows per CTA. b_ih + b_hh(r,z) folded;
// r,z entries x0.5 (sigmoid(x) = 0.5*tanh(x/2)+0.5 with /2 pre-applied).
// ---------------------------------------------------------------------------
__global__ void xtab_kernel(const float* __restrict__ ce,
                            const float* __restrict__ wih_f, const float* __restrict__ bih_f,
                            const float* __restrict__ wih_b, const float* __restrict__ bih_b,
                            const float* __restrict__ bhh_f, const float* __restrict__ bhh_b) {
    extern __shared__ float xsm[];
    float* ws = xsm;               // [384*32]
    float* bs = ws + GG * CC;      // [384]
    float* cs = bs + GG;           // [4*32]
    const int d = blockIdx.y, g = threadIdx.x;
    const float* wih = d ? wih_b : wih_f;
    const float* bih = d ? bih_b : bih_f;
    const float* bhh = d ? bhh_b : bhh_f;
    for (int i = g; i < GG * CC; i += GG) ws[i] = wih[i];
    bs[g] = bih[g] + (g < 2 * HH ? bhh[g] : 0.0f);
    const int v0 = blockIdx.x * 4;
    for (int i = g; i < 4 * CC; i += GG) cs[i] = ce[v0 * CC + i];
    __syncthreads();
    const int p = permute_g(g);
    const float sc = (g < 2 * HH) ? 0.5f : 1.0f;
    #pragma unroll
    for (int vi = 0; vi < 4; vi++) {
        float s = bs[g];
        #pragma unroll
        for (int c = 0; c < CC; c++) s = fmaf(cs[vi * CC + c], ws[g * CC + c], s);
        g_xtab[(d * VV + v0 + vi) * GG + p] = s * sc;
    }
}

// ---------------------------------------------------------------------------
// Prep B (fused): w_hh fp16 permuted (r,z x0.5) + up_w transpose + proj_w fp16.
// ---------------------------------------------------------------------------
#define PREP_N0 (2 * GG * HH)
#define PREP_N1 (PREP_N0 + NLN * EE * BNK)
#define PREP_N2 (PREP_N1 + OO * EE)
__global__ void prep_misc(const float* __restrict__ whh_f,
                          const float* __restrict__ whh_b,
                          const float* __restrict__ up_w,
                          const float* __restrict__ proj_w) {
    const int i = blockIdx.x * 256 + threadIdx.x;
    if (i < PREP_N0) {
        int d = i / (GG * HH), rem = i % (GG * HH);
        int g = rem / HH, k = rem % HH;
        const float* w = d ? whh_b : whh_f;
        float v = w[g * HH + k];
        if (g < 2 * HH) v *= 0.5f;
        g_w0[d * GG * HH + permute_g(g) * HH + k] = __float2half_rn(v);
    } else if (i < PREP_N1) {
        int j = i - PREP_N0;
        int l = j / (EE * BNK), rem = j % (EE * BNK);
        int e = rem / BNK, dd = rem % BNK;
        g_upwT[(l * BNK + dd) * EE + e] = up_w[j];
    } else if (i < PREP_N2) {
        int j = i - PREP_N1;
        int o = j >> 8, e = j & 255;
        int pos = (((e >> 3) ^ (o & 7)) << 3) | (e & 7);
        g_pw16[o * EE + pos] = __float2half_rn(proj_w[j]);
    }
}

// ---------------------------------------------------------------------------
// Prep C: tokens transpose via 32x32 SMEM tiles.
// ---------------------------------------------------------------------------
__global__ void tokT_kernel(const int* __restrict__ tokens) {
    __shared__ int tile[32][33];
    const int bt = blockIdx.x, bb = blockIdx.y;
    const int x = threadIdx.x & 31, y0 = threadIdx.x >> 5;
    #pragma unroll
    for (int i = 0; i < 32; i += 8)
        tile[y0 + i][x] = tokens[(bb * 32 + y0 + i) * TT + bt * 32 + x];
    __syncthreads();
    #pragma unroll
    for (int i = 0; i < 32; i += 8)
        g_tokT[(bt * 32 + y0 + i) * BATCH + bb * 32 + x] = tile[x][y0 + i];
}

// ---------------------------------------------------------------------------
// GRU via mma (R15 structure; sole change: packed f16x2 tanh for r,z gates).
// 256 threads, 16 rows, h double-buffered, 2 CTAs/SM, grid (128,2).
// ---------------------------------------------------------------------------
__global__ __launch_bounds__(NTH, 2) void gru_mma_kernel(
    const float* __restrict__ bhh_f, const float* __restrict__ bhh_b) {
    extern __shared__ __align__(16) char smem[];
    const uint32_t sb = (uint32_t)__cvta_generic_to_shared(smem);

    const int dir  = blockIdx.y;
    const int b0r  = blockIdx.x * BM;
    const int tid  = threadIdx.x;
    const int w    = tid >> 5;      // 0..7
    const int lane = tid & 31;
    const int lr   = lane >> 2;     // 0..7
    const int lq   = lane & 3;      // 0..3

    const float* bhh = dir ? bhh_b : bhh_f;
    const float* xt  = g_xtab + dir * VV * GG;

    // ---- load w (swizzled) ----
    {
        const uint4* gw0 = (const uint4*)(g_w0 + dir * (GG * HH));
        for (int idx = tid; idx < GG * 16; idx += NTH) {
            int n = idx >> 4, c = idx & 15;
            int off = n * 256 + ((c ^ (n & 7)) << 4);
            *(uint4*)(smem + SW0 + off) = gw0[idx];
        }
    }

    // n-gate biases for this thread's 4 unit cols (j = 16w + 8hf + 2lq + c)
    float bias_n[2][2];
    #pragma unroll
    for (int hf = 0; hf < 2; hf++)
        #pragma unroll
        for (int c = 0; c < 2; c++)
            bias_n[hf][c] = bhh[2 * 128 + 16 * w + 8 * hf + 2 * lq + c];

    // ldmatrix addressing constants
    const int ar  = lane & 15;
    const int ahi = lane >> 4;
    const int asw = ar & 7;
    const int bj  = lane >> 3;
    const int bsw = lane & 7;
    const int brow = (48 * w + (lane & 7)) * 256;

    // h' store offsets: row = lr + 8rr, chunk = 2w + hf, halves at 4lq
    int stoff[2][2];
    #pragma unroll
    for (int rr = 0; rr < 2; rr++)
        #pragma unroll
        for (int hf = 0; hf < 2; hf++)
            stoff[rr][hf] = (lr + 8 * rr) * 256 + (((2 * w + hf) ^ lr) << 4)
                            + 4 * lq;

    float hprev[2][2][2];
    #pragma unroll
    for (int rr = 0; rr < 2; rr++)
        #pragma unroll
        for (int hf = 0; hf < 2; hf++)
            #pragma unroll
            for (int c = 0; c < 2; c++) hprev[rr][hf][c] = 0.0f;

    __syncthreads();

    #pragma unroll 1
    for (int t = 0; t < TT; t++) {
        const int tcol = dir ? (TT - 1 - t) : t;
        const int* tokrow = g_tokT + tcol * BATCH + b0r;

        // xp gather (consumed at end-of-step gates -> natural latency cover)
        float2 xp[2][2][3];   // [rr][hf][gate]
        #pragma unroll
        for (int rr = 0; rr < 2; rr++) {
            int tok = tokrow[8 * rr + lr];
            const float2* xr = (const float2*)(xt + tok * GG);
            #pragma unroll
            for (int hf = 0; hf < 2; hf++)
                #pragma unroll
                for (int u = 0; u < 3; u++)
                    xp[rr][hf][u] = xr[24 * w + 8 * u + 4 * hf + lq];
        }

        // accumulators
        float acc[6][4];
        #pragma unroll
        for (int nt = 0; nt < 4; nt++)
            #pragma unroll
            for (int rg = 0; rg < 4; rg++) acc[nt][rg] = 0.0f;
        #pragma unroll
        for (int hf = 0; hf < 2; hf++)
            #pragma unroll
            for (int rg = 0; rg < 4; rg++)
                acc[4 + hf][rg] = bias_n[hf][rg & 1];

        // ---- mma: acc += h(t) @ w^T ----
        if (t > 0) {
            const uint32_t ab = sb + SH16(t & 1) + ar * 256;
            #pragma unroll
            for (int kc2 = 0; kc2 < 4; kc2++) {
                uint32_t a0[8];
                uint32_t clo = (uint32_t)(((4 * kc2 + ahi) ^ asw) << 4);
                uint32_t chi = (uint32_t)(((4 * kc2 + 2 + ahi) ^ asw) << 4);
                ldsm4(a0[0], a0[1], a0[2], a0[3], ab + clo);
                ldsm4(a0[4], a0[5], a0[6], a0[7], ab + chi);
                const uint32_t chunk = (uint32_t)(((4 * kc2 + bj) ^ bsw) << 4);
                #pragma unroll
                for (int nt = 0; nt < 6; nt++) {
                    uint32_t bh[4];
                    ldsm4(bh[0], bh[1], bh[2], bh[3],
                          sb + SW0 + brow + nt * 2048 + chunk);
                    mma16816(acc[nt], a0 + 0, bh[0], bh[1]);
                    mma16816(acc[nt], a0 + 4, bh[2], bh[3]);
                }
            }
        }

        // ---- gates: packed f16x2 r,z per cell pair; n via tanh_e ----
        const uint32_t wrb_off = (uint32_t)SH16((t + 1) & 1);
        #pragma unroll
        for (int rr = 0; rr < 2; rr++)
            #pragma unroll
            for (int hf = 0; hf < 2; hf++) {
                float xr0 = xp[rr][hf][0].x + acc[hf][2 * rr + 0];
                float xr1 = xp[rr][hf][0].y + acc[hf][2 * rr + 1];
                float xz0 = xp[rr][hf][1].x + acc[2 + hf][2 * rr + 0];
                float xz1 = xp[rr][hf][1].y + acc[2 + hf][2 * rr + 1];
                uint32_t xr2, xz2, tr2, tz2;
                asm("cvt.rn.f16x2.f32 %0, %1, %2;" : "=r"(xr2) : "f"(xr1), "f"(xr0));
                asm("cvt.rn.f16x2.f32 %0, %1, %2;" : "=r"(xz2) : "f"(xz1), "f"(xz0));
                asm("tanh.approx.f16x2 %0, %1;" : "=r"(tr2) : "r"(xr2));
                asm("tanh.approx.f16x2 %0, %1;" : "=r"(tz2) : "r"(xz2));
                __half2 trh = *reinterpret_cast<__half2*>(&tr2);
                __half2 tzh = *reinterpret_cast<__half2*>(&tz2);
                float r0 = fmaf(__low2float(trh),  0.5f, 0.5f);
                float r1 = fmaf(__high2float(trh), 0.5f, 0.5f);
                float z0 = fmaf(__low2float(tzh),  0.5f, 0.5f);
                float z1 = fmaf(__high2float(tzh), 0.5f, 0.5f);
                float n0 = tanh_e(fmaf(r0, acc[4 + hf][2 * rr + 0], xp[rr][hf][2].x));
                float n1 = tanh_e(fmaf(r1, acc[4 + hf][2 * rr + 1], xp[rr][hf][2].y));
                float h0 = fmaf(z0, hprev[rr][hf][0] - n0, n0);
                float h1 = fmaf(z1, hprev[rr][hf][1] - n1, n1);
                hprev[rr][hf][0] = h0;
                hprev[rr][hf][1] = h1;
                uint32_t hpk;
                asm("cvt.rn.f16x2.f32 %0, %1, %2;" : "=r"(hpk) : "f"(h1), "f"(h0));
                *(uint32_t*)(smem + wrb_off + stoff[rr][hf]) = hpk;
            }
        __syncthreads();
    }

    // final hidden -> feat
    #pragma unroll
    for (int rr = 0; rr < 2; rr++)
        #pragma unroll
        for (int hf = 0; hf < 2; hf++)
            #pragma unroll
            for (int c = 0; c < 2; c++) {
                int m = lr + 8 * rr;
                int j = 16 * w + 8 * hf + 2 * lq + c;
                g_feat[(b0r + m) * EE + dir * HH + j] = hprev[rr][hf][c];
            }
}

// ---------------------------------------------------------------------------
// Head v6 (R12-exact): HB=16 rows, 512 threads, grid 128 (single wave).
// ---------------------------------------------------------------------------
#define HB 16
__global__ __launch_bounds__(512) void head_kernel(
    const int* __restrict__ lang_ids,
    const float* __restrict__ down_w, const float* __restrict__ down_b,
    const float* __restrict__ up_b,
    const float* __restrict__ ln_g,   const float* __restrict__ ln_b,
    const float* __restrict__ proj_b,
    float* __restrict__ out) {
    extern __shared__ __align__(16) char hsm[];
    const uint32_t sb = (uint32_t)__cvta_generic_to_shared(hsm);
    const int tid = threadIdx.x, w = tid >> 5, lane = tid & 31;
    const int b0 = blockIdx.x * HB;
    const int b = b0 + w;
    const int l = lang_ids[b];
    const float* fb = g_feat + b * EE;

    // ---- stage adapter weights (all langs) into SMEM ----
    {
        const uint4* gd = (const uint4*)down_w;
        const uint4* gu = (const uint4*)g_upwT;
        #pragma unroll
        for (int k = 0; k < 12; k++) {
            ((uint4*)(hsm + HDOWN))[tid + 512 * k] = gd[tid + 512 * k];
            ((uint4*)(hsm + HUP))[tid + 512 * k]   = gu[tid + 512 * k];
        }
    }
    __syncthreads();

    // ---- adapter (one row per warp), weights from SMEM ----
    float4 f4[8];
    #pragma unroll
    for (int c = 0; c < 8; c++)
        f4[c] = *(const float4*)(fb + (lane & 7) * 4 + 32 * c);

    float hid = 0.0f;
    const float* dwb = (const float*)(hsm + HDOWN) + l * BNK * EE;
    #pragma unroll
    for (int g = 0; g < 8; g++) {
        const int d = 4 * g + (lane >> 3);
        const float* wr = dwb + d * EE + (lane & 7) * 4;
        float s = 0.0f;
        #pragma unroll
        for (int c = 0; c < 8; c++) {
            float4 wv = *(const float4*)(wr + 32 * c);
            s = fmaf(f4[c].x, wv.x, s); s = fmaf(f4[c].y, wv.y, s);
            s = fmaf(f4[c].z, wv.z, s); s = fmaf(f4[c].w, wv.w, s);
        }
        s += __shfl_xor_sync(0xffffffffu, s, 1);
        s += __shfl_xor_sync(0xffffffffu, s, 2);
        s += __shfl_xor_sync(0xffffffffu, s, 4);
        float got = __shfl_sync(0xffffffffu, s, (lane & 3) * 8);
        if ((lane >> 2) == g) hid = got;
    }
    hid += down_b[l * BNK + lane];
    hid = 0.5f * hid * (1.0f + erff(hid * 0.7071067811865476f));

    const float4 fx0 = *(const float4*)(fb + lane * 8);
    const float4 fx1 = *(const float4*)(fb + lane * 8 + 4);
    float4 a0 = *(const float4*)(up_b + l * EE + lane * 8);
    float4 a1 = *(const float4*)(up_b + l * EE + lane * 8 + 4);
    const float* uwb = (const float*)(hsm + HUP) + l * BNK * EE;
    #pragma unroll 4
    for (int d = 0; d < BNK; d++) {
        float hd = __shfl_sync(0xffffffffu, hid, d);
        float4 u0 = *(const float4*)(uwb + d * EE + lane * 8);
        float4 u1 = *(const float4*)(uwb + d * EE + lane * 8 + 4);
        a0.x = fmaf(hd, u0.x, a0.x); a0.y = fmaf(hd, u0.y, a0.y);
        a0.z = fmaf(hd, u0.z, a0.z); a0.w = fmaf(hd, u0.w, a0.w);
        a1.x = fmaf(hd, u1.x, a1.x); a1.y = fmaf(hd, u1.y, a1.y);
        a1.z = fmaf(hd, u1.z, a1.z); a1.w = fmaf(hd, u1.w, a1.w);
    }
    float x[8] = {fx0.x + a0.x, fx0.y + a0.y, fx0.z + a0.z, fx0.w + a0.w,
                  fx1.x + a1.x, fx1.y + a1.y, fx1.z + a1.z, fx1.w + a1.w};
    float s1 = 0.0f, s2 = 0.0f;
    #pragma unroll
    for (int j = 0; j < 8; j++) { s1 += x[j]; s2 = fmaf(x[j], x[j], s2); }
    #pragma unroll
    for (int o = 16; o; o >>= 1) {
        s1 += __shfl_xor_sync(0xffffffffu, s1, o);
        s2 += __shfl_xor_sync(0xffffffffu, s2, o);
    }
    const float mu = s1 * (1.0f / EE);
    const float rstd = rsqrtf(s2 * (1.0f / EE) - mu * mu + 1e-5f);
    const float4 g0 = *(const float4*)(ln_g + l * EE + lane * 8);
    const float4 g1 = *(const float4*)(ln_g + l * EE + lane * 8 + 4);
    const float4 bb0 = *(const float4*)(ln_b + l * EE + lane * 8);
    const float4 bb1 = *(const float4*)(ln_b + l * EE + lane * 8 + 4);
    float y[8];
    y[0] = (x[0]-mu)*rstd*g0.x + bb0.x;  y[1] = (x[1]-mu)*rstd*g0.y + bb0.y;
    y[2] = (x[2]-mu)*rstd*g0.z + bb0.z;  y[3] = (x[3]-mu)*rstd*g0.w + bb0.w;
    y[4] = (x[4]-mu)*rstd*g1.x + bb1.x;  y[5] = (x[5]-mu)*rstd*g1.y + bb1.y;
    y[6] = (x[6]-mu)*rstd*g1.z + bb1.z;  y[7] = (x[7]-mu)*rstd*g1.w + bb1.w;

    {
        __half h_[8], c_[8];
        #pragma unroll
        for (int j = 0; j < 8; j++) {
            h_[j] = __float2half_rn(y[j]);
            c_[j] = __float2half_rn(y[j] - __half2float(h_[j]));
        }
        const int off = w * 512 + ((lane ^ (w & 7)) << 4);
        *(uint4*)(hsm + HYHI + off) = *(const uint4*)h_;
        *(uint4*)(hsm + HYLO + off) = *(const uint4*)c_;
    }
    __syncthreads();

    // ---- phase B: reuse weight region for proj_w fp16, then mma ----
    {
        const uint4* gp = (const uint4*)g_pw16;
        #pragma unroll
        for (int k = 0; k < 16; k++)
            ((uint4*)(hsm + HDOWN))[tid + 512 * k] = gp[tid + 512 * k];
    }
    __syncthreads();

    const int ar  = lane & 15;
    const int ahi = lane >> 4;
    const int asw = ar & 7;
    const int bj  = lane >> 3;
    const int bsw = lane & 7;
    const uint32_t ahib = sb + HYHI + ar * 512;
    const uint32_t alob = sb + HYLO + ar * 512;
    const uint32_t brow0 = sb + HDOWN + (16 * w + (lane & 7)) * 512;
    const uint32_t brow1 = brow0 + 8 * 512;

    const int lr = lane >> 2, lq = lane & 3;
    float pb0 = proj_b[16 * w + 2 * lq];
    float pb1 = proj_b[16 * w + 2 * lq + 1];
    float pb8 = proj_b[16 * w + 8 + 2 * lq];
    float pb9 = proj_b[16 * w + 8 + 2 * lq + 1];
    float acc[2][4] = {{pb0, pb1, pb0, pb1}, {pb8, pb9, pb8, pb9}};

    #pragma unroll
    for (int kc32 = 0; kc32 < 8; kc32++) {
        uint32_t ah[8], al[8], bF0[4], bF1[4];
        uint32_t clo = (uint32_t)(((4 * kc32 + ahi) ^ asw) << 4);
        uint32_t chi = (uint32_t)(((4 * kc32 + 2 + ahi) ^ asw) << 4);
        ldsm4(ah[0], ah[1], ah[2], ah[3], ahib + clo);
        ldsm4(ah[4], ah[5], ah[6], ah[7], ahib + chi);
        ldsm4(al[0], al[1], al[2], al[3], alob + clo);
        ldsm4(al[4], al[5], al[6], al[7], alob + chi);
        uint32_t bc = (uint32_t)(((4 * kc32 + bj) ^ bsw) << 4);
        ldsm4(bF0[0], bF0[1], bF0[2], bF0[3], brow0 + bc);
        ldsm4(bF1[0], bF1[1], bF1[2], bF1[3], brow1 + bc);
        #pragma unroll
        for (int kk = 0; kk < 2; kk++) {
            mma16816(acc[0], ah + 4 * kk, bF0[2 * kk], bF0[2 * kk + 1]);
            mma16816(acc[0], al + 4 * kk, bF0[2 * kk], bF0[2 * kk + 1]);
            mma16816(acc[1], ah + 4 * kk, bF1[2 * kk], bF1[2 * kk + 1]);
            mma16816(acc[1], al + 4 * kk, bF1[2 * kk], bF1[2 * kk + 1]);
        }
    }

    #pragma unroll
    for (int nt = 0; nt < 2; nt++) {
        const int col = 16 * w + 8 * nt + 2 * lq;
        *(float2*)(out + (b0 + lr) * OO + col)
            = make_float2(acc[nt][0], acc[nt][1]);
        *(float2*)(out + (b0 + lr + 8) * OO + col)
            = make_float2(acc[nt][2], acc[nt][3]);
    }
}

// ---------------------------------------------------------------------------
extern "C" void kernel_launch(void* const* d_in, const int* in_sizes, int n_in,
                              void* d_out, int out_size) {
    const int*   tokens = (const int*)d_in[0];
    const int*   lang   = (const int*)d_in[1];
    const float* ce     = (const float*)d_in[2];
    const float* wih_f  = (const float*)d_in[3];
    const float* whh_f  = (const float*)d_in[4];
    const float* bih_f  = (const float*)d_in[5];
    const float* bhh_f  = (const float*)d_in[6];
    const float* wih_b  = (const float*)d_in[7];
    const float* whh_b  = (const float*)d_in[8];
    const float* bih_b  = (const float*)d_in[9];
    const float* bhh_b  = (const float*)d_in[10];
    const float* down_w = (const float*)d_in[11];
    const float* down_b = (const float*)d_in[12];
    const float* up_w   = (const float*)d_in[13];
    const float* up_b   = (const float*)d_in[14];
    const float* ln_g   = (const float*)d_in[15];
    const float* ln_b   = (const float*)d_in[16];
    const float* proj_w = (const float*)d_in[17];
    const float* proj_b = (const float*)d_in[18];
    float* out = (float*)d_out;

    cudaFuncSetAttribute(gru_mma_kernel,
                         cudaFuncAttributeMaxDynamicSharedMemorySize, SMEM_TOTAL);
    cudaFuncSetAttribute(head_kernel,
                         cudaFuncAttributeMaxDynamicSharedMemorySize, HEAD_SMEM);
    const size_t xsmem = (size_t)(GG * CC + GG + 4 * CC) * sizeof(float);
    cudaFuncSetAttribute(xtab_kernel,
                         cudaFuncAttributeMaxDynamicSharedMemorySize, (int)xsmem);

    tokT_kernel<<<dim3(TT / 32, BATCH / 32), 256>>>(tokens);
    prep_misc<<<(PREP_N2 + 255) / 256, 256>>>(whh_f, whh_b, up_w, proj_w);
    xtab_kernel<<<dim3(VV / 4, 2), GG, xsmem>>>(ce, wih_f, bih_f, wih_b, bih_b,
                                                bhh_f, bhh_b);
    gru_mma_kernel<<<dim3(BATCH / BM, 2), NTH, SMEM_TOTAL>>>(bhh_f, bhh_b);
    head_kernel<<<BATCH / HB, 512, HEAD_SMEM>>>(lang, down_w, down_b, up_b,
                                                ln_g, ln_b, proj_b, out);
}